// round 10
// baseline (speedup 1.0000x reference)
#include <cuda_runtime.h>
#include <cuda_bf16.h>
#include <cstdint>

// ===========================================================================
// Problem constants
// ===========================================================================
#define BLN 8192          // B*L
#define DIM 1024          // D
#define QKSCALE 0.03125f  // 1/sqrt(1024)

// ===========================================================================
// Device scratch (allocation-free rule: device globals)
// ===========================================================================
__device__ __nv_bfloat16 g_xhi[BLN * DIM];
__device__ __nv_bfloat16 g_xlo[BLN * DIM];
__device__ __nv_bfloat16 g_wt_hi[4][DIM * DIM];   // W^T [n][k] hi
__device__ __nv_bfloat16 g_wt_lo[4][DIM * DIM];   // W^T [n][k] lo
// Batch-transposed Q,K (hi only — 1-term path): [b][ch=t][l]
__device__ __nv_bfloat16 g_QThi[BLN * DIM];
__device__ __nv_bfloat16 g_KThi[BLN * DIM];
// Natural split V and attention output A: [row=(b,l)][ch]
__device__ __nv_bfloat16 g_Vhi[BLN * DIM];
__device__ __nv_bfloat16 g_Vlo[BLN * DIM];
__device__ __nv_bfloat16 g_Ahi[BLN * DIM];
__device__ __nv_bfloat16 g_Alo[BLN * DIM];

// ===========================================================================
// PTX helpers (sm_80-era: target is plain sm_100, tcgen05 unavailable)
// ===========================================================================
__device__ __forceinline__ uint32_t smem_u32(const void* p) {
    uint32_t a;
    asm("{ .reg .u64 t; cvta.to.shared.u64 t, %1; cvt.u32.u64 %0, t; }" : "=r"(a) : "l"(p));
    return a;
}
#define CP_ASYNC16(saddr, gptr) \
    asm volatile("cp.async.cg.shared.global [%0], [%1], 16;" :: "r"(saddr), "l"(gptr))
#define CP_COMMIT() asm volatile("cp.async.commit_group;" ::: "memory")
#define CP_WAIT(n)  asm volatile("cp.async.wait_group %0;" :: "n"(n) : "memory")

__device__ __forceinline__ void ldmx4(uint32_t& r0, uint32_t& r1, uint32_t& r2, uint32_t& r3,
                                      uint32_t addr) {
    asm volatile("ldmatrix.sync.aligned.m8n8.x4.shared.b16 {%0,%1,%2,%3}, [%4];"
                 : "=r"(r0), "=r"(r1), "=r"(r2), "=r"(r3) : "r"(addr));
}
__device__ __forceinline__ void ldmx2(uint32_t& r0, uint32_t& r1, uint32_t addr) {
    asm volatile("ldmatrix.sync.aligned.m8n8.x2.shared.b16 {%0,%1}, [%2];"
                 : "=r"(r0), "=r"(r1) : "r"(addr));
}
__device__ __forceinline__ void mma16816(float* c, const uint32_t* a, const uint32_t* b) {
    asm volatile(
        "mma.sync.aligned.m16n8k16.row.col.f32.bf16.bf16.f32 "
        "{%0,%1,%2,%3}, {%4,%5,%6,%7}, {%8,%9}, {%0,%1,%2,%3};"
        : "+f"(c[0]), "+f"(c[1]), "+f"(c[2]), "+f"(c[3])
        : "r"(a[0]), "r"(a[1]), "r"(a[2]), "r"(a[3]), "r"(b[0]), "r"(b[1]));
}
__device__ __forceinline__ void pack_split(float v0, float v1, uint32_t& hi, uint32_t& lo) {
    __nv_bfloat16 h0 = __float2bfloat16(v0);
    __nv_bfloat16 h1 = __float2bfloat16(v1);
    __nv_bfloat162 hp; hp.x = h0; hp.y = h1;
    hi = *(uint32_t*)&hp;
    __nv_bfloat162 lp;
    lp.x = __float2bfloat16(v0 - __bfloat162float(h0));
    lp.y = __float2bfloat16(v1 - __bfloat162float(h1));
    lo = *(uint32_t*)&lp;
}

// ===========================================================================
// Split f32 -> (bf16 hi, bf16 lo)
// ===========================================================================
struct alignas(8) bf4 { __nv_bfloat16 a, b, c, d; };

__global__ void split_f32_kernel(const float* __restrict__ in,
                                 __nv_bfloat16* __restrict__ hi,
                                 __nv_bfloat16* __restrict__ lo, int n4) {
    int i = blockIdx.x * blockDim.x + threadIdx.x;
    int stride = gridDim.x * blockDim.x;
    for (; i < n4; i += stride) {
        float4 v = ((const float4*)in)[i];
        __nv_bfloat16 h0 = __float2bfloat16(v.x);
        __nv_bfloat16 h1 = __float2bfloat16(v.y);
        __nv_bfloat16 h2 = __float2bfloat16(v.z);
        __nv_bfloat16 h3 = __float2bfloat16(v.w);
        bf4 H = {h0, h1, h2, h3};
        bf4 L = {__float2bfloat16(v.x - __bfloat162float(h0)),
                 __float2bfloat16(v.y - __bfloat162float(h1)),
                 __float2bfloat16(v.z - __bfloat162float(h2)),
                 __float2bfloat16(v.w - __bfloat162float(h3))};
        ((bf4*)hi)[i] = H;
        ((bf4*)lo)[i] = L;
    }
}

// ===========================================================================
// Transpose + split: W [K][N] f32 -> W^T [N][K] bf16 hi/lo
// ===========================================================================
__global__ void transpose_split_kernel(const float* __restrict__ W,
                                       __nv_bfloat16* __restrict__ Thi,
                                       __nv_bfloat16* __restrict__ Tlo) {
    __shared__ float t[32][33];
    const int n0 = blockIdx.x << 5;
    const int k0 = blockIdx.y << 5;
    const int tx = threadIdx.x, ty = threadIdx.y;
#pragma unroll
    for (int j = 0; j < 4; j++)
        t[ty + (j << 3)][tx] = W[(k0 + ty + (j << 3)) * DIM + n0 + tx];
    __syncthreads();
#pragma unroll
    for (int j = 0; j < 4; j++) {
        float v = t[tx][ty + (j << 3)];
        __nv_bfloat16 h = __float2bfloat16(v);
        int o = (n0 + ty + (j << 3)) * DIM + k0 + tx;
        Thi[o] = h;
        Tlo[o] = __float2bfloat16(v - __bfloat162float(h));
    }
}

// ===========================================================================
// Tensor-core GEMM via mma.sync, TERMS split terms, 3-stage cp.async pipeline.
// 512 threads, 16 warps in a 4x4 grid, 32x32 warp tile.
// modes: 0 = fp32 natural; 1 = split-bf16 natural; 2 = bf16 transposed [b][ch][l]
// ===========================================================================
#define GSTRIDE 40
#define GTILE_BYTES (128 * GSTRIDE * 2)
#define GSTAGE_BYTES (4 * GTILE_BYTES)
#define GSMEM_BYTES (3 * GSTAGE_BYTES)   // 122880 B (3 stages)

template <int TERMS>
__global__ __launch_bounds__(512, 1)
void gemm_mma_kernel(const __nv_bfloat16* __restrict__ Ahi,
                     const __nv_bfloat16* __restrict__ Alo,
                     const __nv_bfloat16* __restrict__ Bhi,
                     const __nv_bfloat16* __restrict__ Blo,
                     const float* __restrict__ bias,
                     float* __restrict__ Cf,
                     __nv_bfloat16* __restrict__ Chi,
                     __nv_bfloat16* __restrict__ Clo,
                     float scale, int mode) {
    extern __shared__ __align__(16) char smem[];
    const uint32_t sbase = smem_u32(smem);

    const int tid = threadIdx.x;
    const int wid = tid >> 5;           // 0..15
    const int lane = tid & 31;
    const int m0 = blockIdx.y << 7;
    const int n0 = blockIdx.x << 7;
    const int wm = (wid & 3) << 5;      // 0/32/64/96
    const int wn = (wid >> 2) << 5;     // 0/32/64/96

    const __nv_bfloat16* srcs[4] = {Ahi + m0 * 1024, Alo + m0 * 1024,
                                    Bhi + n0 * 1024, Blo + n0 * 1024};

    float acc[2][4][4];
#pragma unroll
    for (int a = 0; a < 2; a++)
#pragma unroll
        for (int b = 0; b < 4; b++)
#pragma unroll
            for (int c = 0; c < 4; c++) acc[a][b][c] = 0.f;

    const int a_r = lane & 15, a_k = lane >> 4;
    const int b_r = lane & 7, b_k = (lane >> 3) & 1;

    auto load_stage = [&](int kt, int buf) {
        const int kb = kt << 5;
        uint32_t sb = sbase + buf * GSTAGE_BYTES;
        constexpr int NLD = (TERMS == 3) ? 4 : 2;
#pragma unroll
        for (int i = 0; i < NLD; i++) {
            int q = tid + (i << 9);               // 0..2047 (T3) / 0..1023 (T1)
            int tile = (TERMS == 3) ? (q >> 9) : ((q >> 9) << 1);
            int idx = q & 511;
            int row = idx >> 2;
            int ch = idx & 3;
            const __nv_bfloat16* g = srcs[tile] + row * 1024 + kb + (ch << 3);
            uint32_t s = sb + tile * GTILE_BYTES + (row * GSTRIDE + (ch << 3)) * 2;
            CP_ASYNC16(s, g);
        }
    };

    load_stage(0, 0); CP_COMMIT();
    load_stage(1, 1); CP_COMMIT();

    for (int kt = 0; kt < 32; kt++) {
        if (kt == 31) { CP_WAIT(0); } else { CP_WAIT(1); }
        __syncthreads();   // all warps done with stage kt-1 -> buffer (kt+2)%3 free
        if (kt + 2 < 32) { load_stage(kt + 2, (kt + 2) % 3); CP_COMMIT(); }

        const uint32_t sb = sbase + (kt % 3) * GSTAGE_BYTES;
        const uint32_t sAhi = sb;
        const uint32_t sAlo = sb + GTILE_BYTES;
        const uint32_t sBhi = sb + 2 * GTILE_BYTES;
        const uint32_t sBlo = sb + 3 * GTILE_BYTES;

#pragma unroll
        for (int ks = 0; ks < 2; ks++) {
            uint32_t ah[2][4], al[2][4], bh[4][2], bl[4][2];
#pragma unroll
            for (int mt = 0; mt < 2; mt++) {
                uint32_t off = ((wm + (mt << 4) + a_r) * GSTRIDE + (ks << 4) + (a_k << 3)) * 2;
                ldmx4(ah[mt][0], ah[mt][1], ah[mt][2], ah[mt][3], sAhi + off);
                if (TERMS == 3)
                    ldmx4(al[mt][0], al[mt][1], al[mt][2], al[mt][3], sAlo + off);
            }
#pragma unroll
            for (int nt = 0; nt < 4; nt++) {
                uint32_t off = ((wn + (nt << 3) + b_r) * GSTRIDE + (ks << 4) + (b_k << 3)) * 2;
                ldmx2(bh[nt][0], bh[nt][1], sBhi + off);
                if (TERMS == 3)
                    ldmx2(bl[nt][0], bl[nt][1], sBlo + off);
            }
#pragma unroll
            for (int mt = 0; mt < 2; mt++)
#pragma unroll
                for (int nt = 0; nt < 4; nt++) {
                    mma16816(acc[mt][nt], ah[mt], bh[nt]);
                    if (TERMS == 3) {
                        mma16816(acc[mt][nt], al[mt], bh[nt]);
                        mma16816(acc[mt][nt], ah[mt], bl[nt]);
                    }
                }
        }
    }
    __syncthreads();   // smem reuse safety for mode-2 staging

    const int er = lane >> 2;
    const int ec = (lane & 3) << 1;

    if (mode == 0) {
#pragma unroll
        for (int mt = 0; mt < 2; mt++) {
#pragma unroll
            for (int nt = 0; nt < 4; nt++) {
                int row = m0 + wm + (mt << 4) + er;
                int col = n0 + wn + (nt << 3) + ec;
                float2 b2 = *(const float2*)(bias + col);
                float2 o0, o1;
                o0.x = (acc[mt][nt][0] + b2.x) * scale;
                o0.y = (acc[mt][nt][1] + b2.y) * scale;
                o1.x = (acc[mt][nt][2] + b2.x) * scale;
                o1.y = (acc[mt][nt][3] + b2.y) * scale;
                *(float2*)(Cf + row * 1024 + col) = o0;
                *(float2*)(Cf + (row + 8) * 1024 + col) = o1;
            }
        }
    } else if (mode == 1) {
#pragma unroll
        for (int mt = 0; mt < 2; mt++) {
#pragma unroll
            for (int nt = 0; nt < 4; nt++) {
                int row = m0 + wm + (mt << 4) + er;
                int col = n0 + wn + (nt << 3) + ec;
                float2 b2 = *(const float2*)(bias + col);
#pragma unroll
                for (int half = 0; half < 2; half++) {
                    int r = row + half * 8;
                    float v0 = (acc[mt][nt][half * 2 + 0] + b2.x) * scale;
                    float v1 = (acc[mt][nt][half * 2 + 1] + b2.y) * scale;
                    uint32_t hp, lp;
                    pack_split(v0, v1, hp, lp);
                    *(uint32_t*)(Chi + r * 1024 + col) = hp;
                    *(uint32_t*)(Clo + r * 1024 + col) = lp;
                }
            }
        }
    } else {
        __nv_bfloat16* sthi = (__nv_bfloat16*)smem;
        __nv_bfloat16* stlo = (__nv_bfloat16*)(smem + 34816);
#pragma unroll
        for (int mt = 0; mt < 2; mt++) {
#pragma unroll
            for (int nt = 0; nt < 4; nt++) {
                int mrow = wm + (mt << 4) + er;
                int ncol = wn + (nt << 3) + ec;
                float2 b2 = *(const float2*)(bias + n0 + ncol);
#pragma unroll
                for (int half = 0; half < 2; half++) {
                    int r = mrow + half * 8;
                    float v0 = (acc[mt][nt][half * 2 + 0] + b2.x) * scale;
                    float v1 = (acc[mt][nt][half * 2 + 1] + b2.y) * scale;
                    __nv_bfloat16 h0 = __float2bfloat16(v0);
                    __nv_bfloat16 h1 = __float2bfloat16(v1);
                    sthi[ncol * 136 + r] = h0;
                    sthi[(ncol + 1) * 136 + r] = h1;
                    if (TERMS == 3) {
                        stlo[ncol * 136 + r] = __float2bfloat16(v0 - __bfloat162float(h0));
                        stlo[(ncol + 1) * 136 + r] = __float2bfloat16(v1 - __bfloat162float(h1));
                    }
                }
            }
        }
        __syncthreads();
        const int bidx = m0 >> 10;
        const int l0 = m0 & 1023;
        constexpr int NCP = (TERMS == 3) ? 8 : 4;
#pragma unroll
        for (int i = 0; i < NCP; i++) {
            int q = tid + (i << 9);     // 0..4095 (T3) / 0..2047 (T1)
            int t = q >> 11;
            int idx = q & 2047;
            int nrow = idx >> 4;
            int ch = idx & 15;
            uint4 v = *(const uint4*)(smem + t * 34816 + (nrow * 136 + ch * 8) * 2);
            __nv_bfloat16* dst = (t ? Clo : Chi) +
                bidx * 1048576 + (n0 + nrow) * 1024 + l0 + ch * 8;
            *(uint4*)dst = v;
        }
    }
}

// ===========================================================================
// FlashAttention-2-style attention (unchanged from round 8).
// ===========================================================================
#define ATT_Q_OFF 0                 // Q hi [128][72]            18432 B
#define ATT_K_OFF 18432             // K hi [128][72] x2 bufs    36864 B
#define ATT_V_OFF 55296             // V hi+lo [64][136] x2 bufs 69632 B
#define ATT_SMEM  124928

__global__ __launch_bounds__(256, 1)
void attn_fa2_kernel() {
    extern __shared__ __align__(16) char sm[];
    const uint32_t R = smem_u32(sm);

    const int g = blockIdx.y, qt = blockIdx.x;   // qt: 0..7 (128 rows each)
    const int b = g >> 4, h = g & 15;
    const int tid = threadIdx.x, wid = tid >> 5, lane = tid & 31;

    const int a_r = lane & 15, a_k = lane >> 4;
    const int b_r = lane & 7, b_k = (lane >> 3) & 1;
    const int ec = (lane & 3) << 1;
    const int er = lane >> 2;

    const int qkrow = b * 1048576 + h * 64;

#pragma unroll
    for (int i = 0; i < 4; i++) {
        int q = tid + (i << 8);
        int r = q >> 3, ch = q & 7;
        const __nv_bfloat16* src = g_QThi + qkrow + (qt * 128 + r) * 1024 + ch * 8;
        CP_ASYNC16(R + ATT_Q_OFF + (r * 72 + ch * 8) * 2, src);
    }
    auto load_K = [&](int c, int buf) {
#pragma unroll
        for (int i = 0; i < 4; i++) {
            int q = tid + (i << 8);
            int r = q >> 3, ch = q & 7;
            const __nv_bfloat16* src = g_KThi + qkrow + (c * 128 + r) * 1024 + ch * 8;
            CP_ASYNC16(R + ATT_K_OFF + buf * 18432 + (r * 72 + ch * 8) * 2, src);
        }
    };
    auto load_V = [&](int c, int buf) {
#pragma unroll
        for (int i = 0; i < 8; i++) {
            int q = tid + (i << 8);
            int t = q >> 10, idx = q & 1023;
            int r = idx >> 4, ch = idx & 15;
            const __nv_bfloat16* src =
                (t ? g_Vlo : g_Vhi) + (b * 1024 + h * 64 + r) * 1024 + c * 128 + ch * 8;
            CP_ASYNC16(R + ATT_V_OFF + buf * 34816 + t * 17408 + (r * 136 + ch * 8) * 2, src);
        }
    };
    load_K(0, 0);
    load_V(0, 0);
    CP_COMMIT();
    CP_WAIT(0);
    __syncthreads();

    uint32_t qh[4][4];
#pragma unroll
    for (int ks = 0; ks < 4; ks++) {
        uint32_t off = R + ATT_Q_OFF + ((wid * 16 + a_r) * 72 + ks * 16 + a_k * 8) * 2;
        ldmx4(qh[ks][0], qh[ks][1], qh[ks][2], qh[ks][3], off);
    }

    float oacc[8][4];
#pragma unroll
    for (int i = 0; i < 8; i++)
#pragma unroll
        for (int j = 0; j < 4; j++) oacc[i][j] = 0.f;
    float mrow[2] = {-1e30f, -1e30f};
    float lrow[2] = {0.f, 0.f};

    for (int c = 0; c < 8; c++) {
        const int buf = c & 1;
        if (c + 1 < 8) {
            load_K(c + 1, buf ^ 1);
            load_V(c + 1, buf ^ 1);
            CP_COMMIT();
        }

        float sacc[16][4];
#pragma unroll
        for (int i = 0; i < 16; i++)
#pragma unroll
            for (int j = 0; j < 4; j++) sacc[i][j] = 0.f;

        const uint32_t kb = R + ATT_K_OFF + buf * 18432;
#pragma unroll
        for (int ks = 0; ks < 4; ks++) {
#pragma unroll
            for (int nt = 0; nt < 16; nt++) {
                uint32_t bb[2];
                ldmx2(bb[0], bb[1], kb + ((nt * 8 + b_r) * 72 + ks * 16 + b_k * 8) * 2);
                mma16816(sacc[nt], qh[ks], bb);
            }
        }

        float cm[2];
#pragma unroll
        for (int rr = 0; rr < 2; rr++) {
            float mx = -1e30f;
#pragma unroll
            for (int nt = 0; nt < 16; nt++)
                mx = fmaxf(mx, fmaxf(sacc[nt][rr * 2], sacc[nt][rr * 2 + 1]));
            mx = fmaxf(mx, __shfl_xor_sync(0xffffffffu, mx, 1));
            mx = fmaxf(mx, __shfl_xor_sync(0xffffffffu, mx, 2));
            float mnew = fmaxf(mrow[rr], mx);
            cm[rr] = __expf(mrow[rr] - mnew);
            mrow[rr] = mnew;
        }
        float rs0 = 0.f, rs1 = 0.f;
#pragma unroll
        for (int nt = 0; nt < 16; nt++) {
            sacc[nt][0] = __expf(sacc[nt][0] - mrow[0]);
            sacc[nt][1] = __expf(sacc[nt][1] - mrow[0]);
            sacc[nt][2] = __expf(sacc[nt][2] - mrow[1]);
            sacc[nt][3] = __expf(sacc[nt][3] - mrow[1]);
            rs0 += sacc[nt][0] + sacc[nt][1];
            rs1 += sacc[nt][2] + sacc[nt][3];
        }
        rs0 += __shfl_xor_sync(0xffffffffu, rs0, 1);
        rs0 += __shfl_xor_sync(0xffffffffu, rs0, 2);
        rs1 += __shfl_xor_sync(0xffffffffu, rs1, 1);
        rs1 += __shfl_xor_sync(0xffffffffu, rs1, 2);
        lrow[0] = lrow[0] * cm[0] + rs0;
        lrow[1] = lrow[1] * cm[1] + rs1;

#pragma unroll
        for (int nt = 0; nt < 8; nt++) {
            oacc[nt][0] *= cm[0]; oacc[nt][1] *= cm[0];
            oacc[nt][2] *= cm[1]; oacc[nt][3] *= cm[1];
        }

        uint32_t ph[8][4], pl[8][4];
#pragma unroll
        for (int j = 0; j < 8; j++) {
            pack_split(sacc[2 * j][0],     sacc[2 * j][1],     ph[j][0], pl[j][0]);
            pack_split(sacc[2 * j][2],     sacc[2 * j][3],     ph[j][1], pl[j][1]);
            pack_split(sacc[2 * j + 1][0], sacc[2 * j + 1][1], ph[j][2], pl[j][2]);
            pack_split(sacc[2 * j + 1][2], sacc[2 * j + 1][3], ph[j][3], pl[j][3]);
        }

        const uint32_t vb = R + ATT_V_OFF + buf * 34816;
#pragma unroll
        for (int ks = 0; ks < 8; ks++) {
#pragma unroll
            for (int nt = 0; nt < 8; nt++) {
                uint32_t vh[2], vl[2];
                uint32_t voff = vb + ((nt * 8 + b_r) * 136 + ks * 16 + b_k * 8) * 2;
                ldmx2(vh[0], vh[1], voff);
                ldmx2(vl[0], vl[1], voff + 17408);
                mma16816(oacc[nt], ph[ks], vh);
                mma16816(oacc[nt], pl[ks], vh);
                mma16816(oacc[nt], ph[ks], vl);
            }
        }

        if (c + 1 < 8) { CP_WAIT(0); __syncthreads(); }
    }

    float inv[2] = {1.f / lrow[0], 1.f / lrow[1]};
#pragma unroll
    for (int nt = 0; nt < 8; nt++) {
#pragma unroll
        for (int half = 0; half < 2; half++) {
            int t1 = qt * 128 + wid * 16 + er + half * 8;
            int p = t1 >> 4, qq = t1 & 15;
            int col = nt * 8 + ec;
            float v0 = oacc[nt][half * 2 + 0] * inv[half];
            float v1 = oacc[nt][half * 2 + 1] * inv[half];
            uint32_t hp, lp;
            pack_split(v0, v1, hp, lp);
            int off = (b * 1024 + h * 64 + p) * 1024 + qq * 64 + col;
            *(uint32_t*)(g_Ahi + off) = hp;
            *(uint32_t*)(g_Alo + off) = lp;
        }
    }
}

// ===========================================================================
extern "C" void kernel_launch(void* const* d_in, const int* in_sizes, int n_in,
                              void* d_out, int out_size) {
    const float* x  = (const float*)d_in[0];
    const float* Wq = (const float*)d_in[1];
    const float* bq = (const float*)d_in[2];
    const float* Wk = (const float*)d_in[3];
    const float* bk = (const float*)d_in[4];
    const float* Wv = (const float*)d_in[5];
    const float* bv = (const float*)d_in[6];
    const float* Wo = (const float*)d_in[7];
    const float* bo = (const float*)d_in[8];
    float* out = (float*)d_out;

    __nv_bfloat16 *xhi, *xlo, *whi, *wlo;
    __nv_bfloat16 *qthi, *kthi, *vhi, *vlo, *ahi, *alo;
    cudaGetSymbolAddress((void**)&xhi, g_xhi);
    cudaGetSymbolAddress((void**)&xlo, g_xlo);
    cudaGetSymbolAddress((void**)&whi, g_wt_hi);
    cudaGetSymbolAddress((void**)&wlo, g_wt_lo);
    cudaGetSymbolAddress((void**)&qthi, g_QThi);
    cudaGetSymbolAddress((void**)&kthi, g_KThi);
    cudaGetSymbolAddress((void**)&vhi, g_Vhi);
    cudaGetSymbolAddress((void**)&vlo, g_Vlo);
    cudaGetSymbolAddress((void**)&ahi, g_Ahi);
    cudaGetSymbolAddress((void**)&alo, g_Alo);

    cudaFuncSetAttribute(gemm_mma_kernel<1>, cudaFuncAttributeMaxDynamicSharedMemorySize,
                         GSMEM_BYTES);
    cudaFuncSetAttribute(gemm_mma_kernel<3>, cudaFuncAttributeMaxDynamicSharedMemorySize,
                         GSMEM_BYTES);
    cudaFuncSetAttribute(attn_fa2_kernel, cudaFuncAttributeMaxDynamicSharedMemorySize,
                         ATT_SMEM);

    // 1) split x
    split_f32_kernel<<<2048, 256>>>(x, xhi, xlo, BLN * DIM / 4);

    // 2) transpose+split weights (W^T [n][k])
    dim3 tgrid(32, 32), tblk(32, 8);
    transpose_split_kernel<<<tgrid, tblk>>>(Wq, whi + 0 * DIM * DIM, wlo + 0 * DIM * DIM);
    transpose_split_kernel<<<tgrid, tblk>>>(Wk, whi + 1 * DIM * DIM, wlo + 1 * DIM * DIM);
    transpose_split_kernel<<<tgrid, tblk>>>(Wv, whi + 2 * DIM * DIM, wlo + 2 * DIM * DIM);
    transpose_split_kernel<<<tgrid, tblk>>>(Wo, whi + 3 * DIM * DIM, wlo + 3 * DIM * DIM);

    // 3) projections: Q,K 1-term transposed-hi; V 3-term natural split
    dim3 ggrid(8, 64);
    gemm_mma_kernel<1><<<ggrid, 512, GSMEM_BYTES>>>(xhi, xlo, whi + 0 * DIM * DIM,
                                                    wlo + 0 * DIM * DIM, bq,
                                                    nullptr, qthi, nullptr, QKSCALE, 2);
    gemm_mma_kernel<1><<<ggrid, 512, GSMEM_BYTES>>>(xhi, xlo, whi + 1 * DIM * DIM,
                                                    wlo + 1 * DIM * DIM, bk,
                                                    nullptr, kthi, nullptr, QKSCALE, 2);
    gemm_mma_kernel<3><<<ggrid, 512, GSMEM_BYTES>>>(xhi, xlo, whi + 2 * DIM * DIM,
                                                    wlo + 2 * DIM * DIM, bv,
                                                    nullptr, vhi, vlo, 1.0f, 1);

    // 4) attention (FA2-style, t1=128 per CTA)
    attn_fa2_kernel<<<dim3(8, 128), 256, ATT_SMEM>>>();

    // 5) output projection (3-term, fp32 out)
    gemm_mma_kernel<3><<<ggrid, 512, GSMEM_BYTES>>>(ahi, alo, whi + 3 * DIM * DIM,
                                                    wlo + 3 * DIM * DIM, bo,
                                                    out, nullptr, nullptr, 1.0f, 0);
}

// round 11
// speedup vs baseline: 1.0418x; 1.0418x over previous
#include <cuda_runtime.h>
#include <cuda_bf16.h>
#include <cstdint>

// ===========================================================================
// Problem constants
// ===========================================================================
#define BLN 8192          // B*L
#define DIM 1024          // D
#define QKSCALE 0.03125f  // 1/sqrt(1024)

// ===========================================================================
// Device scratch (allocation-free rule: device globals)
// ===========================================================================
__device__ __nv_bfloat16 g_xhi[BLN * DIM];
__device__ __nv_bfloat16 g_xlo[BLN * DIM];
__device__ __nv_bfloat16 g_wt_hi[4][DIM * DIM];   // W^T [n][k] hi
__device__ __nv_bfloat16 g_wt_lo[4][DIM * DIM];   // W^T [n][k] lo
// Batch-transposed Q,K (hi only — 1-term path): [b][ch=t][l]
__device__ __nv_bfloat16 g_QThi[BLN * DIM];
__device__ __nv_bfloat16 g_KThi[BLN * DIM];
// Natural split V and attention output A: [row=(b,l)][ch]
__device__ __nv_bfloat16 g_Vhi[BLN * DIM];
__device__ __nv_bfloat16 g_Vlo[BLN * DIM];
__device__ __nv_bfloat16 g_Ahi[BLN * DIM];
__device__ __nv_bfloat16 g_Alo[BLN * DIM];

// ===========================================================================
// PTX helpers (sm_80-era: target is plain sm_100, tcgen05 unavailable)
// ===========================================================================
__device__ __forceinline__ uint32_t smem_u32(const void* p) {
    uint32_t a;
    asm("{ .reg .u64 t; cvta.to.shared.u64 t, %1; cvt.u32.u64 %0, t; }" : "=r"(a) : "l"(p));
    return a;
}
#define CP_ASYNC16(saddr, gptr) \
    asm volatile("cp.async.cg.shared.global [%0], [%1], 16;" :: "r"(saddr), "l"(gptr))
#define CP_COMMIT() asm volatile("cp.async.commit_group;" ::: "memory")
#define CP_WAIT(n)  asm volatile("cp.async.wait_group %0;" :: "n"(n) : "memory")

__device__ __forceinline__ void ldmx4(uint32_t& r0, uint32_t& r1, uint32_t& r2, uint32_t& r3,
                                      uint32_t addr) {
    asm volatile("ldmatrix.sync.aligned.m8n8.x4.shared.b16 {%0,%1,%2,%3}, [%4];"
                 : "=r"(r0), "=r"(r1), "=r"(r2), "=r"(r3) : "r"(addr));
}
__device__ __forceinline__ void mma16816(float* c, const uint32_t* a, const uint32_t* b) {
    asm volatile(
        "mma.sync.aligned.m16n8k16.row.col.f32.bf16.bf16.f32 "
        "{%0,%1,%2,%3}, {%4,%5,%6,%7}, {%8,%9}, {%0,%1,%2,%3};"
        : "+f"(c[0]), "+f"(c[1]), "+f"(c[2]), "+f"(c[3])
        : "r"(a[0]), "r"(a[1]), "r"(a[2]), "r"(a[3]), "r"(b[0]), "r"(b[1]));
}
__device__ __forceinline__ void pack_split(float v0, float v1, uint32_t& hi, uint32_t& lo) {
    __nv_bfloat16 h0 = __float2bfloat16(v0);
    __nv_bfloat16 h1 = __float2bfloat16(v1);
    __nv_bfloat162 hp; hp.x = h0; hp.y = h1;
    hi = *(uint32_t*)&hp;
    __nv_bfloat162 lp;
    lp.x = __float2bfloat16(v0 - __bfloat162float(h0));
    lp.y = __float2bfloat16(v1 - __bfloat162float(h1));
    lo = *(uint32_t*)&lp;
}

// ===========================================================================
// Split f32 -> (bf16 hi, bf16 lo)
// ===========================================================================
struct alignas(8) bf4 { __nv_bfloat16 a, b, c, d; };

__global__ void split_f32_kernel(const float* __restrict__ in,
                                 __nv_bfloat16* __restrict__ hi,
                                 __nv_bfloat16* __restrict__ lo, int n4) {
    int i = blockIdx.x * blockDim.x + threadIdx.x;
    int stride = gridDim.x * blockDim.x;
    for (; i < n4; i += stride) {
        float4 v = ((const float4*)in)[i];
        __nv_bfloat16 h0 = __float2bfloat16(v.x);
        __nv_bfloat16 h1 = __float2bfloat16(v.y);
        __nv_bfloat16 h2 = __float2bfloat16(v.z);
        __nv_bfloat16 h3 = __float2bfloat16(v.w);
        bf4 H = {h0, h1, h2, h3};
        bf4 L = {__float2bfloat16(v.x - __bfloat162float(h0)),
                 __float2bfloat16(v.y - __bfloat162float(h1)),
                 __float2bfloat16(v.z - __bfloat162float(h2)),
                 __float2bfloat16(v.w - __bfloat162float(h3))};
        ((bf4*)hi)[i] = H;
        ((bf4*)lo)[i] = L;
    }
}

// ===========================================================================
// Transpose + split: W [K][N] f32 -> W^T [N][K] bf16 hi/lo
// ===========================================================================
__global__ void transpose_split_kernel(const float* __restrict__ W,
                                       __nv_bfloat16* __restrict__ Thi,
                                       __nv_bfloat16* __restrict__ Tlo) {
    __shared__ float t[32][33];
    const int n0 = blockIdx.x << 5;
    const int k0 = blockIdx.y << 5;
    const int tx = threadIdx.x, ty = threadIdx.y;
#pragma unroll
    for (int j = 0; j < 4; j++)
        t[ty + (j << 3)][tx] = W[(k0 + ty + (j << 3)) * DIM + n0 + tx];
    __syncthreads();
#pragma unroll
    for (int j = 0; j < 4; j++) {
        float v = t[tx][ty + (j << 3)];
        __nv_bfloat16 h = __float2bfloat16(v);
        int o = (n0 + ty + (j << 3)) * DIM + k0 + tx;
        Thi[o] = h;
        Tlo[o] = __float2bfloat16(v - __bfloat162float(h));
    }
}

// ===========================================================================
// Tensor-core GEMM via mma.sync, TERMS split terms, 3-stage cp.async pipeline.
// 256 threads, 8 warps, 64x32 warp tiles (round-8 proven config).
// ALL B operands loaded via ldmatrix.x4 (2 n-tiles per LDSM slot).
// modes: 0 = fp32 natural; 1 = split-bf16 natural; 2 = bf16 transposed [b][ch][l]
// ===========================================================================
#define GSTRIDE 40
#define GTILE_BYTES (128 * GSTRIDE * 2)
#define GSTAGE_BYTES (4 * GTILE_BYTES)
#define GSMEM_BYTES (3 * GSTAGE_BYTES)   // 122880 B (3 stages)

template <int TERMS>
__global__ __launch_bounds__(256, 1)
void gemm_mma_kernel(const __nv_bfloat16* __restrict__ Ahi,
                     const __nv_bfloat16* __restrict__ Alo,
                     const __nv_bfloat16* __restrict__ Bhi,
                     const __nv_bfloat16* __restrict__ Blo,
                     const float* __restrict__ bias,
                     float* __restrict__ Cf,
                     __nv_bfloat16* __restrict__ Chi,
                     __nv_bfloat16* __restrict__ Clo,
                     float scale, int mode) {
    extern __shared__ __align__(16) char smem[];
    const uint32_t sbase = smem_u32(smem);

    const int tid = threadIdx.x;
    const int wid = tid >> 5;
    const int lane = tid & 31;
    const int m0 = blockIdx.y << 7;
    const int n0 = blockIdx.x << 7;
    const int wm = (wid & 1) << 6;
    const int wn = (wid >> 1) << 5;

    const __nv_bfloat16* srcs[4] = {Ahi + m0 * 1024, Alo + m0 * 1024,
                                    Bhi + n0 * 1024, Blo + n0 * 1024};

    float acc[4][4][4];
#pragma unroll
    for (int a = 0; a < 4; a++)
#pragma unroll
        for (int b = 0; b < 4; b++)
#pragma unroll
            for (int c = 0; c < 4; c++) acc[a][b][c] = 0.f;

    const int a_r = lane & 15, a_k = lane >> 4;
    const int x4m = lane >> 3;           // matrix index 0..3 for x4 B loads
    const int x4r = lane & 7;            // row within matrix

    auto load_stage = [&](int kt, int buf) {
        const int kb = kt << 5;
        uint32_t sb = sbase + buf * GSTAGE_BYTES;
        constexpr int NLD = (TERMS == 3) ? 8 : 4;
#pragma unroll
        for (int i = 0; i < NLD; i++) {
            int tile, idx;
            if (TERMS == 3) {
                tile = i >> 1;
                idx = ((i & 1) << 8) + tid;
            } else {
                tile = (i >> 1) << 1;       // 0 (Ahi) or 2 (Bhi)
                idx = ((i & 1) << 8) + tid;
            }
            int row = idx >> 2;
            int ch = idx & 3;
            const __nv_bfloat16* g = srcs[tile] + row * 1024 + kb + (ch << 3);
            uint32_t s = sb + tile * GTILE_BYTES + (row * GSTRIDE + (ch << 3)) * 2;
            CP_ASYNC16(s, g);
        }
    };

    load_stage(0, 0); CP_COMMIT();
    load_stage(1, 1); CP_COMMIT();

    for (int kt = 0; kt < 32; kt++) {
        if (kt == 31) { CP_WAIT(0); } else { CP_WAIT(1); }
        __syncthreads();   // all warps done with stage kt-1 -> buffer (kt+2)%3 free
        if (kt + 2 < 32) { load_stage(kt + 2, (kt + 2) % 3); CP_COMMIT(); }

        const uint32_t sb = sbase + (kt % 3) * GSTAGE_BYTES;
        const uint32_t sAhi = sb;
        const uint32_t sAlo = sb + GTILE_BYTES;
        const uint32_t sBhi = sb + 2 * GTILE_BYTES;
        const uint32_t sBlo = sb + 3 * GTILE_BYTES;

#pragma unroll
        for (int ks = 0; ks < 2; ks++) {
            uint32_t ah[4][4], al[4][4], bh[4][2], bl[4][2];
#pragma unroll
            for (int mt = 0; mt < 4; mt++) {
                uint32_t off = ((wm + (mt << 4) + a_r) * GSTRIDE + (ks << 4) + (a_k << 3)) * 2;
                ldmx4(ah[mt][0], ah[mt][1], ah[mt][2], ah[mt][3], sAhi + off);
                if (TERMS == 3)
                    ldmx4(al[mt][0], al[mt][1], al[mt][2], al[mt][3], sAlo + off);
            }
            // B via x4: matrices = (nt-half, k-half); lane x4m selects matrix
#pragma unroll
            for (int ntp = 0; ntp < 2; ntp++) {
                uint32_t off = ((wn + (ntp << 4) + ((x4m >> 1) << 3) + x4r) * GSTRIDE +
                                (ks << 4) + ((x4m & 1) << 3)) * 2;
                ldmx4(bh[2 * ntp][0], bh[2 * ntp][1],
                      bh[2 * ntp + 1][0], bh[2 * ntp + 1][1], sBhi + off);
                if (TERMS == 3)
                    ldmx4(bl[2 * ntp][0], bl[2 * ntp][1],
                          bl[2 * ntp + 1][0], bl[2 * ntp + 1][1], sBlo + off);
            }
#pragma unroll
            for (int mt = 0; mt < 4; mt++)
#pragma unroll
                for (int nt = 0; nt < 4; nt++) {
                    mma16816(acc[mt][nt], ah[mt], bh[nt]);
                    if (TERMS == 3) {
                        mma16816(acc[mt][nt], al[mt], bh[nt]);
                        mma16816(acc[mt][nt], ah[mt], bl[nt]);
                    }
                }
        }
    }
    __syncthreads();   // smem reuse safety for mode-2 staging

    const int er = lane >> 2;
    const int ec = (lane & 3) << 1;

    if (mode == 0) {
#pragma unroll
        for (int mt = 0; mt < 4; mt++) {
#pragma unroll
            for (int nt = 0; nt < 4; nt++) {
                int row = m0 + wm + (mt << 4) + er;
                int col = n0 + wn + (nt << 3) + ec;
                float2 b2 = *(const float2*)(bias + col);
                float2 o0, o1;
                o0.x = (acc[mt][nt][0] + b2.x) * scale;
                o0.y = (acc[mt][nt][1] + b2.y) * scale;
                o1.x = (acc[mt][nt][2] + b2.x) * scale;
                o1.y = (acc[mt][nt][3] + b2.y) * scale;
                *(float2*)(Cf + row * 1024 + col) = o0;
                *(float2*)(Cf + (row + 8) * 1024 + col) = o1;
            }
        }
    } else if (mode == 1) {
#pragma unroll
        for (int mt = 0; mt < 4; mt++) {
#pragma unroll
            for (int nt = 0; nt < 4; nt++) {
                int row = m0 + wm + (mt << 4) + er;
                int col = n0 + wn + (nt << 3) + ec;
                float2 b2 = *(const float2*)(bias + col);
#pragma unroll
                for (int half = 0; half < 2; half++) {
                    int r = row + half * 8;
                    float v0 = (acc[mt][nt][half * 2 + 0] + b2.x) * scale;
                    float v1 = (acc[mt][nt][half * 2 + 1] + b2.y) * scale;
                    uint32_t hp, lp;
                    pack_split(v0, v1, hp, lp);
                    *(uint32_t*)(Chi + r * 1024 + col) = hp;
                    *(uint32_t*)(Clo + r * 1024 + col) = lp;
                }
            }
        }
    } else {
        __nv_bfloat16* sthi = (__nv_bfloat16*)smem;
        __nv_bfloat16* stlo = (__nv_bfloat16*)(smem + 34816);
#pragma unroll
        for (int mt = 0; mt < 4; mt++) {
#pragma unroll
            for (int nt = 0; nt < 4; nt++) {
                int mrow = wm + (mt << 4) + er;
                int ncol = wn + (nt << 3) + ec;
                float2 b2 = *(const float2*)(bias + n0 + ncol);
#pragma unroll
                for (int half = 0; half < 2; half++) {
                    int r = mrow + half * 8;
                    float v0 = (acc[mt][nt][half * 2 + 0] + b2.x) * scale;
                    float v1 = (acc[mt][nt][half * 2 + 1] + b2.y) * scale;
                    __nv_bfloat16 h0 = __float2bfloat16(v0);
                    __nv_bfloat16 h1 = __float2bfloat16(v1);
                    sthi[ncol * 136 + r] = h0;
                    sthi[(ncol + 1) * 136 + r] = h1;
                    if (TERMS == 3) {
                        stlo[ncol * 136 + r] = __float2bfloat16(v0 - __bfloat162float(h0));
                        stlo[(ncol + 1) * 136 + r] = __float2bfloat16(v1 - __bfloat162float(h1));
                    }
                }
            }
        }
        __syncthreads();
        const int bidx = m0 >> 10;
        const int l0 = m0 & 1023;
        constexpr int NCP = (TERMS == 3) ? 16 : 8;
#pragma unroll
        for (int i = 0; i < NCP; i++) {
            int q = tid + (i << 8);
            int t = q >> 11;
            int idx = q & 2047;
            int nrow = idx >> 4;
            int ch = idx & 15;
            uint4 v = *(const uint4*)(smem + t * 34816 + (nrow * 136 + ch * 8) * 2);
            __nv_bfloat16* dst = (t ? Clo : Chi) +
                bidx * 1048576 + (n0 + nrow) * 1024 + l0 + ch * 8;
            *(uint4*)dst = v;
        }
    }
}

// ===========================================================================
// FlashAttention-2-style attention (round-8 structure), K and V operands
// loaded via ldmatrix.x4 (halves LDSM issue count in both phases).
// ===========================================================================
#define ATT_Q_OFF 0                 // Q hi [128][72]            18432 B
#define ATT_K_OFF 18432             // K hi [128][72] x2 bufs    36864 B
#define ATT_V_OFF 55296             // V hi+lo [64][136] x2 bufs 69632 B
#define ATT_SMEM  124928

__global__ __launch_bounds__(256, 1)
void attn_fa2_kernel() {
    extern __shared__ __align__(16) char sm[];
    const uint32_t R = smem_u32(sm);

    const int g = blockIdx.y, qt = blockIdx.x;   // qt: 0..7 (128 rows each)
    const int b = g >> 4, h = g & 15;
    const int tid = threadIdx.x, wid = tid >> 5, lane = tid & 31;

    const int a_r = lane & 15, a_k = lane >> 4;
    const int x4m = lane >> 3;           // matrix index for x4 B loads
    const int x4r = lane & 7;
    const int ec = (lane & 3) << 1;
    const int er = lane >> 2;

    const int qkrow = b * 1048576 + h * 64;

#pragma unroll
    for (int i = 0; i < 4; i++) {
        int q = tid + (i << 8);
        int r = q >> 3, ch = q & 7;
        const __nv_bfloat16* src = g_QThi + qkrow + (qt * 128 + r) * 1024 + ch * 8;
        CP_ASYNC16(R + ATT_Q_OFF + (r * 72 + ch * 8) * 2, src);
    }
    auto load_K = [&](int c, int buf) {
#pragma unroll
        for (int i = 0; i < 4; i++) {
            int q = tid + (i << 8);
            int r = q >> 3, ch = q & 7;
            const __nv_bfloat16* src = g_KThi + qkrow + (c * 128 + r) * 1024 + ch * 8;
            CP_ASYNC16(R + ATT_K_OFF + buf * 18432 + (r * 72 + ch * 8) * 2, src);
        }
    };
    auto load_V = [&](int c, int buf) {
#pragma unroll
        for (int i = 0; i < 8; i++) {
            int q = tid + (i << 8);
            int t = q >> 10, idx = q & 1023;
            int r = idx >> 4, ch = idx & 15;
            const __nv_bfloat16* src =
                (t ? g_Vlo : g_Vhi) + (b * 1024 + h * 64 + r) * 1024 + c * 128 + ch * 8;
            CP_ASYNC16(R + ATT_V_OFF + buf * 34816 + t * 17408 + (r * 136 + ch * 8) * 2, src);
        }
    };
    load_K(0, 0);
    load_V(0, 0);
    CP_COMMIT();
    CP_WAIT(0);
    __syncthreads();

    uint32_t qh[4][4];
#pragma unroll
    for (int ks = 0; ks < 4; ks++) {
        uint32_t off = R + ATT_Q_OFF + ((wid * 16 + a_r) * 72 + ks * 16 + a_k * 8) * 2;
        ldmx4(qh[ks][0], qh[ks][1], qh[ks][2], qh[ks][3], off);
    }

    float oacc[8][4];
#pragma unroll
    for (int i = 0; i < 8; i++)
#pragma unroll
        for (int j = 0; j < 4; j++) oacc[i][j] = 0.f;
    float mrow[2] = {-1e30f, -1e30f};
    float lrow[2] = {0.f, 0.f};

    for (int c = 0; c < 8; c++) {
        const int buf = c & 1;
        if (c + 1 < 8) {
            load_K(c + 1, buf ^ 1);
            load_V(c + 1, buf ^ 1);
            CP_COMMIT();
        }

        float sacc[16][4];
#pragma unroll
        for (int i = 0; i < 16; i++)
#pragma unroll
            for (int j = 0; j < 4; j++) sacc[i][j] = 0.f;

        const uint32_t kb = R + ATT_K_OFF + buf * 18432;
#pragma unroll
        for (int ks = 0; ks < 4; ks++) {
#pragma unroll
            for (int ntp = 0; ntp < 8; ntp++) {
                uint32_t bb[4];
                uint32_t off = kb + (((ntp << 4) + ((x4m >> 1) << 3) + x4r) * 72 +
                                     (ks << 4) + ((x4m & 1) << 3)) * 2;
                ldmx4(bb[0], bb[1], bb[2], bb[3], off);
                mma16816(sacc[2 * ntp],     qh[ks], bb);
                mma16816(sacc[2 * ntp + 1], qh[ks], bb + 2);
            }
        }

        float cm[2];
#pragma unroll
        for (int rr = 0; rr < 2; rr++) {
            float mx = -1e30f;
#pragma unroll
            for (int nt = 0; nt < 16; nt++)
                mx = fmaxf(mx, fmaxf(sacc[nt][rr * 2], sacc[nt][rr * 2 + 1]));
            mx = fmaxf(mx, __shfl_xor_sync(0xffffffffu, mx, 1));
            mx = fmaxf(mx, __shfl_xor_sync(0xffffffffu, mx, 2));
            float mnew = fmaxf(mrow[rr], mx);
            cm[rr] = __expf(mrow[rr] - mnew);
            mrow[rr] = mnew;
        }
        float rs0 = 0.f, rs1 = 0.f;
#pragma unroll
        for (int nt = 0; nt < 16; nt++) {
            sacc[nt][0] = __expf(sacc[nt][0] - mrow[0]);
            sacc[nt][1] = __expf(sacc[nt][1] - mrow[0]);
            sacc[nt][2] = __expf(sacc[nt][2] - mrow[1]);
            sacc[nt][3] = __expf(sacc[nt][3] - mrow[1]);
            rs0 += sacc[nt][0] + sacc[nt][1];
            rs1 += sacc[nt][2] + sacc[nt][3];
        }
        rs0 += __shfl_xor_sync(0xffffffffu, rs0, 1);
        rs0 += __shfl_xor_sync(0xffffffffu, rs0, 2);
        rs1 += __shfl_xor_sync(0xffffffffu, rs1, 1);
        rs1 += __shfl_xor_sync(0xffffffffu, rs1, 2);
        lrow[0] = lrow[0] * cm[0] + rs0;
        lrow[1] = lrow[1] * cm[1] + rs1;

#pragma unroll
        for (int nt = 0; nt < 8; nt++) {
            oacc[nt][0] *= cm[0]; oacc[nt][1] *= cm[0];
            oacc[nt][2] *= cm[1]; oacc[nt][3] *= cm[1];
        }

        uint32_t ph[8][4], pl[8][4];
#pragma unroll
        for (int j = 0; j < 8; j++) {
            pack_split(sacc[2 * j][0],     sacc[2 * j][1],     ph[j][0], pl[j][0]);
            pack_split(sacc[2 * j][2],     sacc[2 * j][3],     ph[j][1], pl[j][1]);
            pack_split(sacc[2 * j + 1][0], sacc[2 * j + 1][1], ph[j][2], pl[j][2]);
            pack_split(sacc[2 * j + 1][2], sacc[2 * j + 1][3], ph[j][3], pl[j][3]);
        }

        const uint32_t vb = R + ATT_V_OFF + buf * 34816;
#pragma unroll
        for (int ks = 0; ks < 8; ks++) {
#pragma unroll
            for (int ntp = 0; ntp < 4; ntp++) {
                uint32_t vh4[4], vl4[4];
                uint32_t off = vb + (((ntp << 4) + ((x4m >> 1) << 3) + x4r) * 136 +
                                     (ks << 4) + ((x4m & 1) << 3)) * 2;
                ldmx4(vh4[0], vh4[1], vh4[2], vh4[3], off);
                ldmx4(vl4[0], vl4[1], vl4[2], vl4[3], off + 17408);
#pragma unroll
                for (int u = 0; u < 2; u++) {
                    int nt = 2 * ntp + u;
                    mma16816(oacc[nt], ph[ks], vh4 + 2 * u);
                    mma16816(oacc[nt], pl[ks], vh4 + 2 * u);
                    mma16816(oacc[nt], ph[ks], vl4 + 2 * u);
                }
            }
        }

        if (c + 1 < 8) { CP_WAIT(0); __syncthreads(); }
    }

    float inv[2] = {1.f / lrow[0], 1.f / lrow[1]};
#pragma unroll
    for (int nt = 0; nt < 8; nt++) {
#pragma unroll
        for (int half = 0; half < 2; half++) {
            int t1 = qt * 128 + wid * 16 + er + half * 8;
            int p = t1 >> 4, qq = t1 & 15;
            int col = nt * 8 + ec;
            float v0 = oacc[nt][half * 2 + 0] * inv[half];
            float v1 = oacc[nt][half * 2 + 1] * inv[half];
            uint32_t hp, lp;
            pack_split(v0, v1, hp, lp);
            int off = (b * 1024 + h * 64 + p) * 1024 + qq * 64 + col;
            *(uint32_t*)(g_Ahi + off) = hp;
            *(uint32_t*)(g_Alo + off) = lp;
        }
    }
}

// ===========================================================================
extern "C" void kernel_launch(void* const* d_in, const int* in_sizes, int n_in,
                              void* d_out, int out_size) {
    const float* x  = (const float*)d_in[0];
    const float* Wq = (const float*)d_in[1];
    const float* bq = (const float*)d_in[2];
    const float* Wk = (const float*)d_in[3];
    const float* bk = (const float*)d_in[4];
    const float* Wv = (const float*)d_in[5];
    const float* bv = (const float*)d_in[6];
    const float* Wo = (const float*)d_in[7];
    const float* bo = (const float*)d_in[8];
    float* out = (float*)d_out;

    __nv_bfloat16 *xhi, *xlo, *whi, *wlo;
    __nv_bfloat16 *qthi, *kthi, *vhi, *vlo, *ahi, *alo;
    cudaGetSymbolAddress((void**)&xhi, g_xhi);
    cudaGetSymbolAddress((void**)&xlo, g_xlo);
    cudaGetSymbolAddress((void**)&whi, g_wt_hi);
    cudaGetSymbolAddress((void**)&wlo, g_wt_lo);
    cudaGetSymbolAddress((void**)&qthi, g_QThi);
    cudaGetSymbolAddress((void**)&kthi, g_KThi);
    cudaGetSymbolAddress((void**)&vhi, g_Vhi);
    cudaGetSymbolAddress((void**)&vlo, g_Vlo);
    cudaGetSymbolAddress((void**)&ahi, g_Ahi);
    cudaGetSymbolAddress((void**)&alo, g_Alo);

    cudaFuncSetAttribute(gemm_mma_kernel<1>, cudaFuncAttributeMaxDynamicSharedMemorySize,
                         GSMEM_BYTES);
    cudaFuncSetAttribute(gemm_mma_kernel<3>, cudaFuncAttributeMaxDynamicSharedMemorySize,
                         GSMEM_BYTES);
    cudaFuncSetAttribute(attn_fa2_kernel, cudaFuncAttributeMaxDynamicSharedMemorySize,
                         ATT_SMEM);

    // 1) split x
    split_f32_kernel<<<2048, 256>>>(x, xhi, xlo, BLN * DIM / 4);

    // 2) transpose+split weights (W^T [n][k])
    dim3 tgrid(32, 32), tblk(32, 8);
    transpose_split_kernel<<<tgrid, tblk>>>(Wq, whi + 0 * DIM * DIM, wlo + 0 * DIM * DIM);
    transpose_split_kernel<<<tgrid, tblk>>>(Wk, whi + 1 * DIM * DIM, wlo + 1 * DIM * DIM);
    transpose_split_kernel<<<tgrid, tblk>>>(Wv, whi + 2 * DIM * DIM, wlo + 2 * DIM * DIM);
    transpose_split_kernel<<<tgrid, tblk>>>(Wo, whi + 3 * DIM * DIM, wlo + 3 * DIM * DIM);

    // 3) projections: Q,K 1-term transposed-hi; V 3-term natural split
    dim3 ggrid(8, 64);
    gemm_mma_kernel<1><<<ggrid, 256, GSMEM_BYTES>>>(xhi, xlo, whi + 0 * DIM * DIM,
                                                    wlo + 0 * DIM * DIM, bq,
                                                    nullptr, qthi, nullptr, QKSCALE, 2);
    gemm_mma_kernel<1><<<ggrid, 256, GSMEM_BYTES>>>(xhi, xlo, whi + 1 * DIM * DIM,
                                                    wlo + 1 * DIM * DIM, bk,
                                                    nullptr, kthi, nullptr, QKSCALE, 2);
    gemm_mma_kernel<3><<<ggrid, 256, GSMEM_BYTES>>>(xhi, xlo, whi + 2 * DIM * DIM,
                                                    wlo + 2 * DIM * DIM, bv,
                                                    nullptr, vhi, vlo, 1.0f, 1);

    // 4) attention (FA2-style, t1=128 per CTA)
    attn_fa2_kernel<<<dim3(8, 128), 256, ATT_SMEM>>>();

    // 5) output projection (3-term, fp32 out)
    gemm_mma_kernel<3><<<ggrid, 256, GSMEM_BYTES>>>(ahi, alo, whi + 3 * DIM * DIM,
                                                    wlo + 3 * DIM * DIM, bo,
                                                    out, nullptr, nullptr, 1.0f, 0);
}

// round 12
// speedup vs baseline: 1.1047x; 1.0604x over previous
#include <cuda_runtime.h>
#include <cuda_bf16.h>
#include <cstdint>

// ===========================================================================
// Problem constants
// ===========================================================================
#define BLN 8192          // B*L
#define DIM 1024          // D
#define QKSCALE 0.03125f  // 1/sqrt(1024)

// ===========================================================================
// Device scratch (allocation-free rule: device globals)
// ===========================================================================
__device__ __nv_bfloat16 g_xhi[BLN * DIM];
__device__ __nv_bfloat16 g_xlo[BLN * DIM];
__device__ __nv_bfloat16 g_wt_hi[4][DIM * DIM];   // W^T [n][k] hi
__device__ __nv_bfloat16 g_wt_lo[4][DIM * DIM];   // W^T [n][k] lo
// Batch-transposed Q,K (hi only — 1-term path): [b][ch=t][l]
__device__ __nv_bfloat16 g_QThi[BLN * DIM];
__device__ __nv_bfloat16 g_KThi[BLN * DIM];
// Natural split V and attention output A: [row=(b,l)][ch]
__device__ __nv_bfloat16 g_Vhi[BLN * DIM];
__device__ __nv_bfloat16 g_Vlo[BLN * DIM];
__device__ __nv_bfloat16 g_Ahi[BLN * DIM];
__device__ __nv_bfloat16 g_Alo[BLN * DIM];

// ===========================================================================
// PTX helpers (sm_80-era: target is plain sm_100, tcgen05 unavailable)
// ===========================================================================
__device__ __forceinline__ uint32_t smem_u32(const void* p) {
    uint32_t a;
    asm("{ .reg .u64 t; cvta.to.shared.u64 t, %1; cvt.u32.u64 %0, t; }" : "=r"(a) : "l"(p));
    return a;
}
#define CP_ASYNC16(saddr, gptr) \
    asm volatile("cp.async.cg.shared.global [%0], [%1], 16;" :: "r"(saddr), "l"(gptr))
#define CP_COMMIT() asm volatile("cp.async.commit_group;" ::: "memory")
#define CP_WAIT(n)  asm volatile("cp.async.wait_group %0;" :: "n"(n) : "memory")

__device__ __forceinline__ void ldmx4(uint32_t& r0, uint32_t& r1, uint32_t& r2, uint32_t& r3,
                                      uint32_t addr) {
    asm volatile("ldmatrix.sync.aligned.m8n8.x4.shared.b16 {%0,%1,%2,%3}, [%4];"
                 : "=r"(r0), "=r"(r1), "=r"(r2), "=r"(r3) : "r"(addr));
}
__device__ __forceinline__ void mma16816(float* c, const uint32_t* a, const uint32_t* b) {
    asm volatile(
        "mma.sync.aligned.m16n8k16.row.col.f32.bf16.bf16.f32 "
        "{%0,%1,%2,%3}, {%4,%5,%6,%7}, {%8,%9}, {%0,%1,%2,%3};"
        : "+f"(c[0]), "+f"(c[1]), "+f"(c[2]), "+f"(c[3])
        : "r"(a[0]), "r"(a[1]), "r"(a[2]), "r"(a[3]), "r"(b[0]), "r"(b[1]));
}
__device__ __forceinline__ void pack_split(float v0, float v1, uint32_t& hi, uint32_t& lo) {
    __nv_bfloat16 h0 = __float2bfloat16(v0);
    __nv_bfloat16 h1 = __float2bfloat16(v1);
    __nv_bfloat162 hp; hp.x = h0; hp.y = h1;
    hi = *(uint32_t*)&hp;
    __nv_bfloat162 lp;
    lp.x = __float2bfloat16(v0 - __bfloat162float(h0));
    lp.y = __float2bfloat16(v1 - __bfloat162float(h1));
    lo = *(uint32_t*)&lp;
}

// ===========================================================================
// Split f32 -> (bf16 hi, bf16 lo)
// ===========================================================================
struct alignas(8) bf4 { __nv_bfloat16 a, b, c, d; };

__global__ void split_f32_kernel(const float* __restrict__ in,
                                 __nv_bfloat16* __restrict__ hi,
                                 __nv_bfloat16* __restrict__ lo, int n4) {
    int i = blockIdx.x * blockDim.x + threadIdx.x;
    int stride = gridDim.x * blockDim.x;
    for (; i < n4; i += stride) {
        float4 v = ((const float4*)in)[i];
        __nv_bfloat16 h0 = __float2bfloat16(v.x);
        __nv_bfloat16 h1 = __float2bfloat16(v.y);
        __nv_bfloat16 h2 = __float2bfloat16(v.z);
        __nv_bfloat16 h3 = __float2bfloat16(v.w);
        bf4 H = {h0, h1, h2, h3};
        bf4 L = {__float2bfloat16(v.x - __bfloat162float(h0)),
                 __float2bfloat16(v.y - __bfloat162float(h1)),
                 __float2bfloat16(v.z - __bfloat162float(h2)),
                 __float2bfloat16(v.w - __bfloat162float(h3))};
        ((bf4*)hi)[i] = H;
        ((bf4*)lo)[i] = L;
    }
}

// ===========================================================================
// Transpose + split: W [K][N] f32 -> W^T [N][K] bf16 hi/lo
// ===========================================================================
__global__ void transpose_split_kernel(const float* __restrict__ W,
                                       __nv_bfloat16* __restrict__ Thi,
                                       __nv_bfloat16* __restrict__ Tlo) {
    __shared__ float t[32][33];
    const int n0 = blockIdx.x << 5;
    const int k0 = blockIdx.y << 5;
    const int tx = threadIdx.x, ty = threadIdx.y;
#pragma unroll
    for (int j = 0; j < 4; j++)
        t[ty + (j << 3)][tx] = W[(k0 + ty + (j << 3)) * DIM + n0 + tx];
    __syncthreads();
#pragma unroll
    for (int j = 0; j < 4; j++) {
        float v = t[tx][ty + (j << 3)];
        __nv_bfloat16 h = __float2bfloat16(v);
        int o = (n0 + ty + (j << 3)) * DIM + k0 + tx;
        Thi[o] = h;
        Tlo[o] = __float2bfloat16(v - __bfloat162float(h));
    }
}

// ===========================================================================
// GEMM body (device function): mma.sync, TERMS split terms, 3-stage pipeline,
// 256 threads / 8 warps / 64x32 warp tiles, x4-only ldmatrix.
// modes: 0 = fp32 natural; 1 = split-bf16 natural; 2 = bf16 transposed [b][ch][l]
// ===========================================================================
#define GSTRIDE 40
#define GTILE_BYTES (128 * GSTRIDE * 2)
#define GSTAGE_BYTES (4 * GTILE_BYTES)
#define GSMEM_BYTES (3 * GSTAGE_BYTES)   // 122880 B (3 stages)

template <int TERMS>
__device__ __forceinline__
void gemm_body(char* smem,
               const __nv_bfloat16* __restrict__ Ahi,
               const __nv_bfloat16* __restrict__ Alo,
               const __nv_bfloat16* __restrict__ Bhi,
               const __nv_bfloat16* __restrict__ Blo,
               const float* __restrict__ bias,
               float* __restrict__ Cf,
               __nv_bfloat16* __restrict__ Chi,
               __nv_bfloat16* __restrict__ Clo,
               float scale, int mode, int m0, int n0) {
    const uint32_t sbase = smem_u32(smem);

    const int tid = threadIdx.x;
    const int wid = tid >> 5;
    const int lane = tid & 31;
    const int wm = (wid & 1) << 6;
    const int wn = (wid >> 1) << 5;

    const __nv_bfloat16* srcs[4] = {Ahi + m0 * 1024, Alo + m0 * 1024,
                                    Bhi + n0 * 1024, Blo + n0 * 1024};

    float acc[4][4][4];
#pragma unroll
    for (int a = 0; a < 4; a++)
#pragma unroll
        for (int b = 0; b < 4; b++)
#pragma unroll
            for (int c = 0; c < 4; c++) acc[a][b][c] = 0.f;

    const int a_r = lane & 15, a_k = lane >> 4;
    const int x4m = lane >> 3;           // matrix index 0..3 for x4 B loads
    const int x4r = lane & 7;            // row within matrix

    auto load_stage = [&](int kt, int buf) {
        const int kb = kt << 5;
        uint32_t sb = sbase + buf * GSTAGE_BYTES;
        constexpr int NLD = (TERMS == 3) ? 8 : 4;
#pragma unroll
        for (int i = 0; i < NLD; i++) {
            int tile, idx;
            if (TERMS == 3) {
                tile = i >> 1;
                idx = ((i & 1) << 8) + tid;
            } else {
                tile = (i >> 1) << 1;       // 0 (Ahi) or 2 (Bhi)
                idx = ((i & 1) << 8) + tid;
            }
            int row = idx >> 2;
            int ch = idx & 3;
            const __nv_bfloat16* g = srcs[tile] + row * 1024 + kb + (ch << 3);
            uint32_t s = sb + tile * GTILE_BYTES + (row * GSTRIDE + (ch << 3)) * 2;
            CP_ASYNC16(s, g);
        }
    };

    load_stage(0, 0); CP_COMMIT();
    load_stage(1, 1); CP_COMMIT();

    for (int kt = 0; kt < 32; kt++) {
        if (kt == 31) { CP_WAIT(0); } else { CP_WAIT(1); }
        __syncthreads();   // all warps done with stage kt-1 -> buffer (kt+2)%3 free
        if (kt + 2 < 32) { load_stage(kt + 2, (kt + 2) % 3); CP_COMMIT(); }

        const uint32_t sb = sbase + (kt % 3) * GSTAGE_BYTES;
        const uint32_t sAhi = sb;
        const uint32_t sAlo = sb + GTILE_BYTES;
        const uint32_t sBhi = sb + 2 * GTILE_BYTES;
        const uint32_t sBlo = sb + 3 * GTILE_BYTES;

#pragma unroll
        for (int ks = 0; ks < 2; ks++) {
            uint32_t ah[4][4], al[4][4], bh[4][2], bl[4][2];
#pragma unroll
            for (int mt = 0; mt < 4; mt++) {
                uint32_t off = ((wm + (mt << 4) + a_r) * GSTRIDE + (ks << 4) + (a_k << 3)) * 2;
                ldmx4(ah[mt][0], ah[mt][1], ah[mt][2], ah[mt][3], sAhi + off);
                if (TERMS == 3)
                    ldmx4(al[mt][0], al[mt][1], al[mt][2], al[mt][3], sAlo + off);
            }
            // B via x4: matrices = (nt-half, k-half); lane x4m selects matrix
#pragma unroll
            for (int ntp = 0; ntp < 2; ntp++) {
                uint32_t off = ((wn + (ntp << 4) + ((x4m >> 1) << 3) + x4r) * GSTRIDE +
                                (ks << 4) + ((x4m & 1) << 3)) * 2;
                ldmx4(bh[2 * ntp][0], bh[2 * ntp][1],
                      bh[2 * ntp + 1][0], bh[2 * ntp + 1][1], sBhi + off);
                if (TERMS == 3)
                    ldmx4(bl[2 * ntp][0], bl[2 * ntp][1],
                          bl[2 * ntp + 1][0], bl[2 * ntp + 1][1], sBlo + off);
            }
#pragma unroll
            for (int mt = 0; mt < 4; mt++)
#pragma unroll
                for (int nt = 0; nt < 4; nt++) {
                    mma16816(acc[mt][nt], ah[mt], bh[nt]);
                    if (TERMS == 3) {
                        mma16816(acc[mt][nt], al[mt], bh[nt]);
                        mma16816(acc[mt][nt], ah[mt], bl[nt]);
                    }
                }
        }
    }
    __syncthreads();   // smem reuse safety for mode-2 staging

    const int er = lane >> 2;
    const int ec = (lane & 3) << 1;

    if (mode == 0) {
#pragma unroll
        for (int mt = 0; mt < 4; mt++) {
#pragma unroll
            for (int nt = 0; nt < 4; nt++) {
                int row = m0 + wm + (mt << 4) + er;
                int col = n0 + wn + (nt << 3) + ec;
                float2 b2 = *(const float2*)(bias + col);
                float2 o0, o1;
                o0.x = (acc[mt][nt][0] + b2.x) * scale;
                o0.y = (acc[mt][nt][1] + b2.y) * scale;
                o1.x = (acc[mt][nt][2] + b2.x) * scale;
                o1.y = (acc[mt][nt][3] + b2.y) * scale;
                *(float2*)(Cf + row * 1024 + col) = o0;
                *(float2*)(Cf + (row + 8) * 1024 + col) = o1;
            }
        }
    } else if (mode == 1) {
#pragma unroll
        for (int mt = 0; mt < 4; mt++) {
#pragma unroll
            for (int nt = 0; nt < 4; nt++) {
                int row = m0 + wm + (mt << 4) + er;
                int col = n0 + wn + (nt << 3) + ec;
                float2 b2 = *(const float2*)(bias + col);
#pragma unroll
                for (int half = 0; half < 2; half++) {
                    int r = row + half * 8;
                    float v0 = (acc[mt][nt][half * 2 + 0] + b2.x) * scale;
                    float v1 = (acc[mt][nt][half * 2 + 1] + b2.y) * scale;
                    uint32_t hp, lp;
                    pack_split(v0, v1, hp, lp);
                    *(uint32_t*)(Chi + r * 1024 + col) = hp;
                    *(uint32_t*)(Clo + r * 1024 + col) = lp;
                }
            }
        }
    } else {
        __nv_bfloat16* sthi = (__nv_bfloat16*)smem;
        __nv_bfloat16* stlo = (__nv_bfloat16*)(smem + 34816);
#pragma unroll
        for (int mt = 0; mt < 4; mt++) {
#pragma unroll
            for (int nt = 0; nt < 4; nt++) {
                int mrow = wm + (mt << 4) + er;
                int ncol = wn + (nt << 3) + ec;
                float2 b2 = *(const float2*)(bias + n0 + ncol);
#pragma unroll
                for (int half = 0; half < 2; half++) {
                    int r = mrow + half * 8;
                    float v0 = (acc[mt][nt][half * 2 + 0] + b2.x) * scale;
                    float v1 = (acc[mt][nt][half * 2 + 1] + b2.y) * scale;
                    __nv_bfloat16 h0 = __float2bfloat16(v0);
                    __nv_bfloat16 h1 = __float2bfloat16(v1);
                    sthi[ncol * 136 + r] = h0;
                    sthi[(ncol + 1) * 136 + r] = h1;
                    if (TERMS == 3) {
                        stlo[ncol * 136 + r] = __float2bfloat16(v0 - __bfloat162float(h0));
                        stlo[(ncol + 1) * 136 + r] = __float2bfloat16(v1 - __bfloat162float(h1));
                    }
                }
            }
        }
        __syncthreads();
        const int bidx = m0 >> 10;
        const int l0 = m0 & 1023;
        constexpr int NCP = (TERMS == 3) ? 16 : 8;
#pragma unroll
        for (int i = 0; i < NCP; i++) {
            int q = tid + (i << 8);
            int t = q >> 11;
            int idx = q & 2047;
            int nrow = idx >> 4;
            int ch = idx & 15;
            uint4 v = *(const uint4*)(smem + t * 34816 + (nrow * 136 + ch * 8) * 2);
            __nv_bfloat16* dst = (t ? Clo : Chi) +
                bidx * 1048576 + (n0 + nrow) * 1024 + l0 + ch * 8;
            *(uint4*)dst = v;
        }
    }
}

// Fused QKV projection: grid (8, 64, 3); z=0 V (3-term, longest — launches
// first for load balance), z=1 Q, z=2 K (1-term).
__global__ __launch_bounds__(256, 1)
void qkv_mma_kernel(const __nv_bfloat16* __restrict__ xhi,
                    const __nv_bfloat16* __restrict__ xlo,
                    const __nv_bfloat16* __restrict__ wq_hi,
                    const __nv_bfloat16* __restrict__ wq_lo,
                    const __nv_bfloat16* __restrict__ wk_hi,
                    const __nv_bfloat16* __restrict__ wk_lo,
                    const __nv_bfloat16* __restrict__ wv_hi,
                    const __nv_bfloat16* __restrict__ wv_lo,
                    const float* __restrict__ bq,
                    const float* __restrict__ bk,
                    const float* __restrict__ bv,
                    __nv_bfloat16* __restrict__ qthi,
                    __nv_bfloat16* __restrict__ kthi,
                    __nv_bfloat16* __restrict__ vhi,
                    __nv_bfloat16* __restrict__ vlo) {
    extern __shared__ __align__(16) char smem[];
    const int m0 = blockIdx.y << 7;
    const int n0 = blockIdx.x << 7;
    const int z = blockIdx.z;
    if (z == 0) {
        gemm_body<3>(smem, xhi, xlo, wv_hi, wv_lo, bv,
                     nullptr, vhi, vlo, 1.0f, 1, m0, n0);
    } else if (z == 1) {
        gemm_body<1>(smem, xhi, xlo, wq_hi, wq_lo, bq,
                     nullptr, qthi, nullptr, QKSCALE, 2, m0, n0);
    } else {
        gemm_body<1>(smem, xhi, xlo, wk_hi, wk_lo, bk,
                     nullptr, kthi, nullptr, QKSCALE, 2, m0, n0);
    }
}

// Standalone output projection (3-term, fp32 out).
__global__ __launch_bounds__(256, 1)
void wo_mma_kernel(const __nv_bfloat16* __restrict__ Ahi,
                   const __nv_bfloat16* __restrict__ Alo,
                   const __nv_bfloat16* __restrict__ Bhi,
                   const __nv_bfloat16* __restrict__ Blo,
                   const float* __restrict__ bias,
                   float* __restrict__ Cf) {
    extern __shared__ __align__(16) char smem[];
    gemm_body<3>(smem, Ahi, Alo, Bhi, Blo, bias,
                 Cf, nullptr, nullptr, 1.0f, 0,
                 blockIdx.y << 7, blockIdx.x << 7);
}

// ===========================================================================
// FlashAttention-2-style attention (round-11 version, x4 loads).
// ===========================================================================
#define ATT_Q_OFF 0                 // Q hi [128][72]            18432 B
#define ATT_K_OFF 18432             // K hi [128][72] x2 bufs    36864 B
#define ATT_V_OFF 55296             // V hi+lo [64][136] x2 bufs 69632 B
#define ATT_SMEM  124928

__global__ __launch_bounds__(256, 1)
void attn_fa2_kernel() {
    extern __shared__ __align__(16) char sm[];
    const uint32_t R = smem_u32(sm);

    const int g = blockIdx.y, qt = blockIdx.x;   // qt: 0..7 (128 rows each)
    const int b = g >> 4, h = g & 15;
    const int tid = threadIdx.x, wid = tid >> 5, lane = tid & 31;

    const int a_r = lane & 15, a_k = lane >> 4;
    const int x4m = lane >> 3;           // matrix index for x4 B loads
    const int x4r = lane & 7;
    const int ec = (lane & 3) << 1;
    const int er = lane >> 2;

    const int qkrow = b * 1048576 + h * 64;

#pragma unroll
    for (int i = 0; i < 4; i++) {
        int q = tid + (i << 8);
        int r = q >> 3, ch = q & 7;
        const __nv_bfloat16* src = g_QThi + qkrow + (qt * 128 + r) * 1024 + ch * 8;
        CP_ASYNC16(R + ATT_Q_OFF + (r * 72 + ch * 8) * 2, src);
    }
    auto load_K = [&](int c, int buf) {
#pragma unroll
        for (int i = 0; i < 4; i++) {
            int q = tid + (i << 8);
            int r = q >> 3, ch = q & 7;
            const __nv_bfloat16* src = g_KThi + qkrow + (c * 128 + r) * 1024 + ch * 8;
            CP_ASYNC16(R + ATT_K_OFF + buf * 18432 + (r * 72 + ch * 8) * 2, src);
        }
    };
    auto load_V = [&](int c, int buf) {
#pragma unroll
        for (int i = 0; i < 8; i++) {
            int q = tid + (i << 8);
            int t = q >> 10, idx = q & 1023;
            int r = idx >> 4, ch = idx & 15;
            const __nv_bfloat16* src =
                (t ? g_Vlo : g_Vhi) + (b * 1024 + h * 64 + r) * 1024 + c * 128 + ch * 8;
            CP_ASYNC16(R + ATT_V_OFF + buf * 34816 + t * 17408 + (r * 136 + ch * 8) * 2, src);
        }
    };
    load_K(0, 0);
    load_V(0, 0);
    CP_COMMIT();
    CP_WAIT(0);
    __syncthreads();

    uint32_t qh[4][4];
#pragma unroll
    for (int ks = 0; ks < 4; ks++) {
        uint32_t off = R + ATT_Q_OFF + ((wid * 16 + a_r) * 72 + ks * 16 + a_k * 8) * 2;
        ldmx4(qh[ks][0], qh[ks][1], qh[ks][2], qh[ks][3], off);
    }

    float oacc[8][4];
#pragma unroll
    for (int i = 0; i < 8; i++)
#pragma unroll
        for (int j = 0; j < 4; j++) oacc[i][j] = 0.f;
    float mrow[2] = {-1e30f, -1e30f};
    float lrow[2] = {0.f, 0.f};

    for (int c = 0; c < 8; c++) {
        const int buf = c & 1;
        if (c + 1 < 8) {
            load_K(c + 1, buf ^ 1);
            load_V(c + 1, buf ^ 1);
            CP_COMMIT();
        }

        float sacc[16][4];
#pragma unroll
        for (int i = 0; i < 16; i++)
#pragma unroll
            for (int j = 0; j < 4; j++) sacc[i][j] = 0.f;

        const uint32_t kb = R + ATT_K_OFF + buf * 18432;
#pragma unroll
        for (int ks = 0; ks < 4; ks++) {
#pragma unroll
            for (int ntp = 0; ntp < 8; ntp++) {
                uint32_t bb[4];
                uint32_t off = kb + (((ntp << 4) + ((x4m >> 1) << 3) + x4r) * 72 +
                                     (ks << 4) + ((x4m & 1) << 3)) * 2;
                ldmx4(bb[0], bb[1], bb[2], bb[3], off);
                mma16816(sacc[2 * ntp],     qh[ks], bb);
                mma16816(sacc[2 * ntp + 1], qh[ks], bb + 2);
            }
        }

        float cm[2];
#pragma unroll
        for (int rr = 0; rr < 2; rr++) {
            float mx = -1e30f;
#pragma unroll
            for (int nt = 0; nt < 16; nt++)
                mx = fmaxf(mx, fmaxf(sacc[nt][rr * 2], sacc[nt][rr * 2 + 1]));
            mx = fmaxf(mx, __shfl_xor_sync(0xffffffffu, mx, 1));
            mx = fmaxf(mx, __shfl_xor_sync(0xffffffffu, mx, 2));
            float mnew = fmaxf(mrow[rr], mx);
            cm[rr] = __expf(mrow[rr] - mnew);
            mrow[rr] = mnew;
        }
        float rs0 = 0.f, rs1 = 0.f;
#pragma unroll
        for (int nt = 0; nt < 16; nt++) {
            sacc[nt][0] = __expf(sacc[nt][0] - mrow[0]);
            sacc[nt][1] = __expf(sacc[nt][1] - mrow[0]);
            sacc[nt][2] = __expf(sacc[nt][2] - mrow[1]);
            sacc[nt][3] = __expf(sacc[nt][3] - mrow[1]);
            rs0 += sacc[nt][0] + sacc[nt][1];
            rs1 += sacc[nt][2] + sacc[nt][3];
        }
        rs0 += __shfl_xor_sync(0xffffffffu, rs0, 1);
        rs0 += __shfl_xor_sync(0xffffffffu, rs0, 2);
        rs1 += __shfl_xor_sync(0xffffffffu, rs1, 1);
        rs1 += __shfl_xor_sync(0xffffffffu, rs1, 2);
        lrow[0] = lrow[0] * cm[0] + rs0;
        lrow[1] = lrow[1] * cm[1] + rs1;

#pragma unroll
        for (int nt = 0; nt < 8; nt++) {
            oacc[nt][0] *= cm[0]; oacc[nt][1] *= cm[0];
            oacc[nt][2] *= cm[1]; oacc[nt][3] *= cm[1];
        }

        uint32_t ph[8][4], pl[8][4];
#pragma unroll
        for (int j = 0; j < 8; j++) {
            pack_split(sacc[2 * j][0],     sacc[2 * j][1],     ph[j][0], pl[j][0]);
            pack_split(sacc[2 * j][2],     sacc[2 * j][3],     ph[j][1], pl[j][1]);
            pack_split(sacc[2 * j + 1][0], sacc[2 * j + 1][1], ph[j][2], pl[j][2]);
            pack_split(sacc[2 * j + 1][2], sacc[2 * j + 1][3], ph[j][3], pl[j][3]);
        }

        const uint32_t vb = R + ATT_V_OFF + buf * 34816;
#pragma unroll
        for (int ks = 0; ks < 8; ks++) {
#pragma unroll
            for (int ntp = 0; ntp < 4; ntp++) {
                uint32_t vh4[4], vl4[4];
                uint32_t off = vb + (((ntp << 4) + ((x4m >> 1) << 3) + x4r) * 136 +
                                     (ks << 4) + ((x4m & 1) << 3)) * 2;
                ldmx4(vh4[0], vh4[1], vh4[2], vh4[3], off);
                ldmx4(vl4[0], vl4[1], vl4[2], vl4[3], off + 17408);
#pragma unroll
                for (int u = 0; u < 2; u++) {
                    int nt = 2 * ntp + u;
                    mma16816(oacc[nt], ph[ks], vh4 + 2 * u);
                    mma16816(oacc[nt], pl[ks], vh4 + 2 * u);
                    mma16816(oacc[nt], ph[ks], vl4 + 2 * u);
                }
            }
        }

        if (c + 1 < 8) { CP_WAIT(0); __syncthreads(); }
    }

    float inv[2] = {1.f / lrow[0], 1.f / lrow[1]};
#pragma unroll
    for (int nt = 0; nt < 8; nt++) {
#pragma unroll
        for (int half = 0; half < 2; half++) {
            int t1 = qt * 128 + wid * 16 + er + half * 8;
            int p = t1 >> 4, qq = t1 & 15;
            int col = nt * 8 + ec;
            float v0 = oacc[nt][half * 2 + 0] * inv[half];
            float v1 = oacc[nt][half * 2 + 1] * inv[half];
            uint32_t hp, lp;
            pack_split(v0, v1, hp, lp);
            int off = (b * 1024 + h * 64 + p) * 1024 + qq * 64 + col;
            *(uint32_t*)(g_Ahi + off) = hp;
            *(uint32_t*)(g_Alo + off) = lp;
        }
    }
}

// ===========================================================================
extern "C" void kernel_launch(void* const* d_in, const int* in_sizes, int n_in,
                              void* d_out, int out_size) {
    const float* x  = (const float*)d_in[0];
    const float* Wq = (const float*)d_in[1];
    const float* bq = (const float*)d_in[2];
    const float* Wk = (const float*)d_in[3];
    const float* bk = (const float*)d_in[4];
    const float* Wv = (const float*)d_in[5];
    const float* bv = (const float*)d_in[6];
    const float* Wo = (const float*)d_in[7];
    const float* bo = (const float*)d_in[8];
    float* out = (float*)d_out;

    __nv_bfloat16 *xhi, *xlo, *whi, *wlo;
    __nv_bfloat16 *qthi, *kthi, *vhi, *vlo, *ahi, *alo;
    cudaGetSymbolAddress((void**)&xhi, g_xhi);
    cudaGetSymbolAddress((void**)&xlo, g_xlo);
    cudaGetSymbolAddress((void**)&whi, g_wt_hi);
    cudaGetSymbolAddress((void**)&wlo, g_wt_lo);
    cudaGetSymbolAddress((void**)&qthi, g_QThi);
    cudaGetSymbolAddress((void**)&kthi, g_KThi);
    cudaGetSymbolAddress((void**)&vhi, g_Vhi);
    cudaGetSymbolAddress((void**)&vlo, g_Vlo);
    cudaGetSymbolAddress((void**)&ahi, g_Ahi);
    cudaGetSymbolAddress((void**)&alo, g_Alo);

    cudaFuncSetAttribute(qkv_mma_kernel, cudaFuncAttributeMaxDynamicSharedMemorySize,
                         GSMEM_BYTES);
    cudaFuncSetAttribute(wo_mma_kernel, cudaFuncAttributeMaxDynamicSharedMemorySize,
                         GSMEM_BYTES);
    cudaFuncSetAttribute(attn_fa2_kernel, cudaFuncAttributeMaxDynamicSharedMemorySize,
                         ATT_SMEM);

    // 1) split x                                                (launch 0)
    split_f32_kernel<<<2048, 256>>>(x, xhi, xlo, BLN * DIM / 4);

    // 2) transpose+split weights (W^T [n][k])                   (launches 1-4)
    dim3 tgrid(32, 32), tblk(32, 8);
    transpose_split_kernel<<<tgrid, tblk>>>(Wq, whi + 0 * DIM * DIM, wlo + 0 * DIM * DIM);
    transpose_split_kernel<<<tgrid, tblk>>>(Wk, whi + 1 * DIM * DIM, wlo + 1 * DIM * DIM);
    transpose_split_kernel<<<tgrid, tblk>>>(Wv, whi + 2 * DIM * DIM, wlo + 2 * DIM * DIM);
    transpose_split_kernel<<<tgrid, tblk>>>(Wo, whi + 3 * DIM * DIM, wlo + 3 * DIM * DIM);

    // 3) fused QKV projections (z=0 V heavy first)              (launch 5 -> ncu)
    qkv_mma_kernel<<<dim3(8, 64, 3), 256, GSMEM_BYTES>>>(
        xhi, xlo,
        whi + 0 * DIM * DIM, wlo + 0 * DIM * DIM,
        whi + 1 * DIM * DIM, wlo + 1 * DIM * DIM,
        whi + 2 * DIM * DIM, wlo + 2 * DIM * DIM,
        bq, bk, bv, qthi, kthi, vhi, vlo);

    // 4) attention (FA2-style, t1=128 per CTA)                  (launch 6)
    attn_fa2_kernel<<<dim3(8, 128), 256, ATT_SMEM>>>();

    // 5) output projection (3-term, fp32 out)                   (launch 7)
    wo_mma_kernel<<<dim3(8, 64), 256, GSMEM_BYTES>>>(ahi, alo, whi + 3 * DIM * DIM,
                                                     wlo + 3 * DIM * DIM, bo, out);
}

// round 13
// speedup vs baseline: 1.1239x; 1.0174x over previous
#include <cuda_runtime.h>
#include <cuda_bf16.h>
#include <cstdint>

// ===========================================================================
// Problem constants
// ===========================================================================
#define BLN 8192          // B*L
#define DIM 1024          // D
#define QKSCALE 0.03125f  // 1/sqrt(1024)

// ===========================================================================
// Device scratch (allocation-free rule: device globals)
// ===========================================================================
__device__ __nv_bfloat16 g_xhi[BLN * DIM];
__device__ __nv_bfloat16 g_xlo[BLN * DIM];
__device__ __nv_bfloat16 g_wt_hi[4][DIM * DIM];   // W^T [n][k] hi
__device__ __nv_bfloat16 g_wt_lo[4][DIM * DIM];   // W^T [n][k] lo
// Batch-transposed Q,K (hi only — 1-term path): [b][ch=t][l]
__device__ __nv_bfloat16 g_QThi[BLN * DIM];
__device__ __nv_bfloat16 g_KThi[BLN * DIM];
// Natural split V and attention output A: [row=(b,l)][ch]
__device__ __nv_bfloat16 g_Vhi[BLN * DIM];
__device__ __nv_bfloat16 g_Vlo[BLN * DIM];
__device__ __nv_bfloat16 g_Ahi[BLN * DIM];
__device__ __nv_bfloat16 g_Alo[BLN * DIM];

// ===========================================================================
// PTX helpers (sm_80-era: target is plain sm_100, tcgen05 unavailable)
// ===========================================================================
__device__ __forceinline__ uint32_t smem_u32(const void* p) {
    uint32_t a;
    asm("{ .reg .u64 t; cvta.to.shared.u64 t, %1; cvt.u32.u64 %0, t; }" : "=r"(a) : "l"(p));
    return a;
}
#define CP_ASYNC16(saddr, gptr) \
    asm volatile("cp.async.cg.shared.global [%0], [%1], 16;" :: "r"(saddr), "l"(gptr))
#define CP_COMMIT() asm volatile("cp.async.commit_group;" ::: "memory")
#define CP_WAIT(n)  asm volatile("cp.async.wait_group %0;" :: "n"(n) : "memory")

__device__ __forceinline__ void ldmx4(uint32_t& r0, uint32_t& r1, uint32_t& r2, uint32_t& r3,
                                      uint32_t addr) {
    asm volatile("ldmatrix.sync.aligned.m8n8.x4.shared.b16 {%0,%1,%2,%3}, [%4];"
                 : "=r"(r0), "=r"(r1), "=r"(r2), "=r"(r3) : "r"(addr));
}
__device__ __forceinline__ void mma16816(float* c, const uint32_t* a, const uint32_t* b) {
    asm volatile(
        "mma.sync.aligned.m16n8k16.row.col.f32.bf16.bf16.f32 "
        "{%0,%1,%2,%3}, {%4,%5,%6,%7}, {%8,%9}, {%0,%1,%2,%3};"
        : "+f"(c[0]), "+f"(c[1]), "+f"(c[2]), "+f"(c[3])
        : "r"(a[0]), "r"(a[1]), "r"(a[2]), "r"(a[3]), "r"(b[0]), "r"(b[1]));
}
__device__ __forceinline__ void pack_split(float v0, float v1, uint32_t& hi, uint32_t& lo) {
    __nv_bfloat16 h0 = __float2bfloat16(v0);
    __nv_bfloat16 h1 = __float2bfloat16(v1);
    __nv_bfloat162 hp; hp.x = h0; hp.y = h1;
    hi = *(uint32_t*)&hp;
    __nv_bfloat162 lp;
    lp.x = __float2bfloat16(v0 - __bfloat162float(h0));
    lp.y = __float2bfloat16(v1 - __bfloat162float(h1));
    lo = *(uint32_t*)&lp;
}

struct alignas(8) bf4 { __nv_bfloat16 a, b, c, d; };

// ===========================================================================
// Fused preprocessing: ONE launch.
//   z=0..3 : transpose+split W[z] [K][N] f32 -> W^T [N][K] bf16 hi/lo
//   z=4    : split x f32 -> bf16 hi/lo (natural layout)
// grid (32, 32, 5), block (32, 8)
// ===========================================================================
__global__ void prep_kernel(const float* __restrict__ x,
                            const float* __restrict__ Wq,
                            const float* __restrict__ Wk,
                            const float* __restrict__ Wv,
                            const float* __restrict__ Wo,
                            __nv_bfloat16* __restrict__ xhi,
                            __nv_bfloat16* __restrict__ xlo,
                            __nv_bfloat16* __restrict__ whi,
                            __nv_bfloat16* __restrict__ wlo) {
    const int z = blockIdx.z;
    const int tx = threadIdx.x, ty = threadIdx.y;
    if (z < 4) {
        const float* W = (z == 0) ? Wq : (z == 1) ? Wk : (z == 2) ? Wv : Wo;
        __nv_bfloat16* Thi = whi + z * DIM * DIM;
        __nv_bfloat16* Tlo = wlo + z * DIM * DIM;
        __shared__ float t[32][33];
        const int n0 = blockIdx.x << 5;
        const int k0 = blockIdx.y << 5;
#pragma unroll
        for (int j = 0; j < 4; j++)
            t[ty + (j << 3)][tx] = W[(k0 + ty + (j << 3)) * DIM + n0 + tx];
        __syncthreads();
#pragma unroll
        for (int j = 0; j < 4; j++) {
            float v = t[tx][ty + (j << 3)];
            __nv_bfloat16 h = __float2bfloat16(v);
            int o = (n0 + ty + (j << 3)) * DIM + k0 + tx;
            Thi[o] = h;
            Tlo[o] = __float2bfloat16(v - __bfloat162float(h));
        }
    } else {
        // split x: 2,097,152 float4 over 1024 blocks x 256 thr x 8 each
        const int flat = (blockIdx.y * 32 + blockIdx.x) * 256 + ty * 32 + tx;
        const float4* in4 = (const float4*)x;
#pragma unroll
        for (int j = 0; j < 8; j++) {
            int i = flat + j * 262144;
            float4 v = in4[i];
            __nv_bfloat16 h0 = __float2bfloat16(v.x);
            __nv_bfloat16 h1 = __float2bfloat16(v.y);
            __nv_bfloat16 h2 = __float2bfloat16(v.z);
            __nv_bfloat16 h3 = __float2bfloat16(v.w);
            bf4 H = {h0, h1, h2, h3};
            bf4 L = {__float2bfloat16(v.x - __bfloat162float(h0)),
                     __float2bfloat16(v.y - __bfloat162float(h1)),
                     __float2bfloat16(v.z - __bfloat162float(h2)),
                     __float2bfloat16(v.w - __bfloat162float(h3))};
            ((bf4*)xhi)[i] = H;
            ((bf4*)xlo)[i] = L;
        }
    }
}

// ===========================================================================
// GEMM body: mma.sync, TERMS split terms, tile 128 x TN, 3-stage pipeline,
// 256 threads / 8 warps. TN=128: 2x4 warp grid (64x32 tiles). TN=64: 2x4
// warp grid (64x16 tiles). x4-only ldmatrix.
// modes: 0 = fp32 natural; 1 = split-bf16 natural; 2 = bf16 transposed [b][ch][l]
// ===========================================================================
#define GSTRIDE 40
#define ATILE_B (128 * GSTRIDE * 2)          // 10240

template <int TERMS, int TN>
__device__ __forceinline__
void gemm_body(char* smem,
               const __nv_bfloat16* __restrict__ Ahi,
               const __nv_bfloat16* __restrict__ Alo,
               const __nv_bfloat16* __restrict__ Bhi,
               const __nv_bfloat16* __restrict__ Blo,
               const float* __restrict__ bias,
               float* __restrict__ Cf,
               __nv_bfloat16* __restrict__ Chi,
               __nv_bfloat16* __restrict__ Clo,
               float scale, int mode, int m0, int n0) {
    constexpr int BTILE_B = TN * GSTRIDE * 2;         // 10240 or 5120
    constexpr int SSTAGE = 2 * ATILE_B + 2 * BTILE_B; // 40960 or 30720
    constexpr int NT = TN / 32;                        // n-tiles per warp (4 or 2)

    const uint32_t sbase = smem_u32(smem);

    const int tid = threadIdx.x;
    const int wid = tid >> 5;
    const int lane = tid & 31;
    const int wm = (wid & 1) << 6;
    const int wn = (wid >> 1) * (TN / 4);

    const __nv_bfloat16* srcs[4] = {Ahi + m0 * 1024, Alo + m0 * 1024,
                                    Bhi + n0 * 1024, Blo + n0 * 1024};

    float acc[4][NT][4];
#pragma unroll
    for (int a = 0; a < 4; a++)
#pragma unroll
        for (int b = 0; b < NT; b++)
#pragma unroll
            for (int c = 0; c < 4; c++) acc[a][b][c] = 0.f;

    const int a_r = lane & 15, a_k = lane >> 4;
    const int x4m = lane >> 3;           // matrix index 0..3 for x4 B loads
    const int x4r = lane & 7;            // row within matrix

    auto load_stage = [&](int kt, int buf) {
        const int kb = kt << 5;
        uint32_t sb = sbase + buf * SSTAGE;
        // A hi (+lo): 512 chunks each
#pragma unroll
        for (int j = 0; j < 2; j++) {
            int idx = (j << 8) + tid;
            int row = idx >> 2, ch = idx & 3;
            CP_ASYNC16(sb + (row * GSTRIDE + (ch << 3)) * 2,
                       srcs[0] + row * 1024 + kb + (ch << 3));
        }
        if (TERMS == 3) {
#pragma unroll
            for (int j = 0; j < 2; j++) {
                int idx = (j << 8) + tid;
                int row = idx >> 2, ch = idx & 3;
                CP_ASYNC16(sb + ATILE_B + (row * GSTRIDE + (ch << 3)) * 2,
                           srcs[1] + row * 1024 + kb + (ch << 3));
            }
        }
        // B hi (+lo): TN*4/256 iterations (2 or 1)
#pragma unroll
        for (int j = 0; j < TN / 64; j++) {
            int idx = (j << 8) + tid;
            int row = idx >> 2, ch = idx & 3;
            CP_ASYNC16(sb + 2 * ATILE_B + (row * GSTRIDE + (ch << 3)) * 2,
                       srcs[2] + row * 1024 + kb + (ch << 3));
        }
        if (TERMS == 3) {
#pragma unroll
            for (int j = 0; j < TN / 64; j++) {
                int idx = (j << 8) + tid;
                int row = idx >> 2, ch = idx & 3;
                CP_ASYNC16(sb + 2 * ATILE_B + BTILE_B + (row * GSTRIDE + (ch << 3)) * 2,
                           srcs[3] + row * 1024 + kb + (ch << 3));
            }
        }
    };

    load_stage(0, 0); CP_COMMIT();
    load_stage(1, 1); CP_COMMIT();

    for (int kt = 0; kt < 32; kt++) {
        if (kt == 31) { CP_WAIT(0); } else { CP_WAIT(1); }
        __syncthreads();   // all warps done with stage kt-1 -> buffer (kt+2)%3 free
        if (kt + 2 < 32) { load_stage(kt + 2, (kt + 2) % 3); CP_COMMIT(); }

        const uint32_t sb = sbase + (kt % 3) * SSTAGE;
        const uint32_t sAhi = sb;
        const uint32_t sAlo = sb + ATILE_B;
        const uint32_t sBhi = sb + 2 * ATILE_B;
        const uint32_t sBlo = sb + 2 * ATILE_B + BTILE_B;

#pragma unroll
        for (int ks = 0; ks < 2; ks++) {
            uint32_t ah[4][4], al[4][4], bh[NT][2], bl[NT][2];
#pragma unroll
            for (int mt = 0; mt < 4; mt++) {
                uint32_t off = ((wm + (mt << 4) + a_r) * GSTRIDE + (ks << 4) + (a_k << 3)) * 2;
                ldmx4(ah[mt][0], ah[mt][1], ah[mt][2], ah[mt][3], sAhi + off);
                if (TERMS == 3)
                    ldmx4(al[mt][0], al[mt][1], al[mt][2], al[mt][3], sAlo + off);
            }
            // B via x4: one load covers 2 n-tiles (16 cols)
#pragma unroll
            for (int ntp = 0; ntp < NT / 2; ntp++) {
                uint32_t off = ((wn + (ntp << 4) + ((x4m >> 1) << 3) + x4r) * GSTRIDE +
                                (ks << 4) + ((x4m & 1) << 3)) * 2;
                ldmx4(bh[2 * ntp][0], bh[2 * ntp][1],
                      bh[2 * ntp + 1][0], bh[2 * ntp + 1][1], sBhi + off);
                if (TERMS == 3)
                    ldmx4(bl[2 * ntp][0], bl[2 * ntp][1],
                          bl[2 * ntp + 1][0], bl[2 * ntp + 1][1], sBlo + off);
            }
#pragma unroll
            for (int mt = 0; mt < 4; mt++)
#pragma unroll
                for (int nt = 0; nt < NT; nt++) {
                    mma16816(acc[mt][nt], ah[mt], bh[nt]);
                    if (TERMS == 3) {
                        mma16816(acc[mt][nt], al[mt], bh[nt]);
                        mma16816(acc[mt][nt], ah[mt], bl[nt]);
                    }
                }
        }
    }
    __syncthreads();   // smem reuse safety for mode-2 staging

    const int er = lane >> 2;
    const int ec = (lane & 3) << 1;

    if (mode == 0) {
#pragma unroll
        for (int mt = 0; mt < 4; mt++) {
#pragma unroll
            for (int nt = 0; nt < NT; nt++) {
                int row = m0 + wm + (mt << 4) + er;
                int col = n0 + wn + (nt << 3) + ec;
                float2 b2 = *(const float2*)(bias + col);
                float2 o0, o1;
                o0.x = (acc[mt][nt][0] + b2.x) * scale;
                o0.y = (acc[mt][nt][1] + b2.y) * scale;
                o1.x = (acc[mt][nt][2] + b2.x) * scale;
                o1.y = (acc[mt][nt][3] + b2.y) * scale;
                *(float2*)(Cf + row * 1024 + col) = o0;
                *(float2*)(Cf + (row + 8) * 1024 + col) = o1;
            }
        }
    } else if (mode == 1) {
#pragma unroll
        for (int mt = 0; mt < 4; mt++) {
#pragma unroll
            for (int nt = 0; nt < NT; nt++) {
                int row = m0 + wm + (mt << 4) + er;
                int col = n0 + wn + (nt << 3) + ec;
                float2 b2 = *(const float2*)(bias + col);
#pragma unroll
                for (int half = 0; half < 2; half++) {
                    int r = row + half * 8;
                    float v0 = (acc[mt][nt][half * 2 + 0] + b2.x) * scale;
                    float v1 = (acc[mt][nt][half * 2 + 1] + b2.y) * scale;
                    uint32_t hp, lp;
                    pack_split(v0, v1, hp, lp);
                    *(uint32_t*)(Chi + r * 1024 + col) = hp;
                    *(uint32_t*)(Clo + r * 1024 + col) = lp;
                }
            }
        }
    } else {
        __nv_bfloat16* sthi = (__nv_bfloat16*)smem;
        __nv_bfloat16* stlo = (__nv_bfloat16*)(smem + 34816);
#pragma unroll
        for (int mt = 0; mt < 4; mt++) {
#pragma unroll
            for (int nt = 0; nt < NT; nt++) {
                int mrow = wm + (mt << 4) + er;
                int ncol = wn + (nt << 3) + ec;
                float2 b2 = *(const float2*)(bias + n0 + ncol);
#pragma unroll
                for (int half = 0; half < 2; half++) {
                    int r = mrow + half * 8;
                    float v0 = (acc[mt][nt][half * 2 + 0] + b2.x) * scale;
                    float v1 = (acc[mt][nt][half * 2 + 1] + b2.y) * scale;
                    __nv_bfloat16 h0 = __float2bfloat16(v0);
                    __nv_bfloat16 h1 = __float2bfloat16(v1);
                    sthi[ncol * 136 + r] = h0;
                    sthi[(ncol + 1) * 136 + r] = h1;
                    if (TERMS == 3) {
                        stlo[ncol * 136 + r] = __float2bfloat16(v0 - __bfloat162float(h0));
                        stlo[(ncol + 1) * 136 + r] = __float2bfloat16(v1 - __bfloat162float(h1));
                    }
                }
            }
        }
        __syncthreads();
        const int bidx = m0 >> 10;
        const int l0 = m0 & 1023;
        constexpr int NCP = (TERMS == 3) ? 16 : 8;
#pragma unroll
        for (int i = 0; i < NCP; i++) {
            int q = tid + (i << 8);
            int t = q >> 11;
            int idx = q & 2047;
            int nrow = idx >> 4;
            int ch = idx & 15;
            uint4 v = *(const uint4*)(smem + t * 34816 + (nrow * 136 + ch * 8) * 2);
            __nv_bfloat16* dst = (t ? Clo : Chi) +
                bidx * 1048576 + (n0 + nrow) * 1024 + l0 + ch * 8;
            *(uint4*)dst = v;
        }
    }
}

#define GSMEM_QKV (3 * (2 * ATILE_B + 2 * (128 * GSTRIDE * 2)))  // 122880
#define GSMEM_WO  (3 * (2 * ATILE_B + 2 * (64 * GSTRIDE * 2)))   // 92160

// Fused QKV projection: grid (8, 64, 3); z=0 V (3-term, heaviest, first).
__global__ __launch_bounds__(256, 1)
void qkv_mma_kernel(const __nv_bfloat16* __restrict__ xhi,
                    const __nv_bfloat16* __restrict__ xlo,
                    const __nv_bfloat16* __restrict__ wq_hi,
                    const __nv_bfloat16* __restrict__ wq_lo,
                    const __nv_bfloat16* __restrict__ wk_hi,
                    const __nv_bfloat16* __restrict__ wk_lo,
                    const __nv_bfloat16* __restrict__ wv_hi,
                    const __nv_bfloat16* __restrict__ wv_lo,
                    const float* __restrict__ bq,
                    const float* __restrict__ bk,
                    const float* __restrict__ bv,
                    __nv_bfloat16* __restrict__ qthi,
                    __nv_bfloat16* __restrict__ kthi,
                    __nv_bfloat16* __restrict__ vhi,
                    __nv_bfloat16* __restrict__ vlo) {
    extern __shared__ __align__(16) char smem[];
    const int m0 = blockIdx.y << 7;
    const int n0 = blockIdx.x << 7;
    const int z = blockIdx.z;
    if (z == 0) {
        gemm_body<3, 128>(smem, xhi, xlo, wv_hi, wv_lo, bv,
                          nullptr, vhi, vlo, 1.0f, 1, m0, n0);
    } else if (z == 1) {
        gemm_body<1, 128>(smem, xhi, xlo, wq_hi, wq_lo, bq,
                          nullptr, qthi, nullptr, QKSCALE, 2, m0, n0);
    } else {
        gemm_body<1, 128>(smem, xhi, xlo, wk_hi, wk_lo, bk,
                          nullptr, kthi, nullptr, QKSCALE, 2, m0, n0);
    }
}

// Output projection, 128x64 tiles (grid 16 x 64) to kill the wave tail.
__global__ __launch_bounds__(256, 1)
void wo_mma_kernel(const __nv_bfloat16* __restrict__ Ahi,
                   const __nv_bfloat16* __restrict__ Alo,
                   const __nv_bfloat16* __restrict__ Bhi,
                   const __nv_bfloat16* __restrict__ Blo,
                   const float* __restrict__ bias,
                   float* __restrict__ Cf) {
    extern __shared__ __align__(16) char smem[];
    gemm_body<3, 64>(smem, Ahi, Alo, Bhi, Blo, bias,
                     Cf, nullptr, nullptr, 1.0f, 0,
                     blockIdx.y << 7, blockIdx.x << 6);
}

// ===========================================================================
// FlashAttention-2-style attention (round-11 version, x4 loads).
// ===========================================================================
#define ATT_Q_OFF 0                 // Q hi [128][72]            18432 B
#define ATT_K_OFF 18432             // K hi [128][72] x2 bufs    36864 B
#define ATT_V_OFF 55296             // V hi+lo [64][136] x2 bufs 69632 B
#define ATT_SMEM  124928

__global__ __launch_bounds__(256, 1)
void attn_fa2_kernel() {
    extern __shared__ __align__(16) char sm[];
    const uint32_t R = smem_u32(sm);

    const int g = blockIdx.y, qt = blockIdx.x;   // qt: 0..7 (128 rows each)
    const int b = g >> 4, h = g & 15;
    const int tid = threadIdx.x, wid = tid >> 5, lane = tid & 31;

    const int a_r = lane & 15, a_k = lane >> 4;
    const int x4m = lane >> 3;           // matrix index for x4 B loads
    const int x4r = lane & 7;
    const int ec = (lane & 3) << 1;
    const int er = lane >> 2;

    const int qkrow = b * 1048576 + h * 64;

#pragma unroll
    for (int i = 0; i < 4; i++) {
        int q = tid + (i << 8);
        int r = q >> 3, ch = q & 7;
        const __nv_bfloat16* src = g_QThi + qkrow + (qt * 128 + r) * 1024 + ch * 8;
        CP_ASYNC16(R + ATT_Q_OFF + (r * 72 + ch * 8) * 2, src);
    }
    auto load_K = [&](int c, int buf) {
#pragma unroll
        for (int i = 0; i < 4; i++) {
            int q = tid + (i << 8);
            int r = q >> 3, ch = q & 7;
            const __nv_bfloat16* src = g_KThi + qkrow + (c * 128 + r) * 1024 + ch * 8;
            CP_ASYNC16(R + ATT_K_OFF + buf * 18432 + (r * 72 + ch * 8) * 2, src);
        }
    };
    auto load_V = [&](int c, int buf) {
#pragma unroll
        for (int i = 0; i < 8; i++) {
            int q = tid + (i << 8);
            int t = q >> 10, idx = q & 1023;
            int r = idx >> 4, ch = idx & 15;
            const __nv_bfloat16* src =
                (t ? g_Vlo : g_Vhi) + (b * 1024 + h * 64 + r) * 1024 + c * 128 + ch * 8;
            CP_ASYNC16(R + ATT_V_OFF + buf * 34816 + t * 17408 + (r * 136 + ch * 8) * 2, src);
        }
    };
    load_K(0, 0);
    load_V(0, 0);
    CP_COMMIT();
    CP_WAIT(0);
    __syncthreads();

    uint32_t qh[4][4];
#pragma unroll
    for (int ks = 0; ks < 4; ks++) {
        uint32_t off = R + ATT_Q_OFF + ((wid * 16 + a_r) * 72 + ks * 16 + a_k * 8) * 2;
        ldmx4(qh[ks][0], qh[ks][1], qh[ks][2], qh[ks][3], off);
    }

    float oacc[8][4];
#pragma unroll
    for (int i = 0; i < 8; i++)
#pragma unroll
        for (int j = 0; j < 4; j++) oacc[i][j] = 0.f;
    float mrow[2] = {-1e30f, -1e30f};
    float lrow[2] = {0.f, 0.f};

    for (int c = 0; c < 8; c++) {
        const int buf = c & 1;
        if (c + 1 < 8) {
            load_K(c + 1, buf ^ 1);
            load_V(c + 1, buf ^ 1);
            CP_COMMIT();
        }

        float sacc[16][4];
#pragma unroll
        for (int i = 0; i < 16; i++)
#pragma unroll
            for (int j = 0; j < 4; j++) sacc[i][j] = 0.f;

        const uint32_t kb = R + ATT_K_OFF + buf * 18432;
#pragma unroll
        for (int ks = 0; ks < 4; ks++) {
#pragma unroll
            for (int ntp = 0; ntp < 8; ntp++) {
                uint32_t bb[4];
                uint32_t off = kb + (((ntp << 4) + ((x4m >> 1) << 3) + x4r) * 72 +
                                     (ks << 4) + ((x4m & 1) << 3)) * 2;
                ldmx4(bb[0], bb[1], bb[2], bb[3], off);
                mma16816(sacc[2 * ntp],     qh[ks], bb);
                mma16816(sacc[2 * ntp + 1], qh[ks], bb + 2);
            }
        }

        float cm[2];
#pragma unroll
        for (int rr = 0; rr < 2; rr++) {
            float mx = -1e30f;
#pragma unroll
            for (int nt = 0; nt < 16; nt++)
                mx = fmaxf(mx, fmaxf(sacc[nt][rr * 2], sacc[nt][rr * 2 + 1]));
            mx = fmaxf(mx, __shfl_xor_sync(0xffffffffu, mx, 1));
            mx = fmaxf(mx, __shfl_xor_sync(0xffffffffu, mx, 2));
            float mnew = fmaxf(mrow[rr], mx);
            cm[rr] = __expf(mrow[rr] - mnew);
            mrow[rr] = mnew;
        }
        float rs0 = 0.f, rs1 = 0.f;
#pragma unroll
        for (int nt = 0; nt < 16; nt++) {
            sacc[nt][0] = __expf(sacc[nt][0] - mrow[0]);
            sacc[nt][1] = __expf(sacc[nt][1] - mrow[0]);
            sacc[nt][2] = __expf(sacc[nt][2] - mrow[1]);
            sacc[nt][3] = __expf(sacc[nt][3] - mrow[1]);
            rs0 += sacc[nt][0] + sacc[nt][1];
            rs1 += sacc[nt][2] + sacc[nt][3];
        }
        rs0 += __shfl_xor_sync(0xffffffffu, rs0, 1);
        rs0 += __shfl_xor_sync(0xffffffffu, rs0, 2);
        rs1 += __shfl_xor_sync(0xffffffffu, rs1, 1);
        rs1 += __shfl_xor_sync(0xffffffffu, rs1, 2);
        lrow[0] = lrow[0] * cm[0] + rs0;
        lrow[1] = lrow[1] * cm[1] + rs1;

#pragma unroll
        for (int nt = 0; nt < 8; nt++) {
            oacc[nt][0] *= cm[0]; oacc[nt][1] *= cm[0];
            oacc[nt][2] *= cm[1]; oacc[nt][3] *= cm[1];
        }

        uint32_t ph[8][4], pl[8][4];
#pragma unroll
        for (int j = 0; j < 8; j++) {
            pack_split(sacc[2 * j][0],     sacc[2 * j][1],     ph[j][0], pl[j][0]);
            pack_split(sacc[2 * j][2],     sacc[2 * j][3],     ph[j][1], pl[j][1]);
            pack_split(sacc[2 * j + 1][0], sacc[2 * j + 1][1], ph[j][2], pl[j][2]);
            pack_split(sacc[2 * j + 1][2], sacc[2 * j + 1][3], ph[j][3], pl[j][3]);
        }

        const uint32_t vb = R + ATT_V_OFF + buf * 34816;
#pragma unroll
        for (int ks = 0; ks < 8; ks++) {
#pragma unroll
            for (int ntp = 0; ntp < 4; ntp++) {
                uint32_t vh4[4], vl4[4];
                uint32_t off = vb + (((ntp << 4) + ((x4m >> 1) << 3) + x4r) * 136 +
                                     (ks << 4) + ((x4m & 1) << 3)) * 2;
                ldmx4(vh4[0], vh4[1], vh4[2], vh4[3], off);
                ldmx4(vl4[0], vl4[1], vl4[2], vl4[3], off + 17408);
#pragma unroll
                for (int u = 0; u < 2; u++) {
                    int nt = 2 * ntp + u;
                    mma16816(oacc[nt], ph[ks], vh4 + 2 * u);
                    mma16816(oacc[nt], pl[ks], vh4 + 2 * u);
                    mma16816(oacc[nt], ph[ks], vl4 + 2 * u);
                }
            }
        }

        if (c + 1 < 8) { CP_WAIT(0); __syncthreads(); }
    }

    float inv[2] = {1.f / lrow[0], 1.f / lrow[1]};
#pragma unroll
    for (int nt = 0; nt < 8; nt++) {
#pragma unroll
        for (int half = 0; half < 2; half++) {
            int t1 = qt * 128 + wid * 16 + er + half * 8;
            int p = t1 >> 4, qq = t1 & 15;
            int col = nt * 8 + ec;
            float v0 = oacc[nt][half * 2 + 0] * inv[half];
            float v1 = oacc[nt][half * 2 + 1] * inv[half];
            uint32_t hp, lp;
            pack_split(v0, v1, hp, lp);
            int off = (b * 1024 + h * 64 + p) * 1024 + qq * 64 + col;
            *(uint32_t*)(g_Ahi + off) = hp;
            *(uint32_t*)(g_Alo + off) = lp;
        }
    }
}

// ===========================================================================
extern "C" void kernel_launch(void* const* d_in, const int* in_sizes, int n_in,
                              void* d_out, int out_size) {
    const float* x  = (const float*)d_in[0];
    const float* Wq = (const float*)d_in[1];
    const float* bq = (const float*)d_in[2];
    const float* Wk = (const float*)d_in[3];
    const float* bk = (const float*)d_in[4];
    const float* Wv = (const float*)d_in[5];
    const float* bv = (const float*)d_in[6];
    const float* Wo = (const float*)d_in[7];
    const float* bo = (const float*)d_in[8];
    float* out = (float*)d_out;

    __nv_bfloat16 *xhi, *xlo, *whi, *wlo;
    __nv_bfloat16 *qthi, *kthi, *vhi, *vlo, *ahi, *alo;
    cudaGetSymbolAddress((void**)&xhi, g_xhi);
    cudaGetSymbolAddress((void**)&xlo, g_xlo);
    cudaGetSymbolAddress((void**)&whi, g_wt_hi);
    cudaGetSymbolAddress((void**)&wlo, g_wt_lo);
    cudaGetSymbolAddress((void**)&qthi, g_QThi);
    cudaGetSymbolAddress((void**)&kthi, g_KThi);
    cudaGetSymbolAddress((void**)&vhi, g_Vhi);
    cudaGetSymbolAddress((void**)&vlo, g_Vlo);
    cudaGetSymbolAddress((void**)&ahi, g_Ahi);
    cudaGetSymbolAddress((void**)&alo, g_Alo);

    cudaFuncSetAttribute(qkv_mma_kernel, cudaFuncAttributeMaxDynamicSharedMemorySize,
                         GSMEM_QKV);
    cudaFuncSetAttribute(wo_mma_kernel, cudaFuncAttributeMaxDynamicSharedMemorySize,
                         GSMEM_WO);
    cudaFuncSetAttribute(attn_fa2_kernel, cudaFuncAttributeMaxDynamicSharedMemorySize,
                         ATT_SMEM);

    // 1) fused preprocessing: x split + 4 weight transposes      (launch 0)
    prep_kernel<<<dim3(32, 32, 5), dim3(32, 8)>>>(x, Wq, Wk, Wv, Wo,
                                                  xhi, xlo, whi, wlo);

    // 2) fused QKV projections (z=0 V heavy first)               (launch 1)
    qkv_mma_kernel<<<dim3(8, 64, 3), 256, GSMEM_QKV>>>(
        xhi, xlo,
        whi + 0 * DIM * DIM, wlo + 0 * DIM * DIM,
        whi + 1 * DIM * DIM, wlo + 1 * DIM * DIM,
        whi + 2 * DIM * DIM, wlo + 2 * DIM * DIM,
        bq, bk, bv, qthi, kthi, vhi, vlo);

    // 3) attention (FA2-style, t1=128 per CTA)                   (launch 2)
    attn_fa2_kernel<<<dim3(8, 128), 256, ATT_SMEM>>>();

    // 4) output projection (3-term, 128x64 tiles, fp32 out)      (launch 3)
    wo_mma_kernel<<<dim3(16, 64), 256, GSMEM_WO>>>(ahi, alo, whi + 3 * DIM * DIM,
                                                   wlo + 3 * DIM * DIM, bo, out);
}

// round 14
// speedup vs baseline: 1.1487x; 1.0221x over previous
#include <cuda_runtime.h>
#include <cuda_bf16.h>
#include <cstdint>

// ===========================================================================
// Problem constants
// ===========================================================================
#define BLN 8192          // B*L
#define DIM 1024          // D
#define QKSCALE 0.03125f  // 1/sqrt(1024)

// ===========================================================================
// Device scratch (allocation-free rule: device globals)
// ===========================================================================
__device__ __nv_bfloat16 g_xhi[BLN * DIM];
__device__ __nv_bfloat16 g_xlo[BLN * DIM];
__device__ __nv_bfloat16 g_wt_hi[4][DIM * DIM];   // W^T [n][k] hi
__device__ __nv_bfloat16 g_wt_lo[4][DIM * DIM];   // W^T [n][k] lo
// Batch-transposed Q,K (hi only — 1-term path): [b][ch=t][l]
__device__ __nv_bfloat16 g_QThi[BLN * DIM];
__device__ __nv_bfloat16 g_KThi[BLN * DIM];
// Natural split V and attention output A: [row=(b,l)][ch]
__device__ __nv_bfloat16 g_Vhi[BLN * DIM];
__device__ __nv_bfloat16 g_Vlo[BLN * DIM];
__device__ __nv_bfloat16 g_Ahi[BLN * DIM];
__device__ __nv_bfloat16 g_Alo[BLN * DIM];

// ===========================================================================
// PTX helpers (sm_80-era: target is plain sm_100, tcgen05 unavailable)
// ===========================================================================
__device__ __forceinline__ uint32_t smem_u32(const void* p) {
    uint32_t a;
    asm("{ .reg .u64 t; cvta.to.shared.u64 t, %1; cvt.u32.u64 %0, t; }" : "=r"(a) : "l"(p));
    return a;
}
#define CP_ASYNC16(saddr, gptr) \
    asm volatile("cp.async.cg.shared.global [%0], [%1], 16;" :: "r"(saddr), "l"(gptr))
#define CP_COMMIT() asm volatile("cp.async.commit_group;" ::: "memory")
#define CP_WAIT(n)  asm volatile("cp.async.wait_group %0;" :: "n"(n) : "memory")

__device__ __forceinline__ void ldmx4(uint32_t& r0, uint32_t& r1, uint32_t& r2, uint32_t& r3,
                                      uint32_t addr) {
    asm volatile("ldmatrix.sync.aligned.m8n8.x4.shared.b16 {%0,%1,%2,%3}, [%4];"
                 : "=r"(r0), "=r"(r1), "=r"(r2), "=r"(r3) : "r"(addr));
}
__device__ __forceinline__ void mma16816(float* c, const uint32_t* a, const uint32_t* b) {
    asm volatile(
        "mma.sync.aligned.m16n8k16.row.col.f32.bf16.bf16.f32 "
        "{%0,%1,%2,%3}, {%4,%5,%6,%7}, {%8,%9}, {%0,%1,%2,%3};"
        : "+f"(c[0]), "+f"(c[1]), "+f"(c[2]), "+f"(c[3])
        : "r"(a[0]), "r"(a[1]), "r"(a[2]), "r"(a[3]), "r"(b[0]), "r"(b[1]));
}
__device__ __forceinline__ void pack_split(float v0, float v1, uint32_t& hi, uint32_t& lo) {
    __nv_bfloat16 h0 = __float2bfloat16(v0);
    __nv_bfloat16 h1 = __float2bfloat16(v1);
    __nv_bfloat162 hp; hp.x = h0; hp.y = h1;
    hi = *(uint32_t*)&hp;
    __nv_bfloat162 lp;
    lp.x = __float2bfloat16(v0 - __bfloat162float(h0));
    lp.y = __float2bfloat16(v1 - __bfloat162float(h1));
    lo = *(uint32_t*)&lp;
}

struct alignas(8) bf4 { __nv_bfloat16 a, b, c, d; };

// ===========================================================================
// Fused preprocessing: ONE launch.
//   z=0..3 : transpose+split W[z] [K][N] f32 -> W^T [N][K] bf16 hi/lo
//   z=4    : split x f32 -> bf16 hi/lo (natural layout)
// grid (32, 32, 5), block (32, 8)
// ===========================================================================
__global__ void prep_kernel(const float* __restrict__ x,
                            const float* __restrict__ Wq,
                            const float* __restrict__ Wk,
                            const float* __restrict__ Wv,
                            const float* __restrict__ Wo,
                            __nv_bfloat16* __restrict__ xhi,
                            __nv_bfloat16* __restrict__ xlo,
                            __nv_bfloat16* __restrict__ whi,
                            __nv_bfloat16* __restrict__ wlo) {
    const int z = blockIdx.z;
    const int tx = threadIdx.x, ty = threadIdx.y;
    if (z < 4) {
        const float* W = (z == 0) ? Wq : (z == 1) ? Wk : (z == 2) ? Wv : Wo;
        __nv_bfloat16* Thi = whi + z * DIM * DIM;
        __nv_bfloat16* Tlo = wlo + z * DIM * DIM;
        __shared__ float t[32][33];
        const int n0 = blockIdx.x << 5;
        const int k0 = blockIdx.y << 5;
#pragma unroll
        for (int j = 0; j < 4; j++)
            t[ty + (j << 3)][tx] = W[(k0 + ty + (j << 3)) * DIM + n0 + tx];
        __syncthreads();
#pragma unroll
        for (int j = 0; j < 4; j++) {
            float v = t[tx][ty + (j << 3)];
            __nv_bfloat16 h = __float2bfloat16(v);
            int o = (n0 + ty + (j << 3)) * DIM + k0 + tx;
            Thi[o] = h;
            Tlo[o] = __float2bfloat16(v - __bfloat162float(h));
        }
    } else {
        const int flat = (blockIdx.y * 32 + blockIdx.x) * 256 + ty * 32 + tx;
        const float4* in4 = (const float4*)x;
#pragma unroll
        for (int j = 0; j < 8; j++) {
            int i = flat + j * 262144;
            float4 v = in4[i];
            __nv_bfloat16 h0 = __float2bfloat16(v.x);
            __nv_bfloat16 h1 = __float2bfloat16(v.y);
            __nv_bfloat16 h2 = __float2bfloat16(v.z);
            __nv_bfloat16 h3 = __float2bfloat16(v.w);
            bf4 H = {h0, h1, h2, h3};
            bf4 L = {__float2bfloat16(v.x - __bfloat162float(h0)),
                     __float2bfloat16(v.y - __bfloat162float(h1)),
                     __float2bfloat16(v.z - __bfloat162float(h2)),
                     __float2bfloat16(v.w - __bfloat162float(h3))};
            ((bf4*)xhi)[i] = H;
            ((bf4*)xlo)[i] = L;
        }
    }
}

// ===========================================================================
// GEMM body: mma.sync, TERMS split terms, tile 128 x TN, 3-stage pipeline,
// 256 threads / 8 warps (2x4 warp grid, 64 x TN/4 warp tiles), x4 ldmatrix.
// modes: 0 = fp32 natural; 1 = split-bf16 natural; 2 = bf16 transposed [b][ch][l]
// ===========================================================================
#define GSTRIDE 40
#define ATILE_B (128 * GSTRIDE * 2)          // 10240

template <int TERMS, int TN>
__device__ __forceinline__
void gemm_body(char* smem,
               const __nv_bfloat16* __restrict__ Ahi,
               const __nv_bfloat16* __restrict__ Alo,
               const __nv_bfloat16* __restrict__ Bhi,
               const __nv_bfloat16* __restrict__ Blo,
               const float* __restrict__ bias,
               float* __restrict__ Cf,
               __nv_bfloat16* __restrict__ Chi,
               __nv_bfloat16* __restrict__ Clo,
               float scale, int mode, int m0, int n0) {
    constexpr int BTILE_B = TN * GSTRIDE * 2;         // 10240 or 5120
    constexpr int SSTAGE = 2 * ATILE_B + 2 * BTILE_B; // 40960 or 30720
    constexpr int NT = TN / 32;                        // n-tiles per warp (4 or 2)

    const uint32_t sbase = smem_u32(smem);

    const int tid = threadIdx.x;
    const int wid = tid >> 5;
    const int lane = tid & 31;
    const int wm = (wid & 1) << 6;
    const int wn = (wid >> 1) * (TN / 4);

    const __nv_bfloat16* srcs[4] = {Ahi + m0 * 1024, Alo + m0 * 1024,
                                    Bhi + n0 * 1024, Blo + n0 * 1024};

    float acc[4][NT][4];
#pragma unroll
    for (int a = 0; a < 4; a++)
#pragma unroll
        for (int b = 0; b < NT; b++)
#pragma unroll
            for (int c = 0; c < 4; c++) acc[a][b][c] = 0.f;

    const int a_r = lane & 15, a_k = lane >> 4;
    const int x4m = lane >> 3;           // matrix index 0..3 for x4 B loads
    const int x4r = lane & 7;            // row within matrix

    auto load_stage = [&](int kt, int buf) {
        const int kb = kt << 5;
        uint32_t sb = sbase + buf * SSTAGE;
#pragma unroll
        for (int j = 0; j < 2; j++) {
            int idx = (j << 8) + tid;
            int row = idx >> 2, ch = idx & 3;
            CP_ASYNC16(sb + (row * GSTRIDE + (ch << 3)) * 2,
                       srcs[0] + row * 1024 + kb + (ch << 3));
        }
        if (TERMS == 3) {
#pragma unroll
            for (int j = 0; j < 2; j++) {
                int idx = (j << 8) + tid;
                int row = idx >> 2, ch = idx & 3;
                CP_ASYNC16(sb + ATILE_B + (row * GSTRIDE + (ch << 3)) * 2,
                           srcs[1] + row * 1024 + kb + (ch << 3));
            }
        }
#pragma unroll
        for (int j = 0; j < TN / 64; j++) {
            int idx = (j << 8) + tid;
            int row = idx >> 2, ch = idx & 3;
            CP_ASYNC16(sb + 2 * ATILE_B + (row * GSTRIDE + (ch << 3)) * 2,
                       srcs[2] + row * 1024 + kb + (ch << 3));
        }
        if (TERMS == 3) {
#pragma unroll
            for (int j = 0; j < TN / 64; j++) {
                int idx = (j << 8) + tid;
                int row = idx >> 2, ch = idx & 3;
                CP_ASYNC16(sb + 2 * ATILE_B + BTILE_B + (row * GSTRIDE + (ch << 3)) * 2,
                           srcs[3] + row * 1024 + kb + (ch << 3));
            }
        }
    };

    load_stage(0, 0); CP_COMMIT();
    load_stage(1, 1); CP_COMMIT();

    for (int kt = 0; kt < 32; kt++) {
        if (kt == 31) { CP_WAIT(0); } else { CP_WAIT(1); }
        __syncthreads();   // all warps done with stage kt-1 -> buffer (kt+2)%3 free
        if (kt + 2 < 32) { load_stage(kt + 2, (kt + 2) % 3); CP_COMMIT(); }

        const uint32_t sb = sbase + (kt % 3) * SSTAGE;
        const uint32_t sAhi = sb;
        const uint32_t sAlo = sb + ATILE_B;
        const uint32_t sBhi = sb + 2 * ATILE_B;
        const uint32_t sBlo = sb + 2 * ATILE_B + BTILE_B;

#pragma unroll
        for (int ks = 0; ks < 2; ks++) {
            uint32_t ah[4][4], al[4][4], bh[NT][2], bl[NT][2];
#pragma unroll
            for (int mt = 0; mt < 4; mt++) {
                uint32_t off = ((wm + (mt << 4) + a_r) * GSTRIDE + (ks << 4) + (a_k << 3)) * 2;
                ldmx4(ah[mt][0], ah[mt][1], ah[mt][2], ah[mt][3], sAhi + off);
                if (TERMS == 3)
                    ldmx4(al[mt][0], al[mt][1], al[mt][2], al[mt][3], sAlo + off);
            }
#pragma unroll
            for (int ntp = 0; ntp < NT / 2; ntp++) {
                uint32_t off = ((wn + (ntp << 4) + ((x4m >> 1) << 3) + x4r) * GSTRIDE +
                                (ks << 4) + ((x4m & 1) << 3)) * 2;
                ldmx4(bh[2 * ntp][0], bh[2 * ntp][1],
                      bh[2 * ntp + 1][0], bh[2 * ntp + 1][1], sBhi + off);
                if (TERMS == 3)
                    ldmx4(bl[2 * ntp][0], bl[2 * ntp][1],
                          bl[2 * ntp + 1][0], bl[2 * ntp + 1][1], sBlo + off);
            }
#pragma unroll
            for (int mt = 0; mt < 4; mt++)
#pragma unroll
                for (int nt = 0; nt < NT; nt++) {
                    mma16816(acc[mt][nt], ah[mt], bh[nt]);
                    if (TERMS == 3) {
                        mma16816(acc[mt][nt], al[mt], bh[nt]);
                        mma16816(acc[mt][nt], ah[mt], bl[nt]);
                    }
                }
        }
    }
    __syncthreads();   // smem reuse safety for mode-2 staging

    const int er = lane >> 2;
    const int ec = (lane & 3) << 1;

    if (mode == 0) {
#pragma unroll
        for (int mt = 0; mt < 4; mt++) {
#pragma unroll
            for (int nt = 0; nt < NT; nt++) {
                int row = m0 + wm + (mt << 4) + er;
                int col = n0 + wn + (nt << 3) + ec;
                float2 b2 = *(const float2*)(bias + col);
                float2 o0, o1;
                o0.x = (acc[mt][nt][0] + b2.x) * scale;
                o0.y = (acc[mt][nt][1] + b2.y) * scale;
                o1.x = (acc[mt][nt][2] + b2.x) * scale;
                o1.y = (acc[mt][nt][3] + b2.y) * scale;
                *(float2*)(Cf + row * 1024 + col) = o0;
                *(float2*)(Cf + (row + 8) * 1024 + col) = o1;
            }
        }
    } else if (mode == 1) {
#pragma unroll
        for (int mt = 0; mt < 4; mt++) {
#pragma unroll
            for (int nt = 0; nt < NT; nt++) {
                int row = m0 + wm + (mt << 4) + er;
                int col = n0 + wn + (nt << 3) + ec;
                float2 b2 = *(const float2*)(bias + col);
#pragma unroll
                for (int half = 0; half < 2; half++) {
                    int r = row + half * 8;
                    float v0 = (acc[mt][nt][half * 2 + 0] + b2.x) * scale;
                    float v1 = (acc[mt][nt][half * 2 + 1] + b2.y) * scale;
                    uint32_t hp, lp;
                    pack_split(v0, v1, hp, lp);
                    *(uint32_t*)(Chi + r * 1024 + col) = hp;
                    *(uint32_t*)(Clo + r * 1024 + col) = lp;
                }
            }
        }
    } else {
        __nv_bfloat16* sthi = (__nv_bfloat16*)smem;
        __nv_bfloat16* stlo = (__nv_bfloat16*)(smem + 34816);
#pragma unroll
        for (int mt = 0; mt < 4; mt++) {
#pragma unroll
            for (int nt = 0; nt < NT; nt++) {
                int mrow = wm + (mt << 4) + er;
                int ncol = wn + (nt << 3) + ec;
                float2 b2 = *(const float2*)(bias + n0 + ncol);
#pragma unroll
                for (int half = 0; half < 2; half++) {
                    int r = mrow + half * 8;
                    float v0 = (acc[mt][nt][half * 2 + 0] + b2.x) * scale;
                    float v1 = (acc[mt][nt][half * 2 + 1] + b2.y) * scale;
                    __nv_bfloat16 h0 = __float2bfloat16(v0);
                    __nv_bfloat16 h1 = __float2bfloat16(v1);
                    sthi[ncol * 136 + r] = h0;
                    sthi[(ncol + 1) * 136 + r] = h1;
                    if (TERMS == 3) {
                        stlo[ncol * 136 + r] = __float2bfloat16(v0 - __bfloat162float(h0));
                        stlo[(ncol + 1) * 136 + r] = __float2bfloat16(v1 - __bfloat162float(h1));
                    }
                }
            }
        }
        __syncthreads();
        const int bidx = m0 >> 10;
        const int l0 = m0 & 1023;
        constexpr int CHT = TN * 16;                       // 16B chunks per tile
        constexpr int NCP = (CHT * ((TERMS == 3) ? 2 : 1)) / 256;
#pragma unroll
        for (int i = 0; i < NCP; i++) {
            int q = tid + (i << 8);
            int t = q / CHT;
            int idx = q % CHT;
            int nrow = idx >> 4;
            int ch = idx & 15;
            uint4 v = *(const uint4*)(smem + t * 34816 + (nrow * 136 + ch * 8) * 2);
            __nv_bfloat16* dst = (t ? Clo : Chi) +
                bidx * 1048576 + (n0 + nrow) * 1024 + l0 + ch * 8;
            *(uint4*)dst = v;
        }
    }
}

#define GSMEM_QKV (3 * (2 * ATILE_B + 2 * (64 * GSTRIDE * 2)))  // 92160 -> 2 CTAs/SM
#define GSMEM_WO  (3 * (2 * ATILE_B + 2 * (64 * GSTRIDE * 2)))  // 92160

// Fused QKV projection: grid (16, 64, 3), TN=64 tiles; z=0 V (3-term) first.
__global__ __launch_bounds__(256, 1)
void qkv_mma_kernel(const __nv_bfloat16* __restrict__ xhi,
                    const __nv_bfloat16* __restrict__ xlo,
                    const __nv_bfloat16* __restrict__ wq_hi,
                    const __nv_bfloat16* __restrict__ wq_lo,
                    const __nv_bfloat16* __restrict__ wk_hi,
                    const __nv_bfloat16* __restrict__ wk_lo,
                    const __nv_bfloat16* __restrict__ wv_hi,
                    const __nv_bfloat16* __restrict__ wv_lo,
                    const float* __restrict__ bq,
                    const float* __restrict__ bk,
                    const float* __restrict__ bv,
                    __nv_bfloat16* __restrict__ qthi,
                    __nv_bfloat16* __restrict__ kthi,
                    __nv_bfloat16* __restrict__ vhi,
                    __nv_bfloat16* __restrict__ vlo) {
    extern __shared__ __align__(16) char smem[];
    const int m0 = blockIdx.y << 7;
    const int n0 = blockIdx.x << 6;
    const int z = blockIdx.z;
    if (z == 0) {
        gemm_body<3, 64>(smem, xhi, xlo, wv_hi, wv_lo, bv,
                         nullptr, vhi, vlo, 1.0f, 1, m0, n0);
    } else if (z == 1) {
        gemm_body<1, 64>(smem, xhi, xlo, wq_hi, wq_lo, bq,
                         nullptr, qthi, nullptr, QKSCALE, 2, m0, n0);
    } else {
        gemm_body<1, 64>(smem, xhi, xlo, wk_hi, wk_lo, bk,
                         nullptr, kthi, nullptr, QKSCALE, 2, m0, n0);
    }
}

// Output projection, 128x64 tiles (grid 16 x 64).
__global__ __launch_bounds__(256, 1)
void wo_mma_kernel(const __nv_bfloat16* __restrict__ Ahi,
                   const __nv_bfloat16* __restrict__ Alo,
                   const __nv_bfloat16* __restrict__ Bhi,
                   const __nv_bfloat16* __restrict__ Blo,
                   const float* __restrict__ bias,
                   float* __restrict__ Cf) {
    extern __shared__ __align__(16) char smem[];
    gemm_body<3, 64>(smem, Ahi, Alo, Bhi, Blo, bias,
                     Cf, nullptr, nullptr, 1.0f, 0,
                     blockIdx.y << 7, blockIdx.x << 6);
}

// ===========================================================================
// FlashAttention-2-style attention (round-11 version, x4 loads).
// ===========================================================================
#define ATT_Q_OFF 0                 // Q hi [128][72]            18432 B
#define ATT_K_OFF 18432             // K hi [128][72] x2 bufs    36864 B
#define ATT_V_OFF 55296             // V hi+lo [64][136] x2 bufs 69632 B
#define ATT_SMEM  124928

__global__ __launch_bounds__(256, 1)
void attn_fa2_kernel() {
    extern __shared__ __align__(16) char sm[];
    const uint32_t R = smem_u32(sm);

    const int g = blockIdx.y, qt = blockIdx.x;   // qt: 0..7 (128 rows each)
    const int b = g >> 4, h = g & 15;
    const int tid = threadIdx.x, wid = tid >> 5, lane = tid & 31;

    const int a_r = lane & 15, a_k = lane >> 4;
    const int x4m = lane >> 3;           // matrix index for x4 B loads
    const int x4r = lane & 7;
    const int ec = (lane & 3) << 1;
    const int er = lane >> 2;

    const int qkrow = b * 1048576 + h * 64;

#pragma unroll
    for (int i = 0; i < 4; i++) {
        int q = tid + (i << 8);
        int r = q >> 3, ch = q & 7;
        const __nv_bfloat16* src = g_QThi + qkrow + (qt * 128 + r) * 1024 + ch * 8;
        CP_ASYNC16(R + ATT_Q_OFF + (r * 72 + ch * 8) * 2, src);
    }
    auto load_K = [&](int c, int buf) {
#pragma unroll
        for (int i = 0; i < 4; i++) {
            int q = tid + (i << 8);
            int r = q >> 3, ch = q & 7;
            const __nv_bfloat16* src = g_KThi + qkrow + (c * 128 + r) * 1024 + ch * 8;
            CP_ASYNC16(R + ATT_K_OFF + buf * 18432 + (r * 72 + ch * 8) * 2, src);
        }
    };
    auto load_V = [&](int c, int buf) {
#pragma unroll
        for (int i = 0; i < 8; i++) {
            int q = tid + (i << 8);
            int t = q >> 10, idx = q & 1023;
            int r = idx >> 4, ch = idx & 15;
            const __nv_bfloat16* src =
                (t ? g_Vlo : g_Vhi) + (b * 1024 + h * 64 + r) * 1024 + c * 128 + ch * 8;
            CP_ASYNC16(R + ATT_V_OFF + buf * 34816 + t * 17408 + (r * 136 + ch * 8) * 2, src);
        }
    };
    load_K(0, 0);
    load_V(0, 0);
    CP_COMMIT();
    CP_WAIT(0);
    __syncthreads();

    uint32_t qh[4][4];
#pragma unroll
    for (int ks = 0; ks < 4; ks++) {
        uint32_t off = R + ATT_Q_OFF + ((wid * 16 + a_r) * 72 + ks * 16 + a_k * 8) * 2;
        ldmx4(qh[ks][0], qh[ks][1], qh[ks][2], qh[ks][3], off);
    }

    float oacc[8][4];
#pragma unroll
    for (int i = 0; i < 8; i++)
#pragma unroll
        for (int j = 0; j < 4; j++) oacc[i][j] = 0.f;
    float mrow[2] = {-1e30f, -1e30f};
    float lrow[2] = {0.f, 0.f};

    for (int c = 0; c < 8; c++) {
        const int buf = c & 1;
        if (c + 1 < 8) {
            load_K(c + 1, buf ^ 1);
            load_V(c + 1, buf ^ 1);
            CP_COMMIT();
        }

        float sacc[16][4];
#pragma unroll
        for (int i = 0; i < 16; i++)
#pragma unroll
            for (int j = 0; j < 4; j++) sacc[i][j] = 0.f;

        const uint32_t kb = R + ATT_K_OFF + buf * 18432;
#pragma unroll
        for (int ks = 0; ks < 4; ks++) {
#pragma unroll
            for (int ntp = 0; ntp < 8; ntp++) {
                uint32_t bb[4];
                uint32_t off = kb + (((ntp << 4) + ((x4m >> 1) << 3) + x4r) * 72 +
                                     (ks << 4) + ((x4m & 1) << 3)) * 2;
                ldmx4(bb[0], bb[1], bb[2], bb[3], off);
                mma16816(sacc[2 * ntp],     qh[ks], bb);
                mma16816(sacc[2 * ntp + 1], qh[ks], bb + 2);
            }
        }

        float cm[2];
#pragma unroll
        for (int rr = 0; rr < 2; rr++) {
            float mx = -1e30f;
#pragma unroll
            for (int nt = 0; nt < 16; nt++)
                mx = fmaxf(mx, fmaxf(sacc[nt][rr * 2], sacc[nt][rr * 2 + 1]));
            mx = fmaxf(mx, __shfl_xor_sync(0xffffffffu, mx, 1));
            mx = fmaxf(mx, __shfl_xor_sync(0xffffffffu, mx, 2));
            float mnew = fmaxf(mrow[rr], mx);
            cm[rr] = __expf(mrow[rr] - mnew);
            mrow[rr] = mnew;
        }
        float rs0 = 0.f, rs1 = 0.f;
#pragma unroll
        for (int nt = 0; nt < 16; nt++) {
            sacc[nt][0] = __expf(sacc[nt][0] - mrow[0]);
            sacc[nt][1] = __expf(sacc[nt][1] - mrow[0]);
            sacc[nt][2] = __expf(sacc[nt][2] - mrow[1]);
            sacc[nt][3] = __expf(sacc[nt][3] - mrow[1]);
            rs0 += sacc[nt][0] + sacc[nt][1];
            rs1 += sacc[nt][2] + sacc[nt][3];
        }
        rs0 += __shfl_xor_sync(0xffffffffu, rs0, 1);
        rs0 += __shfl_xor_sync(0xffffffffu, rs0, 2);
        rs1 += __shfl_xor_sync(0xffffffffu, rs1, 1);
        rs1 += __shfl_xor_sync(0xffffffffu, rs1, 2);
        lrow[0] = lrow[0] * cm[0] + rs0;
        lrow[1] = lrow[1] * cm[1] + rs1;

#pragma unroll
        for (int nt = 0; nt < 8; nt++) {
            oacc[nt][0] *= cm[0]; oacc[nt][1] *= cm[0];
            oacc[nt][2] *= cm[1]; oacc[nt][3] *= cm[1];
        }

        uint32_t ph[8][4], pl[8][4];
#pragma unroll
        for (int j = 0; j < 8; j++) {
            pack_split(sacc[2 * j][0],     sacc[2 * j][1],     ph[j][0], pl[j][0]);
            pack_split(sacc[2 * j][2],     sacc[2 * j][3],     ph[j][1], pl[j][1]);
            pack_split(sacc[2 * j + 1][0], sacc[2 * j + 1][1], ph[j][2], pl[j][2]);
            pack_split(sacc[2 * j + 1][2], sacc[2 * j + 1][3], ph[j][3], pl[j][3]);
        }

        const uint32_t vb = R + ATT_V_OFF + buf * 34816;
#pragma unroll
        for (int ks = 0; ks < 8; ks++) {
#pragma unroll
            for (int ntp = 0; ntp < 4; ntp++) {
                uint32_t vh4[4], vl4[4];
                uint32_t off = vb + (((ntp << 4) + ((x4m >> 1) << 3) + x4r) * 136 +
                                     (ks << 4) + ((x4m & 1) << 3)) * 2;
                ldmx4(vh4[0], vh4[1], vh4[2], vh4[3], off);
                ldmx4(vl4[0], vl4[1], vl4[2], vl4[3], off + 17408);
#pragma unroll
                for (int u = 0; u < 2; u++) {
                    int nt = 2 * ntp + u;
                    mma16816(oacc[nt], ph[ks], vh4 + 2 * u);
                    mma16816(oacc[nt], pl[ks], vh4 + 2 * u);
                    mma16816(oacc[nt], ph[ks], vl4 + 2 * u);
                }
            }
        }

        if (c + 1 < 8) { CP_WAIT(0); __syncthreads(); }
    }

    float inv[2] = {1.f / lrow[0], 1.f / lrow[1]};
#pragma unroll
    for (int nt = 0; nt < 8; nt++) {
#pragma unroll
        for (int half = 0; half < 2; half++) {
            int t1 = qt * 128 + wid * 16 + er + half * 8;
            int p = t1 >> 4, qq = t1 & 15;
            int col = nt * 8 + ec;
            float v0 = oacc[nt][half * 2 + 0] * inv[half];
            float v1 = oacc[nt][half * 2 + 1] * inv[half];
            uint32_t hp, lp;
            pack_split(v0, v1, hp, lp);
            int off = (b * 1024 + h * 64 + p) * 1024 + qq * 64 + col;
            *(uint32_t*)(g_Ahi + off) = hp;
            *(uint32_t*)(g_Alo + off) = lp;
        }
    }
}

// ===========================================================================
extern "C" void kernel_launch(void* const* d_in, const int* in_sizes, int n_in,
                              void* d_out, int out_size) {
    const float* x  = (const float*)d_in[0];
    const float* Wq = (const float*)d_in[1];
    const float* bq = (const float*)d_in[2];
    const float* Wk = (const float*)d_in[3];
    const float* bk = (const float*)d_in[4];
    const float* Wv = (const float*)d_in[5];
    const float* bv = (const float*)d_in[6];
    const float* Wo = (const float*)d_in[7];
    const float* bo = (const float*)d_in[8];
    float* out = (float*)d_out;

    __nv_bfloat16 *xhi, *xlo, *whi, *wlo;
    __nv_bfloat16 *qthi, *kthi, *vhi, *vlo, *ahi, *alo;
    cudaGetSymbolAddress((void**)&xhi, g_xhi);
    cudaGetSymbolAddress((void**)&xlo, g_xlo);
    cudaGetSymbolAddress((void**)&whi, g_wt_hi);
    cudaGetSymbolAddress((void**)&wlo, g_wt_lo);
    cudaGetSymbolAddress((void**)&qthi, g_QThi);
    cudaGetSymbolAddress((void**)&kthi, g_KThi);
    cudaGetSymbolAddress((void**)&vhi, g_Vhi);
    cudaGetSymbolAddress((void**)&vlo, g_Vlo);
    cudaGetSymbolAddress((void**)&ahi, g_Ahi);
    cudaGetSymbolAddress((void**)&alo, g_Alo);

    cudaFuncSetAttribute(qkv_mma_kernel, cudaFuncAttributeMaxDynamicSharedMemorySize,
                         GSMEM_QKV);
    cudaFuncSetAttribute(wo_mma_kernel, cudaFuncAttributeMaxDynamicSharedMemorySize,
                         GSMEM_WO);
    cudaFuncSetAttribute(attn_fa2_kernel, cudaFuncAttributeMaxDynamicSharedMemorySize,
                         ATT_SMEM);

    // 1) fused preprocessing: x split + 4 weight transposes      (launch 0)
    prep_kernel<<<dim3(32, 32, 5), dim3(32, 8)>>>(x, Wq, Wk, Wv, Wo,
                                                  xhi, xlo, whi, wlo);

    // 2) fused QKV projections (TN=64 tiles -> 2 CTAs/SM)        (launch 1)
    qkv_mma_kernel<<<dim3(16, 64, 3), 256, GSMEM_QKV>>>(
        xhi, xlo,
        whi + 0 * DIM * DIM, wlo + 0 * DIM * DIM,
        whi + 1 * DIM * DIM, wlo + 1 * DIM * DIM,
        whi + 2 * DIM * DIM, wlo + 2 * DIM * DIM,
        bq, bk, bv, qthi, kthi, vhi, vlo);

    // 3) attention (FA2-style, t1=128 per CTA)                   (launch 2)
    attn_fa2_kernel<<<dim3(8, 128), 256, ATT_SMEM>>>();

    // 4) output projection (3-term, 128x64 tiles, fp32 out)      (launch 3)
    wo_mma_kernel<<<dim3(16, 64), 256, GSMEM_WO>>>(ahi, alo, whi + 3 * DIM * DIM,
                                                   wlo + 3 * DIM * DIM, bo, out);
}

// round 15
// speedup vs baseline: 1.1650x; 1.0142x over previous
#include <cuda_runtime.h>
#include <cuda_bf16.h>
#include <cstdint>

// ===========================================================================
// Problem constants
// ===========================================================================
#define BLN 8192          // B*L
#define DIM 1024          // D
#define QKSCALE 0.03125f  // 1/sqrt(1024)

// ===========================================================================
// Device scratch (allocation-free rule: device globals)
// ===========================================================================
__device__ __nv_bfloat16 g_xhi[BLN * DIM];
__device__ __nv_bfloat16 g_xlo[BLN * DIM];
__device__ __nv_bfloat16 g_wt_hi[4][DIM * DIM];   // W^T [n][k] hi
__device__ __nv_bfloat16 g_wt_lo[4][DIM * DIM];   // W^T [n][k] lo
// Batch-transposed Q,K (hi only — 1-term path): [b][ch=t][l]
__device__ __nv_bfloat16 g_QThi[BLN * DIM];
__device__ __nv_bfloat16 g_KThi[BLN * DIM];
// Natural split V and attention output A: [row=(b,l)][ch]
__device__ __nv_bfloat16 g_Vhi[BLN * DIM];
__device__ __nv_bfloat16 g_Vlo[BLN * DIM];
__device__ __nv_bfloat16 g_Ahi[BLN * DIM];
__device__ __nv_bfloat16 g_Alo[BLN * DIM];

// ===========================================================================
// PTX helpers (sm_80-era: target is plain sm_100, tcgen05 unavailable)
// ===========================================================================
__device__ __forceinline__ uint32_t smem_u32(const void* p) {
    uint32_t a;
    asm("{ .reg .u64 t; cvta.to.shared.u64 t, %1; cvt.u32.u64 %0, t; }" : "=r"(a) : "l"(p));
    return a;
}
#define CP_ASYNC16(saddr, gptr) \
    asm volatile("cp.async.cg.shared.global [%0], [%1], 16;" :: "r"(saddr), "l"(gptr))
#define CP_COMMIT() asm volatile("cp.async.commit_group;" ::: "memory")
#define CP_WAIT(n)  asm volatile("cp.async.wait_group %0;" :: "n"(n) : "memory")

__device__ __forceinline__ void ldmx4(uint32_t& r0, uint32_t& r1, uint32_t& r2, uint32_t& r3,
                                      uint32_t addr) {
    asm volatile("ldmatrix.sync.aligned.m8n8.x4.shared.b16 {%0,%1,%2,%3}, [%4];"
                 : "=r"(r0), "=r"(r1), "=r"(r2), "=r"(r3) : "r"(addr));
}
__device__ __forceinline__ void mma16816(float* c, const uint32_t* a, const uint32_t* b) {
    asm volatile(
        "mma.sync.aligned.m16n8k16.row.col.f32.bf16.bf16.f32 "
        "{%0,%1,%2,%3}, {%4,%5,%6,%7}, {%8,%9}, {%0,%1,%2,%3};"
        : "+f"(c[0]), "+f"(c[1]), "+f"(c[2]), "+f"(c[3])
        : "r"(a[0]), "r"(a[1]), "r"(a[2]), "r"(a[3]), "r"(b[0]), "r"(b[1]));
}
__device__ __forceinline__ void pack_split(float v0, float v1, uint32_t& hi, uint32_t& lo) {
    __nv_bfloat16 h0 = __float2bfloat16(v0);
    __nv_bfloat16 h1 = __float2bfloat16(v1);
    __nv_bfloat162 hp; hp.x = h0; hp.y = h1;
    hi = *(uint32_t*)&hp;
    __nv_bfloat162 lp;
    lp.x = __float2bfloat16(v0 - __bfloat162float(h0));
    lp.y = __float2bfloat16(v1 - __bfloat162float(h1));
    lo = *(uint32_t*)&lp;
}

struct alignas(8) bf4 { __nv_bfloat16 a, b, c, d; };

// ===========================================================================
// Fused preprocessing (one launch): z=0..3 transpose+split W[z]; z=4 split x
// ===========================================================================
__global__ void prep_kernel(const float* __restrict__ x,
                            const float* __restrict__ Wq,
                            const float* __restrict__ Wk,
                            const float* __restrict__ Wv,
                            const float* __restrict__ Wo,
                            __nv_bfloat16* __restrict__ xhi,
                            __nv_bfloat16* __restrict__ xlo,
                            __nv_bfloat16* __restrict__ whi,
                            __nv_bfloat16* __restrict__ wlo) {
    const int z = blockIdx.z;
    const int tx = threadIdx.x, ty = threadIdx.y;
    if (z < 4) {
        const float* W = (z == 0) ? Wq : (z == 1) ? Wk : (z == 2) ? Wv : Wo;
        __nv_bfloat16* Thi = whi + z * DIM * DIM;
        __nv_bfloat16* Tlo = wlo + z * DIM * DIM;
        __shared__ float t[32][33];
        const int n0 = blockIdx.x << 5;
        const int k0 = blockIdx.y << 5;
#pragma unroll
        for (int j = 0; j < 4; j++)
            t[ty + (j << 3)][tx] = W[(k0 + ty + (j << 3)) * DIM + n0 + tx];
        __syncthreads();
#pragma unroll
        for (int j = 0; j < 4; j++) {
            float v = t[tx][ty + (j << 3)];
            __nv_bfloat16 h = __float2bfloat16(v);
            int o = (n0 + ty + (j << 3)) * DIM + k0 + tx;
            Thi[o] = h;
            Tlo[o] = __float2bfloat16(v - __bfloat162float(h));
        }
    } else {
        const int flat = (blockIdx.y * 32 + blockIdx.x) * 256 + ty * 32 + tx;
        const float4* in4 = (const float4*)x;
#pragma unroll
        for (int j = 0; j < 8; j++) {
            int i = flat + j * 262144;
            float4 v = in4[i];
            __nv_bfloat16 h0 = __float2bfloat16(v.x);
            __nv_bfloat16 h1 = __float2bfloat16(v.y);
            __nv_bfloat16 h2 = __float2bfloat16(v.z);
            __nv_bfloat16 h3 = __float2bfloat16(v.w);
            bf4 H = {h0, h1, h2, h3};
            bf4 L = {__float2bfloat16(v.x - __bfloat162float(h0)),
                     __float2bfloat16(v.y - __bfloat162float(h1)),
                     __float2bfloat16(v.z - __bfloat162float(h2)),
                     __float2bfloat16(v.w - __bfloat162float(h3))};
            ((bf4*)xhi)[i] = H;
            ((bf4*)xlo)[i] = L;
        }
    }
}

// ===========================================================================
// GEMM body: mma.sync, TERMS split terms, tile 128 x TN, 3-stage pipeline,
// 256 threads / 8 warps (2x4 warp grid). TERM-OUTER mma order: consecutive
// MMAs hit different accumulators (ILP); per-accumulator term order unchanged
// (bit-identical results).
// ===========================================================================
#define GSTRIDE 40
#define ATILE_B (128 * GSTRIDE * 2)          // 10240

template <int TERMS, int TN>
__device__ __forceinline__
void gemm_body(char* smem,
               const __nv_bfloat16* __restrict__ Ahi,
               const __nv_bfloat16* __restrict__ Alo,
               const __nv_bfloat16* __restrict__ Bhi,
               const __nv_bfloat16* __restrict__ Blo,
               const float* __restrict__ bias,
               float* __restrict__ Cf,
               __nv_bfloat16* __restrict__ Chi,
               __nv_bfloat16* __restrict__ Clo,
               float scale, int mode, int m0, int n0) {
    constexpr int BTILE_B = TN * GSTRIDE * 2;
    constexpr int SSTAGE = 2 * ATILE_B + 2 * BTILE_B;
    constexpr int NT = TN / 32;

    const uint32_t sbase = smem_u32(smem);

    const int tid = threadIdx.x;
    const int wid = tid >> 5;
    const int lane = tid & 31;
    const int wm = (wid & 1) << 6;
    const int wn = (wid >> 1) * (TN / 4);

    const __nv_bfloat16* srcs[4] = {Ahi + m0 * 1024, Alo + m0 * 1024,
                                    Bhi + n0 * 1024, Blo + n0 * 1024};

    float acc[4][NT][4];
#pragma unroll
    for (int a = 0; a < 4; a++)
#pragma unroll
        for (int b = 0; b < NT; b++)
#pragma unroll
            for (int c = 0; c < 4; c++) acc[a][b][c] = 0.f;

    const int a_r = lane & 15, a_k = lane >> 4;
    const int x4m = lane >> 3;
    const int x4r = lane & 7;

    auto load_stage = [&](int kt, int buf) {
        const int kb = kt << 5;
        uint32_t sb = sbase + buf * SSTAGE;
#pragma unroll
        for (int j = 0; j < 2; j++) {
            int idx = (j << 8) + tid;
            int row = idx >> 2, ch = idx & 3;
            CP_ASYNC16(sb + (row * GSTRIDE + (ch << 3)) * 2,
                       srcs[0] + row * 1024 + kb + (ch << 3));
        }
        if (TERMS == 3) {
#pragma unroll
            for (int j = 0; j < 2; j++) {
                int idx = (j << 8) + tid;
                int row = idx >> 2, ch = idx & 3;
                CP_ASYNC16(sb + ATILE_B + (row * GSTRIDE + (ch << 3)) * 2,
                           srcs[1] + row * 1024 + kb + (ch << 3));
            }
        }
#pragma unroll
        for (int j = 0; j < TN / 64; j++) {
            int idx = (j << 8) + tid;
            int row = idx >> 2, ch = idx & 3;
            CP_ASYNC16(sb + 2 * ATILE_B + (row * GSTRIDE + (ch << 3)) * 2,
                       srcs[2] + row * 1024 + kb + (ch << 3));
        }
        if (TERMS == 3) {
#pragma unroll
            for (int j = 0; j < TN / 64; j++) {
                int idx = (j << 8) + tid;
                int row = idx >> 2, ch = idx & 3;
                CP_ASYNC16(sb + 2 * ATILE_B + BTILE_B + (row * GSTRIDE + (ch << 3)) * 2,
                           srcs[3] + row * 1024 + kb + (ch << 3));
            }
        }
    };

    load_stage(0, 0); CP_COMMIT();
    load_stage(1, 1); CP_COMMIT();

    for (int kt = 0; kt < 32; kt++) {
        if (kt == 31) { CP_WAIT(0); } else { CP_WAIT(1); }
        __syncthreads();
        if (kt + 2 < 32) { load_stage(kt + 2, (kt + 2) % 3); CP_COMMIT(); }

        const uint32_t sb = sbase + (kt % 3) * SSTAGE;
        const uint32_t sAhi = sb;
        const uint32_t sAlo = sb + ATILE_B;
        const uint32_t sBhi = sb + 2 * ATILE_B;
        const uint32_t sBlo = sb + 2 * ATILE_B + BTILE_B;

#pragma unroll
        for (int ks = 0; ks < 2; ks++) {
            uint32_t ah[4][4], al[4][4], bh[NT][2], bl[NT][2];
#pragma unroll
            for (int mt = 0; mt < 4; mt++) {
                uint32_t off = ((wm + (mt << 4) + a_r) * GSTRIDE + (ks << 4) + (a_k << 3)) * 2;
                ldmx4(ah[mt][0], ah[mt][1], ah[mt][2], ah[mt][3], sAhi + off);
                if (TERMS == 3)
                    ldmx4(al[mt][0], al[mt][1], al[mt][2], al[mt][3], sAlo + off);
            }
#pragma unroll
            for (int ntp = 0; ntp < NT / 2; ntp++) {
                uint32_t off = ((wn + (ntp << 4) + ((x4m >> 1) << 3) + x4r) * GSTRIDE +
                                (ks << 4) + ((x4m & 1) << 3)) * 2;
                ldmx4(bh[2 * ntp][0], bh[2 * ntp][1],
                      bh[2 * ntp + 1][0], bh[2 * ntp + 1][1], sBhi + off);
                if (TERMS == 3)
                    ldmx4(bl[2 * ntp][0], bl[2 * ntp][1],
                          bl[2 * ntp + 1][0], bl[2 * ntp + 1][1], sBlo + off);
            }
            // term-outer: every consecutive MMA targets a different accumulator
#pragma unroll
            for (int mt = 0; mt < 4; mt++)
#pragma unroll
                for (int nt = 0; nt < NT; nt++)
                    mma16816(acc[mt][nt], ah[mt], bh[nt]);
            if (TERMS == 3) {
#pragma unroll
                for (int mt = 0; mt < 4; mt++)
#pragma unroll
                    for (int nt = 0; nt < NT; nt++)
                        mma16816(acc[mt][nt], al[mt], bh[nt]);
#pragma unroll
                for (int mt = 0; mt < 4; mt++)
#pragma unroll
                    for (int nt = 0; nt < NT; nt++)
                        mma16816(acc[mt][nt], ah[mt], bl[nt]);
            }
        }
    }
    __syncthreads();

    const int er = lane >> 2;
    const int ec = (lane & 3) << 1;

    if (mode == 0) {
#pragma unroll
        for (int mt = 0; mt < 4; mt++) {
#pragma unroll
            for (int nt = 0; nt < NT; nt++) {
                int row = m0 + wm + (mt << 4) + er;
                int col = n0 + wn + (nt << 3) + ec;
                float2 b2 = *(const float2*)(bias + col);
                float2 o0, o1;
                o0.x = (acc[mt][nt][0] + b2.x) * scale;
                o0.y = (acc[mt][nt][1] + b2.y) * scale;
                o1.x = (acc[mt][nt][2] + b2.x) * scale;
                o1.y = (acc[mt][nt][3] + b2.y) * scale;
                *(float2*)(Cf + row * 1024 + col) = o0;
                *(float2*)(Cf + (row + 8) * 1024 + col) = o1;
            }
        }
    } else if (mode == 1) {
#pragma unroll
        for (int mt = 0; mt < 4; mt++) {
#pragma unroll
            for (int nt = 0; nt < NT; nt++) {
                int row = m0 + wm + (mt << 4) + er;
                int col = n0 + wn + (nt << 3) + ec;
                float2 b2 = *(const float2*)(bias + col);
#pragma unroll
                for (int half = 0; half < 2; half++) {
                    int r = row + half * 8;
                    float v0 = (acc[mt][nt][half * 2 + 0] + b2.x) * scale;
                    float v1 = (acc[mt][nt][half * 2 + 1] + b2.y) * scale;
                    uint32_t hp, lp;
                    pack_split(v0, v1, hp, lp);
                    *(uint32_t*)(Chi + r * 1024 + col) = hp;
                    *(uint32_t*)(Clo + r * 1024 + col) = lp;
                }
            }
        }
    } else {
        __nv_bfloat16* sthi = (__nv_bfloat16*)smem;
        __nv_bfloat16* stlo = (__nv_bfloat16*)(smem + 34816);
#pragma unroll
        for (int mt = 0; mt < 4; mt++) {
#pragma unroll
            for (int nt = 0; nt < NT; nt++) {
                int mrow = wm + (mt << 4) + er;
                int ncol = wn + (nt << 3) + ec;
                float2 b2 = *(const float2*)(bias + n0 + ncol);
#pragma unroll
                for (int half = 0; half < 2; half++) {
                    int r = mrow + half * 8;
                    float v0 = (acc[mt][nt][half * 2 + 0] + b2.x) * scale;
                    float v1 = (acc[mt][nt][half * 2 + 1] + b2.y) * scale;
                    __nv_bfloat16 h0 = __float2bfloat16(v0);
                    __nv_bfloat16 h1 = __float2bfloat16(v1);
                    sthi[ncol * 136 + r] = h0;
                    sthi[(ncol + 1) * 136 + r] = h1;
                    if (TERMS == 3) {
                        stlo[ncol * 136 + r] = __float2bfloat16(v0 - __bfloat162float(h0));
                        stlo[(ncol + 1) * 136 + r] = __float2bfloat16(v1 - __bfloat162float(h1));
                    }
                }
            }
        }
        __syncthreads();
        const int bidx = m0 >> 10;
        const int l0 = m0 & 1023;
        constexpr int CHT = TN * 16;
        constexpr int NCP = (CHT * ((TERMS == 3) ? 2 : 1)) / 256;
#pragma unroll
        for (int i = 0; i < NCP; i++) {
            int q = tid + (i << 8);
            int t = q / CHT;
            int idx = q % CHT;
            int nrow = idx >> 4;
            int ch = idx & 15;
            uint4 v = *(const uint4*)(smem + t * 34816 + (nrow * 136 + ch * 8) * 2);
            __nv_bfloat16* dst = (t ? Clo : Chi) +
                bidx * 1048576 + (n0 + nrow) * 1024 + l0 + ch * 8;
            *(uint4*)dst = v;
        }
    }
}

#define GSMEM_QKV (3 * (2 * ATILE_B + 2 * (64 * GSTRIDE * 2)))  // 92160
#define GSMEM_WO  (3 * (2 * ATILE_B + 2 * (64 * GSTRIDE * 2)))  // 92160

__global__ __launch_bounds__(256, 1)
void qkv_mma_kernel(const __nv_bfloat16* __restrict__ xhi,
                    const __nv_bfloat16* __restrict__ xlo,
                    const __nv_bfloat16* __restrict__ wq_hi,
                    const __nv_bfloat16* __restrict__ wq_lo,
                    const __nv_bfloat16* __restrict__ wk_hi,
                    const __nv_bfloat16* __restrict__ wk_lo,
                    const __nv_bfloat16* __restrict__ wv_hi,
                    const __nv_bfloat16* __restrict__ wv_lo,
                    const float* __restrict__ bq,
                    const float* __restrict__ bk,
                    const float* __restrict__ bv,
                    __nv_bfloat16* __restrict__ qthi,
                    __nv_bfloat16* __restrict__ kthi,
                    __nv_bfloat16* __restrict__ vhi,
                    __nv_bfloat16* __restrict__ vlo) {
    extern __shared__ __align__(16) char smem[];
    const int m0 = blockIdx.y << 7;
    const int n0 = blockIdx.x << 6;
    const int z = blockIdx.z;
    if (z == 0) {
        gemm_body<3, 64>(smem, xhi, xlo, wv_hi, wv_lo, bv,
                         nullptr, vhi, vlo, 1.0f, 1, m0, n0);
    } else if (z == 1) {
        gemm_body<1, 64>(smem, xhi, xlo, wq_hi, wq_lo, bq,
                         nullptr, qthi, nullptr, QKSCALE, 2, m0, n0);
    } else {
        gemm_body<1, 64>(smem, xhi, xlo, wk_hi, wk_lo, bk,
                         nullptr, kthi, nullptr, QKSCALE, 2, m0, n0);
    }
}

__global__ __launch_bounds__(256, 1)
void wo_mma_kernel(const __nv_bfloat16* __restrict__ Ahi,
                   const __nv_bfloat16* __restrict__ Alo,
                   const __nv_bfloat16* __restrict__ Bhi,
                   const __nv_bfloat16* __restrict__ Blo,
                   const float* __restrict__ bias,
                   float* __restrict__ Cf) {
    extern __shared__ __align__(16) char smem[];
    gemm_body<3, 64>(smem, Ahi, Alo, Bhi, Blo, bias,
                     Cf, nullptr, nullptr, 1.0f, 0,
                     blockIdx.y << 7, blockIdx.x << 6);
}

// ===========================================================================
// FlashAttention-2-style attention, restructured for 2 CTAs/SM:
//   smem: Q hi [128][72] + K hi [128][72] (SINGLE buf) + V hi/lo x2 bufs
//         = 18432 + 18432 + 69632 = 106496 B  (2 x 106496 fits 228KB SM)
//   regs: P packed per-ks (8 live, not 64); Q frags reloaded per chunk.
//   Pipeline: V[c+1] prefetch spans whole chunk; K[c+1] load issued after
//   QK[c] + sync, overlaps softmax+PV.
// ===========================================================================
#define ATT_Q_OFF 0
#define ATT_K_OFF 18432
#define ATT_V_OFF 36864
#define ATT_SMEM  106496

__global__ __launch_bounds__(256, 2)
void attn_fa2_kernel() {
    extern __shared__ __align__(16) char sm[];
    const uint32_t R = smem_u32(sm);

    const int g = blockIdx.y, qt = blockIdx.x;
    const int b = g >> 4, h = g & 15;
    const int tid = threadIdx.x, wid = tid >> 5, lane = tid & 31;

    const int a_r = lane & 15, a_k = lane >> 4;
    const int x4m = lane >> 3;
    const int x4r = lane & 7;
    const int ec = (lane & 3) << 1;
    const int er = lane >> 2;

    const int qkrow = b * 1048576 + h * 64;

#pragma unroll
    for (int i = 0; i < 4; i++) {
        int q = tid + (i << 8);
        int r = q >> 3, ch = q & 7;
        const __nv_bfloat16* src = g_QThi + qkrow + (qt * 128 + r) * 1024 + ch * 8;
        CP_ASYNC16(R + ATT_Q_OFF + (r * 72 + ch * 8) * 2, src);
    }
    auto load_K = [&](int c) {
#pragma unroll
        for (int i = 0; i < 4; i++) {
            int q = tid + (i << 8);
            int r = q >> 3, ch = q & 7;
            const __nv_bfloat16* src = g_KThi + qkrow + (c * 128 + r) * 1024 + ch * 8;
            CP_ASYNC16(R + ATT_K_OFF + (r * 72 + ch * 8) * 2, src);
        }
    };
    auto load_V = [&](int c, int buf) {
#pragma unroll
        for (int i = 0; i < 8; i++) {
            int q = tid + (i << 8);
            int t = q >> 10, idx = q & 1023;
            int r = idx >> 4, ch = idx & 15;
            const __nv_bfloat16* src =
                (t ? g_Vlo : g_Vhi) + (b * 1024 + h * 64 + r) * 1024 + c * 128 + ch * 8;
            CP_ASYNC16(R + ATT_V_OFF + buf * 34816 + t * 17408 + (r * 136 + ch * 8) * 2, src);
        }
    };
    load_K(0);
    load_V(0, 0);
    CP_COMMIT();
    CP_WAIT(0);
    __syncthreads();

    float oacc[8][4];
#pragma unroll
    for (int i = 0; i < 8; i++)
#pragma unroll
        for (int j = 0; j < 4; j++) oacc[i][j] = 0.f;
    float mrow[2] = {-1e30f, -1e30f};
    float lrow[2] = {0.f, 0.f};

    for (int c = 0; c < 8; c++) {
        const int vbuf = c & 1;
        if (c + 1 < 8) {
            load_V(c + 1, vbuf ^ 1);   // spans whole chunk
            CP_COMMIT();
        }

        // ---- QK (Q frags reloaded per chunk; K single buffer) ----
        float sacc[16][4];
#pragma unroll
        for (int i = 0; i < 16; i++)
#pragma unroll
            for (int j = 0; j < 4; j++) sacc[i][j] = 0.f;

#pragma unroll
        for (int ks = 0; ks < 4; ks++) {
            uint32_t qh[4];
            uint32_t qoff = R + ATT_Q_OFF + ((wid * 16 + a_r) * 72 + ks * 16 + a_k * 8) * 2;
            ldmx4(qh[0], qh[1], qh[2], qh[3], qoff);
#pragma unroll
            for (int ntp = 0; ntp < 8; ntp++) {
                uint32_t bb[4];
                uint32_t off = R + ATT_K_OFF + (((ntp << 4) + ((x4m >> 1) << 3) + x4r) * 72 +
                                                (ks << 4) + ((x4m & 1) << 3)) * 2;
                ldmx4(bb[0], bb[1], bb[2], bb[3], off);
                mma16816(sacc[2 * ntp],     qh, bb);
                mma16816(sacc[2 * ntp + 1], qh, bb + 2);
            }
        }
        __syncthreads();                 // all warps done reading K buffer
        if (c + 1 < 8) {
            load_K(c + 1);               // overlaps softmax + PV
            CP_COMMIT();
        }

        // ---- online softmax ----
        float cm[2];
#pragma unroll
        for (int rr = 0; rr < 2; rr++) {
            float mx = -1e30f;
#pragma unroll
            for (int nt = 0; nt < 16; nt++)
                mx = fmaxf(mx, fmaxf(sacc[nt][rr * 2], sacc[nt][rr * 2 + 1]));
            mx = fmaxf(mx, __shfl_xor_sync(0xffffffffu, mx, 1));
            mx = fmaxf(mx, __shfl_xor_sync(0xffffffffu, mx, 2));
            float mnew = fmaxf(mrow[rr], mx);
            cm[rr] = __expf(mrow[rr] - mnew);
            mrow[rr] = mnew;
        }
        float rs0 = 0.f, rs1 = 0.f;
#pragma unroll
        for (int nt = 0; nt < 16; nt++) {
            sacc[nt][0] = __expf(sacc[nt][0] - mrow[0]);
            sacc[nt][1] = __expf(sacc[nt][1] - mrow[0]);
            sacc[nt][2] = __expf(sacc[nt][2] - mrow[1]);
            sacc[nt][3] = __expf(sacc[nt][3] - mrow[1]);
            rs0 += sacc[nt][0] + sacc[nt][1];
            rs1 += sacc[nt][2] + sacc[nt][3];
        }
        rs0 += __shfl_xor_sync(0xffffffffu, rs0, 1);
        rs0 += __shfl_xor_sync(0xffffffffu, rs0, 2);
        rs1 += __shfl_xor_sync(0xffffffffu, rs1, 1);
        rs1 += __shfl_xor_sync(0xffffffffu, rs1, 2);
        lrow[0] = lrow[0] * cm[0] + rs0;
        lrow[1] = lrow[1] * cm[1] + rs1;

#pragma unroll
        for (int nt = 0; nt < 8; nt++) {
            oacc[nt][0] *= cm[0]; oacc[nt][1] *= cm[0];
            oacc[nt][2] *= cm[1]; oacc[nt][3] *= cm[1];
        }

        // ---- PV: pack P per-ks (8 live regs), 3-term split ----
        const uint32_t vb = R + ATT_V_OFF + vbuf * 34816;
#pragma unroll
        for (int ks = 0; ks < 8; ks++) {
            uint32_t ph[4], pl[4];
            pack_split(sacc[2 * ks][0],     sacc[2 * ks][1],     ph[0], pl[0]);
            pack_split(sacc[2 * ks][2],     sacc[2 * ks][3],     ph[1], pl[1]);
            pack_split(sacc[2 * ks + 1][0], sacc[2 * ks + 1][1], ph[2], pl[2]);
            pack_split(sacc[2 * ks + 1][2], sacc[2 * ks + 1][3], ph[3], pl[3]);
#pragma unroll
            for (int ntp = 0; ntp < 4; ntp++) {
                uint32_t vh4[4], vl4[4];
                uint32_t off = vb + (((ntp << 4) + ((x4m >> 1) << 3) + x4r) * 136 +
                                     (ks << 4) + ((x4m & 1) << 3)) * 2;
                ldmx4(vh4[0], vh4[1], vh4[2], vh4[3], off);
                ldmx4(vl4[0], vl4[1], vl4[2], vl4[3], off + 17408);
#pragma unroll
                for (int u = 0; u < 2; u++) {
                    int nt = 2 * ntp + u;
                    mma16816(oacc[nt], ph, vh4 + 2 * u);
                    mma16816(oacc[nt], pl, vh4 + 2 * u);
                    mma16816(oacc[nt], ph, vl4 + 2 * u);
                }
            }
        }

        if (c + 1 < 8) { CP_WAIT(0); __syncthreads(); }   // K[c+1], V[c+1] landed
    }

    float inv[2] = {1.f / lrow[0], 1.f / lrow[1]};
#pragma unroll
    for (int nt = 0; nt < 8; nt++) {
#pragma unroll
        for (int half = 0; half < 2; half++) {
            int t1 = qt * 128 + wid * 16 + er + half * 8;
            int p = t1 >> 4, qq = t1 & 15;
            int col = nt * 8 + ec;
            float v0 = oacc[nt][half * 2 + 0] * inv[half];
            float v1 = oacc[nt][half * 2 + 1] * inv[half];
            uint32_t hp, lp;
            pack_split(v0, v1, hp, lp);
            int off = (b * 1024 + h * 64 + p) * 1024 + qq * 64 + col;
            *(uint32_t*)(g_Ahi + off) = hp;
            *(uint32_t*)(g_Alo + off) = lp;
        }
    }
}

// ===========================================================================
extern "C" void kernel_launch(void* const* d_in, const int* in_sizes, int n_in,
                              void* d_out, int out_size) {
    const float* x  = (const float*)d_in[0];
    const float* Wq = (const float*)d_in[1];
    const float* bq = (const float*)d_in[2];
    const float* Wk = (const float*)d_in[3];
    const float* bk = (const float*)d_in[4];
    const float* Wv = (const float*)d_in[5];
    const float* bv = (const float*)d_in[6];
    const float* Wo = (const float*)d_in[7];
    const float* bo = (const float*)d_in[8];
    float* out = (float*)d_out;

    __nv_bfloat16 *xhi, *xlo, *whi, *wlo;
    __nv_bfloat16 *qthi, *kthi, *vhi, *vlo, *ahi, *alo;
    cudaGetSymbolAddress((void**)&xhi, g_xhi);
    cudaGetSymbolAddress((void**)&xlo, g_xlo);
    cudaGetSymbolAddress((void**)&whi, g_wt_hi);
    cudaGetSymbolAddress((void**)&wlo, g_wt_lo);
    cudaGetSymbolAddress((void**)&qthi, g_QThi);
    cudaGetSymbolAddress((void**)&kthi, g_KThi);
    cudaGetSymbolAddress((void**)&vhi, g_Vhi);
    cudaGetSymbolAddress((void**)&vlo, g_Vlo);
    cudaGetSymbolAddress((void**)&ahi, g_Ahi);
    cudaGetSymbolAddress((void**)&alo, g_Alo);

    cudaFuncSetAttribute(qkv_mma_kernel, cudaFuncAttributeMaxDynamicSharedMemorySize,
                         GSMEM_QKV);
    cudaFuncSetAttribute(wo_mma_kernel, cudaFuncAttributeMaxDynamicSharedMemorySize,
                         GSMEM_WO);
    cudaFuncSetAttribute(attn_fa2_kernel, cudaFuncAttributeMaxDynamicSharedMemorySize,
                         ATT_SMEM);

    // 1) fused preprocessing                                      (launch 0)
    prep_kernel<<<dim3(32, 32, 5), dim3(32, 8)>>>(x, Wq, Wk, Wv, Wo,
                                                  xhi, xlo, whi, wlo);

    // 2) fused QKV projections (TN=64 -> 2 CTAs/SM)               (launch 1)
    qkv_mma_kernel<<<dim3(16, 64, 3), 256, GSMEM_QKV>>>(
        xhi, xlo,
        whi + 0 * DIM * DIM, wlo + 0 * DIM * DIM,
        whi + 1 * DIM * DIM, wlo + 1 * DIM * DIM,
        whi + 2 * DIM * DIM, wlo + 2 * DIM * DIM,
        bq, bk, bv, qthi, kthi, vhi, vlo);

    // 3) attention (FA2, 2 CTAs/SM)                               (launch 2)
    attn_fa2_kernel<<<dim3(8, 128), 256, ATT_SMEM>>>();

    // 4) output projection                                        (launch 3)
    wo_mma_kernel<<<dim3(16, 64), 256, GSMEM_WO>>>(ahi, alo, whi + 3 * DIM * DIM,
                                                   wlo + 3 * DIM * DIM, bo, out);
}

// round 16
// speedup vs baseline: 1.3065x; 1.1214x over previous
#include <cuda_runtime.h>
#include <cuda_fp16.h>
#include <cstdint>

// ===========================================================================
// Problem constants
// ===========================================================================
#define BLN 8192          // B*L
#define DIM 1024          // D
#define QKSCALE 0.03125f  // 1/sqrt(1024)

// ===========================================================================
// Device scratch (fp16 split: hi everywhere, lo only where a 2-term needs it)
// ===========================================================================
__device__ __half g_xhi[BLN * DIM];
__device__ __half g_xlo[BLN * DIM];
__device__ __half g_wt_hi[4][DIM * DIM];   // W^T [n][k] hi (lo planes dropped)
// Batch-transposed Q,K (hi only): [b][ch=t][l]
__device__ __half g_QThi[BLN * DIM];
__device__ __half g_KThi[BLN * DIM];
// Natural V (hi only) and attention output A (hi+lo): [row=(b,l)][ch]
__device__ __half g_Vhi[BLN * DIM];
__device__ __half g_Ahi[BLN * DIM];
__device__ __half g_Alo[BLN * DIM];

// ===========================================================================
// PTX helpers (sm_80-era: target is plain sm_100, tcgen05 unavailable)
// ===========================================================================
__device__ __forceinline__ uint32_t smem_u32(const void* p) {
    uint32_t a;
    asm("{ .reg .u64 t; cvta.to.shared.u64 t, %1; cvt.u32.u64 %0, t; }" : "=r"(a) : "l"(p));
    return a;
}
#define CP_ASYNC16(saddr, gptr) \
    asm volatile("cp.async.cg.shared.global [%0], [%1], 16;" :: "r"(saddr), "l"(gptr))
#define CP_COMMIT() asm volatile("cp.async.commit_group;" ::: "memory")
#define CP_WAIT(n)  asm volatile("cp.async.wait_group %0;" :: "n"(n) : "memory")

__device__ __forceinline__ void ldmx4(uint32_t& r0, uint32_t& r1, uint32_t& r2, uint32_t& r3,
                                      uint32_t addr) {
    asm volatile("ldmatrix.sync.aligned.m8n8.x4.shared.b16 {%0,%1,%2,%3}, [%4];"
                 : "=r"(r0), "=r"(r1), "=r"(r2), "=r"(r3) : "r"(addr));
}
__device__ __forceinline__ void mma16816(float* c, const uint32_t* a, const uint32_t* b) {
    asm volatile(
        "mma.sync.aligned.m16n8k16.row.col.f32.f16.f16.f32 "
        "{%0,%1,%2,%3}, {%4,%5,%6,%7}, {%8,%9}, {%0,%1,%2,%3};"
        : "+f"(c[0]), "+f"(c[1]), "+f"(c[2]), "+f"(c[3])
        : "r"(a[0]), "r"(a[1]), "r"(a[2]), "r"(a[3]), "r"(b[0]), "r"(b[1]));
}
__device__ __forceinline__ void pack_split_h(float v0, float v1, uint32_t& hi, uint32_t& lo) {
    __half h0 = __float2half_rn(v0);
    __half h1 = __float2half_rn(v1);
    __half2 hp; hp.x = h0; hp.y = h1;
    hi = *(uint32_t*)&hp;
    __half2 lp;
    lp.x = __float2half_rn(v0 - __half2float(h0));
    lp.y = __float2half_rn(v1 - __half2float(h1));
    lo = *(uint32_t*)&lp;
}
__device__ __forceinline__ uint32_t pack_h2(float v0, float v1) {
    __half2 hp; hp.x = __float2half_rn(v0); hp.y = __float2half_rn(v1);
    return *(uint32_t*)&hp;
}

struct alignas(8) h4 { __half a, b, c, d; };

// ===========================================================================
// Fused preprocessing (one launch): z=0..3 transpose W[z] -> hi; z=4 split x
// ===========================================================================
__global__ void prep_kernel(const float* __restrict__ x,
                            const float* __restrict__ Wq,
                            const float* __restrict__ Wk,
                            const float* __restrict__ Wv,
                            const float* __restrict__ Wo,
                            __half* __restrict__ xhi,
                            __half* __restrict__ xlo,
                            __half* __restrict__ whi) {
    const int z = blockIdx.z;
    const int tx = threadIdx.x, ty = threadIdx.y;
    if (z < 4) {
        const float* W = (z == 0) ? Wq : (z == 1) ? Wk : (z == 2) ? Wv : Wo;
        __half* Thi = whi + z * DIM * DIM;
        __shared__ float t[32][33];
        const int n0 = blockIdx.x << 5;
        const int k0 = blockIdx.y << 5;
#pragma unroll
        for (int j = 0; j < 4; j++)
            t[ty + (j << 3)][tx] = W[(k0 + ty + (j << 3)) * DIM + n0 + tx];
        __syncthreads();
#pragma unroll
        for (int j = 0; j < 4; j++) {
            float v = t[tx][ty + (j << 3)];
            Thi[(n0 + ty + (j << 3)) * DIM + k0 + tx] = __float2half_rn(v);
        }
    } else {
        const int flat = (blockIdx.y * 32 + blockIdx.x) * 256 + ty * 32 + tx;
        const float4* in4 = (const float4*)x;
#pragma unroll
        for (int j = 0; j < 8; j++) {
            int i = flat + j * 262144;
            float4 v = in4[i];
            __half h0 = __float2half_rn(v.x);
            __half h1 = __float2half_rn(v.y);
            __half h2 = __float2half_rn(v.z);
            __half h3 = __float2half_rn(v.w);
            h4 H = {h0, h1, h2, h3};
            h4 L = {__float2half_rn(v.x - __half2float(h0)),
                    __float2half_rn(v.y - __half2float(h1)),
                    __float2half_rn(v.z - __half2float(h2)),
                    __float2half_rn(v.w - __half2float(h3))};
            ((h4*)xhi)[i] = H;
            ((h4*)xlo)[i] = L;
        }
    }
}

// ===========================================================================
// GEMM body: fp16 mma.sync. TERMS=2: Ahi*Bhi + Alo*Bhi (term-outer).
// TERMS=1: Ahi*Bhi. Tile 128 x TN, 3-stage pipeline, 256 thr / 8 warps.
// modes: 0 = fp32 natural; 1 = fp16-hi natural (V); 2 = fp16-hi transposed
// ===========================================================================
#define GSTRIDE 40
#define ATILE_B (128 * GSTRIDE * 2)          // 10240

template <int TERMS, int TN>
__device__ __forceinline__
void gemm_body(char* smem,
               const __half* __restrict__ Ahi,
               const __half* __restrict__ Alo,
               const __half* __restrict__ Bhi,
               const float* __restrict__ bias,
               float* __restrict__ Cf,
               __half* __restrict__ Chi,
               float scale, int mode, int m0, int n0) {
    constexpr int BTILE_B = TN * GSTRIDE * 2;                  // 5120 @ TN=64
    constexpr int NATILE = (TERMS == 2) ? 2 : 1;
    constexpr int SSTAGE = NATILE * ATILE_B + BTILE_B;
    constexpr int NT = TN / 32;

    const uint32_t sbase = smem_u32(smem);

    const int tid = threadIdx.x;
    const int wid = tid >> 5;
    const int lane = tid & 31;
    const int wm = (wid & 1) << 6;
    const int wn = (wid >> 1) * (TN / 4);

    const __half* srcA0 = Ahi + m0 * 1024;
    const __half* srcA1 = (TERMS == 2) ? (Alo + m0 * 1024) : nullptr;
    const __half* srcB  = Bhi + n0 * 1024;

    float acc[4][NT][4];
#pragma unroll
    for (int a = 0; a < 4; a++)
#pragma unroll
        for (int b = 0; b < NT; b++)
#pragma unroll
            for (int c = 0; c < 4; c++) acc[a][b][c] = 0.f;

    const int a_r = lane & 15, a_k = lane >> 4;
    const int x4m = lane >> 3;
    const int x4r = lane & 7;

    auto load_stage = [&](int kt, int buf) {
        const int kb = kt << 5;
        uint32_t sb = sbase + buf * SSTAGE;
#pragma unroll
        for (int j = 0; j < 2; j++) {
            int idx = (j << 8) + tid;
            int row = idx >> 2, ch = idx & 3;
            CP_ASYNC16(sb + (row * GSTRIDE + (ch << 3)) * 2,
                       srcA0 + row * 1024 + kb + (ch << 3));
        }
        if (TERMS == 2) {
#pragma unroll
            for (int j = 0; j < 2; j++) {
                int idx = (j << 8) + tid;
                int row = idx >> 2, ch = idx & 3;
                CP_ASYNC16(sb + ATILE_B + (row * GSTRIDE + (ch << 3)) * 2,
                           srcA1 + row * 1024 + kb + (ch << 3));
            }
        }
#pragma unroll
        for (int j = 0; j < TN / 64; j++) {
            int idx = (j << 8) + tid;
            int row = idx >> 2, ch = idx & 3;
            CP_ASYNC16(sb + NATILE * ATILE_B + (row * GSTRIDE + (ch << 3)) * 2,
                       srcB + row * 1024 + kb + (ch << 3));
        }
    };

    load_stage(0, 0); CP_COMMIT();
    load_stage(1, 1); CP_COMMIT();

    for (int kt = 0; kt < 32; kt++) {
        if (kt == 31) { CP_WAIT(0); } else { CP_WAIT(1); }
        __syncthreads();
        if (kt + 2 < 32) { load_stage(kt + 2, (kt + 2) % 3); CP_COMMIT(); }

        const uint32_t sb = sbase + (kt % 3) * SSTAGE;
        const uint32_t sAhi = sb;
        const uint32_t sAlo = sb + ATILE_B;
        const uint32_t sBhi = sb + NATILE * ATILE_B;

#pragma unroll
        for (int ks = 0; ks < 2; ks++) {
            uint32_t ah[4][4], al[4][4], bh[NT][2];
#pragma unroll
            for (int mt = 0; mt < 4; mt++) {
                uint32_t off = ((wm + (mt << 4) + a_r) * GSTRIDE + (ks << 4) + (a_k << 3)) * 2;
                ldmx4(ah[mt][0], ah[mt][1], ah[mt][2], ah[mt][3], sAhi + off);
                if (TERMS == 2)
                    ldmx4(al[mt][0], al[mt][1], al[mt][2], al[mt][3], sAlo + off);
            }
#pragma unroll
            for (int ntp = 0; ntp < NT / 2; ntp++) {
                uint32_t off = ((wn + (ntp << 4) + ((x4m >> 1) << 3) + x4r) * GSTRIDE +
                                (ks << 4) + ((x4m & 1) << 3)) * 2;
                ldmx4(bh[2 * ntp][0], bh[2 * ntp][1],
                      bh[2 * ntp + 1][0], bh[2 * ntp + 1][1], sBhi + off);
            }
            // term-outer
#pragma unroll
            for (int mt = 0; mt < 4; mt++)
#pragma unroll
                for (int nt = 0; nt < NT; nt++)
                    mma16816(acc[mt][nt], ah[mt], bh[nt]);
            if (TERMS == 2) {
#pragma unroll
                for (int mt = 0; mt < 4; mt++)
#pragma unroll
                    for (int nt = 0; nt < NT; nt++)
                        mma16816(acc[mt][nt], al[mt], bh[nt]);
            }
        }
    }
    __syncthreads();

    const int er = lane >> 2;
    const int ec = (lane & 3) << 1;

    if (mode == 0) {
#pragma unroll
        for (int mt = 0; mt < 4; mt++) {
#pragma unroll
            for (int nt = 0; nt < NT; nt++) {
                int row = m0 + wm + (mt << 4) + er;
                int col = n0 + wn + (nt << 3) + ec;
                float2 b2 = *(const float2*)(bias + col);
                float2 o0, o1;
                o0.x = (acc[mt][nt][0] + b2.x) * scale;
                o0.y = (acc[mt][nt][1] + b2.y) * scale;
                o1.x = (acc[mt][nt][2] + b2.x) * scale;
                o1.y = (acc[mt][nt][3] + b2.y) * scale;
                *(float2*)(Cf + row * 1024 + col) = o0;
                *(float2*)(Cf + (row + 8) * 1024 + col) = o1;
            }
        }
    } else if (mode == 1) {
#pragma unroll
        for (int mt = 0; mt < 4; mt++) {
#pragma unroll
            for (int nt = 0; nt < NT; nt++) {
                int row = m0 + wm + (mt << 4) + er;
                int col = n0 + wn + (nt << 3) + ec;
                float2 b2 = *(const float2*)(bias + col);
#pragma unroll
                for (int half = 0; half < 2; half++) {
                    int r = row + half * 8;
                    float v0 = (acc[mt][nt][half * 2 + 0] + b2.x) * scale;
                    float v1 = (acc[mt][nt][half * 2 + 1] + b2.y) * scale;
                    *(uint32_t*)(Chi + r * 1024 + col) = pack_h2(v0, v1);
                }
            }
        }
    } else {
        __half* sthi = (__half*)smem;
#pragma unroll
        for (int mt = 0; mt < 4; mt++) {
#pragma unroll
            for (int nt = 0; nt < NT; nt++) {
                int mrow = wm + (mt << 4) + er;
                int ncol = wn + (nt << 3) + ec;
                float2 b2 = *(const float2*)(bias + n0 + ncol);
#pragma unroll
                for (int half = 0; half < 2; half++) {
                    int r = mrow + half * 8;
                    float v0 = (acc[mt][nt][half * 2 + 0] + b2.x) * scale;
                    float v1 = (acc[mt][nt][half * 2 + 1] + b2.y) * scale;
                    sthi[ncol * 136 + r] = __float2half_rn(v0);
                    sthi[(ncol + 1) * 136 + r] = __float2half_rn(v1);
                }
            }
        }
        __syncthreads();
        const int bidx = m0 >> 10;
        const int l0 = m0 & 1023;
        constexpr int CHT = TN * 16;           // 16B chunks in the staged tile
        constexpr int NCP = CHT / 256;
#pragma unroll
        for (int i = 0; i < NCP; i++) {
            int q = tid + (i << 8);
            int nrow = q >> 4;
            int ch = q & 15;
            uint4 v = *(const uint4*)(smem + (nrow * 136 + ch * 8) * 2);
            __half* dst = Chi + bidx * 1048576 + (n0 + nrow) * 1024 + l0 + ch * 8;
            *(uint4*)dst = v;
        }
    }
}

#define GSMEM_G (3 * (2 * ATILE_B + 64 * GSTRIDE * 2))   // 76800 -> 2 CTAs/SM

// Fused QKV projection: grid (16, 64, 3); z=0 V (2-term) first.
__global__ __launch_bounds__(256, 1)
void qkv_mma_kernel(const __half* __restrict__ xhi,
                    const __half* __restrict__ xlo,
                    const __half* __restrict__ wq_hi,
                    const __half* __restrict__ wk_hi,
                    const __half* __restrict__ wv_hi,
                    const float* __restrict__ bq,
                    const float* __restrict__ bk,
                    const float* __restrict__ bv,
                    __half* __restrict__ qthi,
                    __half* __restrict__ kthi,
                    __half* __restrict__ vhi) {
    extern __shared__ __align__(16) char smem[];
    const int m0 = blockIdx.y << 7;
    const int n0 = blockIdx.x << 6;
    const int z = blockIdx.z;
    if (z == 0) {
        gemm_body<2, 64>(smem, xhi, xlo, wv_hi, bv, nullptr, vhi, 1.0f, 1, m0, n0);
    } else if (z == 1) {
        gemm_body<1, 64>(smem, xhi, nullptr, wq_hi, bq, nullptr, qthi, QKSCALE, 2, m0, n0);
    } else {
        gemm_body<1, 64>(smem, xhi, nullptr, wk_hi, bk, nullptr, kthi, QKSCALE, 2, m0, n0);
    }
}

// Output projection, 2-term fp16, 128x64 tiles (grid 16 x 64).
__global__ __launch_bounds__(256, 1)
void wo_mma_kernel(const __half* __restrict__ Ahi,
                   const __half* __restrict__ Alo,
                   const __half* __restrict__ Bhi,
                   const float* __restrict__ bias,
                   float* __restrict__ Cf) {
    extern __shared__ __align__(16) char smem[];
    gemm_body<2, 64>(smem, Ahi, Alo, Bhi, bias, Cf, nullptr, 1.0f, 0,
                     blockIdx.y << 7, blockIdx.x << 6);
}

// ===========================================================================
// FlashAttention-2-style attention, fp16.
//   QK: 1-term (Q hi x K hi).  PV: 2-term (Phi*Vhi + Plo*Vhi), V hi only.
//   smem: Q[128][72] + K[128][72] single + V hi [64][136] x2 = 71680 B
//   -> 2 CTAs/SM (launch_bounds(256,2)).
// ===========================================================================
#define ATT_Q_OFF 0
#define ATT_K_OFF 18432
#define ATT_V_OFF 36864
#define ATT_SMEM  71680

__global__ __launch_bounds__(256, 2)
void attn_fa2_kernel() {
    extern __shared__ __align__(16) char sm[];
    const uint32_t R = smem_u32(sm);

    const int g = blockIdx.y, qt = blockIdx.x;
    const int b = g >> 4, h = g & 15;
    const int tid = threadIdx.x, wid = tid >> 5, lane = tid & 31;

    const int a_r = lane & 15, a_k = lane >> 4;
    const int x4m = lane >> 3;
    const int x4r = lane & 7;
    const int ec = (lane & 3) << 1;
    const int er = lane >> 2;

    const int qkrow = b * 1048576 + h * 64;

#pragma unroll
    for (int i = 0; i < 4; i++) {
        int q = tid + (i << 8);
        int r = q >> 3, ch = q & 7;
        const __half* src = g_QThi + qkrow + (qt * 128 + r) * 1024 + ch * 8;
        CP_ASYNC16(R + ATT_Q_OFF + (r * 72 + ch * 8) * 2, src);
    }
    auto load_K = [&](int c) {
#pragma unroll
        for (int i = 0; i < 4; i++) {
            int q = tid + (i << 8);
            int r = q >> 3, ch = q & 7;
            const __half* src = g_KThi + qkrow + (c * 128 + r) * 1024 + ch * 8;
            CP_ASYNC16(R + ATT_K_OFF + (r * 72 + ch * 8) * 2, src);
        }
    };
    auto load_V = [&](int c, int buf) {
#pragma unroll
        for (int i = 0; i < 4; i++) {
            int q = tid + (i << 8);           // 0..1023: 64 rows x 16 chunks
            int r = q >> 4, ch = q & 15;
            const __half* src =
                g_Vhi + (b * 1024 + h * 64 + r) * 1024 + c * 128 + ch * 8;
            CP_ASYNC16(R + ATT_V_OFF + buf * 17408 + (r * 136 + ch * 8) * 2, src);
        }
    };
    load_K(0);
    load_V(0, 0);
    CP_COMMIT();
    CP_WAIT(0);
    __syncthreads();

    float oacc[8][4];
#pragma unroll
    for (int i = 0; i < 8; i++)
#pragma unroll
        for (int j = 0; j < 4; j++) oacc[i][j] = 0.f;
    float mrow[2] = {-1e30f, -1e30f};
    float lrow[2] = {0.f, 0.f};

    for (int c = 0; c < 8; c++) {
        const int vbuf = c & 1;
        if (c + 1 < 8) {
            load_V(c + 1, vbuf ^ 1);
            CP_COMMIT();
        }

        // ---- QK (1-term fp16) ----
        float sacc[16][4];
#pragma unroll
        for (int i = 0; i < 16; i++)
#pragma unroll
            for (int j = 0; j < 4; j++) sacc[i][j] = 0.f;

#pragma unroll
        for (int ks = 0; ks < 4; ks++) {
            uint32_t qh[4];
            uint32_t qoff = R + ATT_Q_OFF + ((wid * 16 + a_r) * 72 + ks * 16 + a_k * 8) * 2;
            ldmx4(qh[0], qh[1], qh[2], qh[3], qoff);
#pragma unroll
            for (int ntp = 0; ntp < 8; ntp++) {
                uint32_t bb[4];
                uint32_t off = R + ATT_K_OFF + (((ntp << 4) + ((x4m >> 1) << 3) + x4r) * 72 +
                                                (ks << 4) + ((x4m & 1) << 3)) * 2;
                ldmx4(bb[0], bb[1], bb[2], bb[3], off);
                mma16816(sacc[2 * ntp],     qh, bb);
                mma16816(sacc[2 * ntp + 1], qh, bb + 2);
            }
        }
        __syncthreads();
        if (c + 1 < 8) {
            load_K(c + 1);
            CP_COMMIT();
        }

        // ---- online softmax ----
        float cm[2];
#pragma unroll
        for (int rr = 0; rr < 2; rr++) {
            float mx = -1e30f;
#pragma unroll
            for (int nt = 0; nt < 16; nt++)
                mx = fmaxf(mx, fmaxf(sacc[nt][rr * 2], sacc[nt][rr * 2 + 1]));
            mx = fmaxf(mx, __shfl_xor_sync(0xffffffffu, mx, 1));
            mx = fmaxf(mx, __shfl_xor_sync(0xffffffffu, mx, 2));
            float mnew = fmaxf(mrow[rr], mx);
            cm[rr] = __expf(mrow[rr] - mnew);
            mrow[rr] = mnew;
        }
        float rs0 = 0.f, rs1 = 0.f;
#pragma unroll
        for (int nt = 0; nt < 16; nt++) {
            sacc[nt][0] = __expf(sacc[nt][0] - mrow[0]);
            sacc[nt][1] = __expf(sacc[nt][1] - mrow[0]);
            sacc[nt][2] = __expf(sacc[nt][2] - mrow[1]);
            sacc[nt][3] = __expf(sacc[nt][3] - mrow[1]);
            rs0 += sacc[nt][0] + sacc[nt][1];
            rs1 += sacc[nt][2] + sacc[nt][3];
        }
        rs0 += __shfl_xor_sync(0xffffffffu, rs0, 1);
        rs0 += __shfl_xor_sync(0xffffffffu, rs0, 2);
        rs1 += __shfl_xor_sync(0xffffffffu, rs1, 1);
        rs1 += __shfl_xor_sync(0xffffffffu, rs1, 2);
        lrow[0] = lrow[0] * cm[0] + rs0;
        lrow[1] = lrow[1] * cm[1] + rs1;

#pragma unroll
        for (int nt = 0; nt < 8; nt++) {
            oacc[nt][0] *= cm[0]; oacc[nt][1] *= cm[0];
            oacc[nt][2] *= cm[1]; oacc[nt][3] *= cm[1];
        }

        // ---- PV: 2-term fp16 (Phi + Plo) x Vhi ----
        const uint32_t vb = R + ATT_V_OFF + vbuf * 17408;
#pragma unroll
        for (int ks = 0; ks < 8; ks++) {
            uint32_t ph[4], pl[4];
            pack_split_h(sacc[2 * ks][0],     sacc[2 * ks][1],     ph[0], pl[0]);
            pack_split_h(sacc[2 * ks][2],     sacc[2 * ks][3],     ph[1], pl[1]);
            pack_split_h(sacc[2 * ks + 1][0], sacc[2 * ks + 1][1], ph[2], pl[2]);
            pack_split_h(sacc[2 * ks + 1][2], sacc[2 * ks + 1][3], ph[3], pl[3]);
#pragma unroll
            for (int ntp = 0; ntp < 4; ntp++) {
                uint32_t vh4[4];
                uint32_t off = vb + (((ntp << 4) + ((x4m >> 1) << 3) + x4r) * 136 +
                                     (ks << 4) + ((x4m & 1) << 3)) * 2;
                ldmx4(vh4[0], vh4[1], vh4[2], vh4[3], off);
#pragma unroll
                for (int u = 0; u < 2; u++) {
                    int nt = 2 * ntp + u;
                    mma16816(oacc[nt], ph, vh4 + 2 * u);
                    mma16816(oacc[nt], pl, vh4 + 2 * u);
                }
            }
        }

        if (c + 1 < 8) { CP_WAIT(0); __syncthreads(); }
    }

    float inv[2] = {1.f / lrow[0], 1.f / lrow[1]};
#pragma unroll
    for (int nt = 0; nt < 8; nt++) {
#pragma unroll
        for (int half = 0; half < 2; half++) {
            int t1 = qt * 128 + wid * 16 + er + half * 8;
            int p = t1 >> 4, qq = t1 & 15;
            int col = nt * 8 + ec;
            float v0 = oacc[nt][half * 2 + 0] * inv[half];
            float v1 = oacc[nt][half * 2 + 1] * inv[half];
            uint32_t hp, lp;
            pack_split_h(v0, v1, hp, lp);
            int off = (b * 1024 + h * 64 + p) * 1024 + qq * 64 + col;
            *(uint32_t*)(g_Ahi + off) = hp;
            *(uint32_t*)(g_Alo + off) = lp;
        }
    }
}

// ===========================================================================
extern "C" void kernel_launch(void* const* d_in, const int* in_sizes, int n_in,
                              void* d_out, int out_size) {
    const float* x  = (const float*)d_in[0];
    const float* Wq = (const float*)d_in[1];
    const float* bq = (const float*)d_in[2];
    const float* Wk = (const float*)d_in[3];
    const float* bk = (const float*)d_in[4];
    const float* Wv = (const float*)d_in[5];
    const float* bv = (const float*)d_in[6];
    const float* Wo = (const float*)d_in[7];
    const float* bo = (const float*)d_in[8];
    float* out = (float*)d_out;

    __half *xhi, *xlo, *whi;
    __half *qthi, *kthi, *vhi, *ahi, *alo;
    cudaGetSymbolAddress((void**)&xhi, g_xhi);
    cudaGetSymbolAddress((void**)&xlo, g_xlo);
    cudaGetSymbolAddress((void**)&whi, g_wt_hi);
    cudaGetSymbolAddress((void**)&qthi, g_QThi);
    cudaGetSymbolAddress((void**)&kthi, g_KThi);
    cudaGetSymbolAddress((void**)&vhi, g_Vhi);
    cudaGetSymbolAddress((void**)&ahi, g_Ahi);
    cudaGetSymbolAddress((void**)&alo, g_Alo);

    cudaFuncSetAttribute(qkv_mma_kernel, cudaFuncAttributeMaxDynamicSharedMemorySize,
                         GSMEM_G);
    cudaFuncSetAttribute(wo_mma_kernel, cudaFuncAttributeMaxDynamicSharedMemorySize,
                         GSMEM_G);
    cudaFuncSetAttribute(attn_fa2_kernel, cudaFuncAttributeMaxDynamicSharedMemorySize,
                         ATT_SMEM);

    // 1) fused preprocessing                                      (launch 0)
    prep_kernel<<<dim3(32, 32, 5), dim3(32, 8)>>>(x, Wq, Wk, Wv, Wo, xhi, xlo, whi);

    // 2) fused QKV projections (V 2-term, Q/K 1-term)             (launch 1)
    qkv_mma_kernel<<<dim3(16, 64, 3), 256, GSMEM_G>>>(
        xhi, xlo,
        whi + 0 * DIM * DIM, whi + 1 * DIM * DIM, whi + 2 * DIM * DIM,
        bq, bk, bv, qthi, kthi, vhi);

    // 3) attention (fp16, PV 2-term, 2 CTAs/SM)                   (launch 2)
    attn_fa2_kernel<<<dim3(8, 128), 256, ATT_SMEM>>>();

    // 4) output projection (2-term fp16)                          (launch 3)
    wo_mma_kernel<<<dim3(16, 64), 256, GSMEM_G>>>(ahi, alo, whi + 3 * DIM * DIM, bo, out);
}

// round 17
// speedup vs baseline: 1.5017x; 1.1495x over previous
#include <cuda_runtime.h>
#include <cuda_fp16.h>
#include <cstdint>

// ===========================================================================
// Problem constants
// ===========================================================================
#define BLN 8192          // B*L
#define DIM 1024          // D
#define QKSCALE 0.03125f  // 1/sqrt(1024)

// ===========================================================================
// Device scratch (fp16 split)
// ===========================================================================
__device__ __half g_xhi[BLN * DIM];
__device__ __half g_xlo[BLN * DIM];
__device__ __half g_wt_hi[4][DIM * DIM];   // W^T [n][k] hi
__device__ __half g_QThi[BLN * DIM];       // [b][t][l]
__device__ __half g_KThi[BLN * DIM];
__device__ __half g_Vhi[BLN * DIM];        // [row=(b,l)][ch]
__device__ __half g_Ahi[BLN * DIM];
__device__ __half g_Alo[BLN * DIM];

// ===========================================================================
// PTX helpers
// ===========================================================================
__device__ __forceinline__ uint32_t smem_u32(const void* p) {
    uint32_t a;
    asm("{ .reg .u64 t; cvta.to.shared.u64 t, %1; cvt.u32.u64 %0, t; }" : "=r"(a) : "l"(p));
    return a;
}
#define CP_ASYNC16(saddr, gptr) \
    asm volatile("cp.async.cg.shared.global [%0], [%1], 16;" :: "r"(saddr), "l"(gptr))
#define CP_COMMIT() asm volatile("cp.async.commit_group;" ::: "memory")
#define CP_WAIT(n)  asm volatile("cp.async.wait_group %0;" :: "n"(n) : "memory")

__device__ __forceinline__ void ldmx4(uint32_t& r0, uint32_t& r1, uint32_t& r2, uint32_t& r3,
                                      uint32_t addr) {
    asm volatile("ldmatrix.sync.aligned.m8n8.x4.shared.b16 {%0,%1,%2,%3}, [%4];"
                 : "=r"(r0), "=r"(r1), "=r"(r2), "=r"(r3) : "r"(addr));
}
__device__ __forceinline__ void mma16816(float* c, const uint32_t* a, const uint32_t* b) {
    asm volatile(
        "mma.sync.aligned.m16n8k16.row.col.f32.f16.f16.f32 "
        "{%0,%1,%2,%3}, {%4,%5,%6,%7}, {%8,%9}, {%0,%1,%2,%3};"
        : "+f"(c[0]), "+f"(c[1]), "+f"(c[2]), "+f"(c[3])
        : "r"(a[0]), "r"(a[1]), "r"(a[2]), "r"(a[3]), "r"(b[0]), "r"(b[1]));
}
__device__ __forceinline__ void pack_split_h(float v0, float v1, uint32_t& hi, uint32_t& lo) {
    __half h0 = __float2half_rn(v0);
    __half h1 = __float2half_rn(v1);
    __half2 hp; hp.x = h0; hp.y = h1;
    hi = *(uint32_t*)&hp;
    __half2 lp;
    lp.x = __float2half_rn(v0 - __half2float(h0));
    lp.y = __float2half_rn(v1 - __half2float(h1));
    lo = *(uint32_t*)&lp;
}
__device__ __forceinline__ uint32_t pack_h2(float v0, float v1) {
    __half2 hp; hp.x = __float2half_rn(v0); hp.y = __float2half_rn(v1);
    return *(uint32_t*)&hp;
}

struct alignas(8) h4 { __half a, b, c, d; };

// ===========================================================================
// Fused preprocessing (one launch): z=0..3 transpose W[z] -> hi; z=4 split x
// ===========================================================================
__global__ void prep_kernel(const float* __restrict__ x,
                            const float* __restrict__ Wq,
                            const float* __restrict__ Wk,
                            const float* __restrict__ Wv,
                            const float* __restrict__ Wo,
                            __half* __restrict__ xhi,
                            __half* __restrict__ xlo,
                            __half* __restrict__ whi) {
    const int z = blockIdx.z;
    const int tx = threadIdx.x, ty = threadIdx.y;
    if (z < 4) {
        const float* W = (z == 0) ? Wq : (z == 1) ? Wk : (z == 2) ? Wv : Wo;
        __half* Thi = whi + z * DIM * DIM;
        __shared__ float t[32][33];
        const int n0 = blockIdx.x << 5;
        const int k0 = blockIdx.y << 5;
#pragma unroll
        for (int j = 0; j < 4; j++)
            t[ty + (j << 3)][tx] = W[(k0 + ty + (j << 3)) * DIM + n0 + tx];
        __syncthreads();
#pragma unroll
        for (int j = 0; j < 4; j++) {
            float v = t[tx][ty + (j << 3)];
            Thi[(n0 + ty + (j << 3)) * DIM + k0 + tx] = __float2half_rn(v);
        }
    } else {
        const int flat = (blockIdx.y * 32 + blockIdx.x) * 256 + ty * 32 + tx;
        const float4* in4 = (const float4*)x;
#pragma unroll
        for (int j = 0; j < 8; j++) {
            int i = flat + j * 262144;
            float4 v = in4[i];
            __half h0 = __float2half_rn(v.x);
            __half h1 = __float2half_rn(v.y);
            __half h2 = __float2half_rn(v.z);
            __half h3 = __float2half_rn(v.w);
            h4 H = {h0, h1, h2, h3};
            h4 L = {__float2half_rn(v.x - __half2float(h0)),
                    __float2half_rn(v.y - __half2float(h1)),
                    __float2half_rn(v.z - __half2float(h2)),
                    __float2half_rn(v.w - __half2float(h3))};
            ((h4*)xhi)[i] = H;
            ((h4*)xlo)[i] = L;
        }
    }
}

// ===========================================================================
// GEMM body: fp16 mma.sync, BK=64, 2-stage double buffer (16 iterations,
// ONE sync per iteration). Stride 72 elems (144B) -> conflict-free ldmatrix.
// TERMS=2: Ahi*Bhi + Alo*Bhi (term-outer). TERMS=1: Ahi*Bhi.
// modes: 0 = fp32 natural; 1 = fp16-hi natural; 2 = fp16-hi transposed
// ===========================================================================
#define GS2 72                              // elems per smem row (144 B)
#define ATILE_B (128 * GS2 * 2)             // 18432
#define BTILE64_B (64 * GS2 * 2)            // 9216

template <int TERMS, int TN>
__device__ __forceinline__
void gemm_body(char* smem,
               const __half* __restrict__ Ahi,
               const __half* __restrict__ Alo,
               const __half* __restrict__ Bhi,
               const float* __restrict__ bias,
               float* __restrict__ Cf,
               __half* __restrict__ Chi,
               float scale, int mode, int m0, int n0) {
    constexpr int BTILE_B = TN * GS2 * 2;
    constexpr int NATILE = (TERMS == 2) ? 2 : 1;
    constexpr int SSTAGE = NATILE * ATILE_B + BTILE_B;   // 46080 / 27648 @TN=64
    constexpr int NT = TN / 32;

    const uint32_t sbase = smem_u32(smem);

    const int tid = threadIdx.x;
    const int wid = tid >> 5;
    const int lane = tid & 31;
    const int wm = (wid & 1) << 6;
    const int wn = (wid >> 1) * (TN / 4);

    const __half* srcA0 = Ahi + m0 * 1024;
    const __half* srcA1 = (TERMS == 2) ? (Alo + m0 * 1024) : nullptr;
    const __half* srcB  = Bhi + n0 * 1024;

    float acc[4][NT][4];
#pragma unroll
    for (int a = 0; a < 4; a++)
#pragma unroll
        for (int b = 0; b < NT; b++)
#pragma unroll
            for (int c = 0; c < 4; c++) acc[a][b][c] = 0.f;

    const int a_r = lane & 15, a_k = lane >> 4;
    const int x4m = lane >> 3;
    const int x4r = lane & 7;

    // BK=64: A tile = 128 rows x 8 chunks (16B) = 1024 chunks; B = TN x 8.
    auto load_stage = [&](int kt, int buf) {
        const int kb = kt << 6;
        uint32_t sb = sbase + buf * SSTAGE;
#pragma unroll
        for (int j = 0; j < 4; j++) {
            int idx = (j << 8) + tid;
            int row = idx >> 3, ch = idx & 7;
            CP_ASYNC16(sb + (row * GS2 + (ch << 3)) * 2,
                       srcA0 + row * 1024 + kb + (ch << 3));
        }
        if (TERMS == 2) {
#pragma unroll
            for (int j = 0; j < 4; j++) {
                int idx = (j << 8) + tid;
                int row = idx >> 3, ch = idx & 7;
                CP_ASYNC16(sb + ATILE_B + (row * GS2 + (ch << 3)) * 2,
                           srcA1 + row * 1024 + kb + (ch << 3));
            }
        }
#pragma unroll
        for (int j = 0; j < TN / 32; j++) {
            int idx = (j << 8) + tid;
            int row = idx >> 3, ch = idx & 7;
            CP_ASYNC16(sb + NATILE * ATILE_B + (row * GS2 + (ch << 3)) * 2,
                       srcB + row * 1024 + kb + (ch << 3));
        }
    };

    load_stage(0, 0); CP_COMMIT();

    for (int kt = 0; kt < 16; kt++) {
        CP_WAIT(0);
        __syncthreads();   // stage kt landed; all warps done reading buf kt^1
        if (kt + 1 < 16) { load_stage(kt + 1, (kt + 1) & 1); CP_COMMIT(); }

        const uint32_t sb = sbase + (kt & 1) * SSTAGE;
        const uint32_t sAhi = sb;
        const uint32_t sAlo = sb + ATILE_B;
        const uint32_t sBhi = sb + NATILE * ATILE_B;

#pragma unroll
        for (int ks = 0; ks < 4; ks++) {
            uint32_t ah[4][4], al[4][4], bh[NT][2];
#pragma unroll
            for (int mt = 0; mt < 4; mt++) {
                uint32_t off = ((wm + (mt << 4) + a_r) * GS2 + (ks << 4) + (a_k << 3)) * 2;
                ldmx4(ah[mt][0], ah[mt][1], ah[mt][2], ah[mt][3], sAhi + off);
                if (TERMS == 2)
                    ldmx4(al[mt][0], al[mt][1], al[mt][2], al[mt][3], sAlo + off);
            }
#pragma unroll
            for (int ntp = 0; ntp < NT / 2; ntp++) {
                uint32_t off = ((wn + (ntp << 4) + ((x4m >> 1) << 3) + x4r) * GS2 +
                                (ks << 4) + ((x4m & 1) << 3)) * 2;
                ldmx4(bh[2 * ntp][0], bh[2 * ntp][1],
                      bh[2 * ntp + 1][0], bh[2 * ntp + 1][1], sBhi + off);
            }
            // term-outer
#pragma unroll
            for (int mt = 0; mt < 4; mt++)
#pragma unroll
                for (int nt = 0; nt < NT; nt++)
                    mma16816(acc[mt][nt], ah[mt], bh[nt]);
            if (TERMS == 2) {
#pragma unroll
                for (int mt = 0; mt < 4; mt++)
#pragma unroll
                    for (int nt = 0; nt < NT; nt++)
                        mma16816(acc[mt][nt], al[mt], bh[nt]);
            }
        }
    }
    __syncthreads();

    const int er = lane >> 2;
    const int ec = (lane & 3) << 1;

    if (mode == 0) {
#pragma unroll
        for (int mt = 0; mt < 4; mt++) {
#pragma unroll
            for (int nt = 0; nt < NT; nt++) {
                int row = m0 + wm + (mt << 4) + er;
                int col = n0 + wn + (nt << 3) + ec;
                float2 b2 = *(const float2*)(bias + col);
                float2 o0, o1;
                o0.x = (acc[mt][nt][0] + b2.x) * scale;
                o0.y = (acc[mt][nt][1] + b2.y) * scale;
                o1.x = (acc[mt][nt][2] + b2.x) * scale;
                o1.y = (acc[mt][nt][3] + b2.y) * scale;
                *(float2*)(Cf + row * 1024 + col) = o0;
                *(float2*)(Cf + (row + 8) * 1024 + col) = o1;
            }
        }
    } else if (mode == 1) {
#pragma unroll
        for (int mt = 0; mt < 4; mt++) {
#pragma unroll
            for (int nt = 0; nt < NT; nt++) {
                int row = m0 + wm + (mt << 4) + er;
                int col = n0 + wn + (nt << 3) + ec;
                float2 b2 = *(const float2*)(bias + col);
#pragma unroll
                for (int half = 0; half < 2; half++) {
                    int r = row + half * 8;
                    float v0 = (acc[mt][nt][half * 2 + 0] + b2.x) * scale;
                    float v1 = (acc[mt][nt][half * 2 + 1] + b2.y) * scale;
                    *(uint32_t*)(Chi + r * 1024 + col) = pack_h2(v0, v1);
                }
            }
        }
    } else {
        __half* sthi = (__half*)smem;
#pragma unroll
        for (int mt = 0; mt < 4; mt++) {
#pragma unroll
            for (int nt = 0; nt < NT; nt++) {
                int mrow = wm + (mt << 4) + er;
                int ncol = wn + (nt << 3) + ec;
                float2 b2 = *(const float2*)(bias + n0 + ncol);
#pragma unroll
                for (int half = 0; half < 2; half++) {
                    int r = mrow + half * 8;
                    float v0 = (acc[mt][nt][half * 2 + 0] + b2.x) * scale;
                    float v1 = (acc[mt][nt][half * 2 + 1] + b2.y) * scale;
                    sthi[ncol * 136 + r] = __float2half_rn(v0);
                    sthi[(ncol + 1) * 136 + r] = __float2half_rn(v1);
                }
            }
        }
        __syncthreads();
        const int bidx = m0 >> 10;
        const int l0 = m0 & 1023;
        constexpr int CHT = TN * 16;
        constexpr int NCP = CHT / 256;
#pragma unroll
        for (int i = 0; i < NCP; i++) {
            int q = tid + (i << 8);
            int nrow = q >> 4;
            int ch = q & 15;
            uint4 v = *(const uint4*)(smem + (nrow * 136 + ch * 8) * 2);
            __half* dst = Chi + bidx * 1048576 + (n0 + nrow) * 1024 + l0 + ch * 8;
            *(uint4*)dst = v;
        }
    }
}

#define GSMEM_G (2 * (2 * ATILE_B + BTILE64_B))   // 92160 -> 2 CTAs/SM

// Fused QKV projection: grid (16, 64, 3); z=0 V (2-term) first.
__global__ __launch_bounds__(256, 1)
void qkv_mma_kernel(const __half* __restrict__ xhi,
                    const __half* __restrict__ xlo,
                    const __half* __restrict__ wq_hi,
                    const __half* __restrict__ wk_hi,
                    const __half* __restrict__ wv_hi,
                    const float* __restrict__ bq,
                    const float* __restrict__ bk,
                    const float* __restrict__ bv,
                    __half* __restrict__ qthi,
                    __half* __restrict__ kthi,
                    __half* __restrict__ vhi) {
    extern __shared__ __align__(16) char smem[];
    const int m0 = blockIdx.y << 7;
    const int n0 = blockIdx.x << 6;
    const int z = blockIdx.z;
    if (z == 0) {
        gemm_body<2, 64>(smem, xhi, xlo, wv_hi, bv, nullptr, vhi, 1.0f, 1, m0, n0);
    } else if (z == 1) {
        gemm_body<1, 64>(smem, xhi, nullptr, wq_hi, bq, nullptr, qthi, QKSCALE, 2, m0, n0);
    } else {
        gemm_body<1, 64>(smem, xhi, nullptr, wk_hi, bk, nullptr, kthi, QKSCALE, 2, m0, n0);
    }
}

// Output projection, 2-term fp16, 128x64 tiles (grid 16 x 64).
__global__ __launch_bounds__(256, 1)
void wo_mma_kernel(const __half* __restrict__ Ahi,
                   const __half* __restrict__ Alo,
                   const __half* __restrict__ Bhi,
                   const float* __restrict__ bias,
                   float* __restrict__ Cf) {
    extern __shared__ __align__(16) char smem[];
    gemm_body<2, 64>(smem, Ahi, Alo, Bhi, bias, Cf, nullptr, 1.0f, 0,
                     blockIdx.y << 7, blockIdx.x << 6);
}

// ===========================================================================
// FlashAttention-2-style attention, fp16 (round-16 version, unchanged).
// ===========================================================================
#define ATT_Q_OFF 0
#define ATT_K_OFF 18432
#define ATT_V_OFF 36864
#define ATT_SMEM  71680

__global__ __launch_bounds__(256, 2)
void attn_fa2_kernel() {
    extern __shared__ __align__(16) char sm[];
    const uint32_t R = smem_u32(sm);

    const int g = blockIdx.y, qt = blockIdx.x;
    const int b = g >> 4, h = g & 15;
    const int tid = threadIdx.x, wid = tid >> 5, lane = tid & 31;

    const int a_r = lane & 15, a_k = lane >> 4;
    const int x4m = lane >> 3;
    const int x4r = lane & 7;
    const int ec = (lane & 3) << 1;
    const int er = lane >> 2;

    const int qkrow = b * 1048576 + h * 64;

#pragma unroll
    for (int i = 0; i < 4; i++) {
        int q = tid + (i << 8);
        int r = q >> 3, ch = q & 7;
        const __half* src = g_QThi + qkrow + (qt * 128 + r) * 1024 + ch * 8;
        CP_ASYNC16(R + ATT_Q_OFF + (r * 72 + ch * 8) * 2, src);
    }
    auto load_K = [&](int c) {
#pragma unroll
        for (int i = 0; i < 4; i++) {
            int q = tid + (i << 8);
            int r = q >> 3, ch = q & 7;
            const __half* src = g_KThi + qkrow + (c * 128 + r) * 1024 + ch * 8;
            CP_ASYNC16(R + ATT_K_OFF + (r * 72 + ch * 8) * 2, src);
        }
    };
    auto load_V = [&](int c, int buf) {
#pragma unroll
        for (int i = 0; i < 4; i++) {
            int q = tid + (i << 8);
            int r = q >> 4, ch = q & 15;
            const __half* src =
                g_Vhi + (b * 1024 + h * 64 + r) * 1024 + c * 128 + ch * 8;
            CP_ASYNC16(R + ATT_V_OFF + buf * 17408 + (r * 136 + ch * 8) * 2, src);
        }
    };
    load_K(0);
    load_V(0, 0);
    CP_COMMIT();
    CP_WAIT(0);
    __syncthreads();

    float oacc[8][4];
#pragma unroll
    for (int i = 0; i < 8; i++)
#pragma unroll
        for (int j = 0; j < 4; j++) oacc[i][j] = 0.f;
    float mrow[2] = {-1e30f, -1e30f};
    float lrow[2] = {0.f, 0.f};

    for (int c = 0; c < 8; c++) {
        const int vbuf = c & 1;
        if (c + 1 < 8) {
            load_V(c + 1, vbuf ^ 1);
            CP_COMMIT();
        }

        float sacc[16][4];
#pragma unroll
        for (int i = 0; i < 16; i++)
#pragma unroll
            for (int j = 0; j < 4; j++) sacc[i][j] = 0.f;

#pragma unroll
        for (int ks = 0; ks < 4; ks++) {
            uint32_t qh[4];
            uint32_t qoff = R + ATT_Q_OFF + ((wid * 16 + a_r) * 72 + ks * 16 + a_k * 8) * 2;
            ldmx4(qh[0], qh[1], qh[2], qh[3], qoff);
#pragma unroll
            for (int ntp = 0; ntp < 8; ntp++) {
                uint32_t bb[4];
                uint32_t off = R + ATT_K_OFF + (((ntp << 4) + ((x4m >> 1) << 3) + x4r) * 72 +
                                                (ks << 4) + ((x4m & 1) << 3)) * 2;
                ldmx4(bb[0], bb[1], bb[2], bb[3], off);
                mma16816(sacc[2 * ntp],     qh, bb);
                mma16816(sacc[2 * ntp + 1], qh, bb + 2);
            }
        }
        __syncthreads();
        if (c + 1 < 8) {
            load_K(c + 1);
            CP_COMMIT();
        }

        float cm[2];
#pragma unroll
        for (int rr = 0; rr < 2; rr++) {
            float mx = -1e30f;
#pragma unroll
            for (int nt = 0; nt < 16; nt++)
                mx = fmaxf(mx, fmaxf(sacc[nt][rr * 2], sacc[nt][rr * 2 + 1]));
            mx = fmaxf(mx, __shfl_xor_sync(0xffffffffu, mx, 1));
            mx = fmaxf(mx, __shfl_xor_sync(0xffffffffu, mx, 2));
            float mnew = fmaxf(mrow[rr], mx);
            cm[rr] = __expf(mrow[rr] - mnew);
            mrow[rr] = mnew;
        }
        float rs0 = 0.f, rs1 = 0.f;
#pragma unroll
        for (int nt = 0; nt < 16; nt++) {
            sacc[nt][0] = __expf(sacc[nt][0] - mrow[0]);
            sacc[nt][1] = __expf(sacc[nt][1] - mrow[0]);
            sacc[nt][2] = __expf(sacc[nt][2] - mrow[1]);
            sacc[nt][3] = __expf(sacc[nt][3] - mrow[1]);
            rs0 += sacc[nt][0] + sacc[nt][1];
            rs1 += sacc[nt][2] + sacc[nt][3];
        }
        rs0 += __shfl_xor_sync(0xffffffffu, rs0, 1);
        rs0 += __shfl_xor_sync(0xffffffffu, rs0, 2);
        rs1 += __shfl_xor_sync(0xffffffffu, rs1, 1);
        rs1 += __shfl_xor_sync(0xffffffffu, rs1, 2);
        lrow[0] = lrow[0] * cm[0] + rs0;
        lrow[1] = lrow[1] * cm[1] + rs1;

#pragma unroll
        for (int nt = 0; nt < 8; nt++) {
            oacc[nt][0] *= cm[0]; oacc[nt][1] *= cm[0];
            oacc[nt][2] *= cm[1]; oacc[nt][3] *= cm[1];
        }

        const uint32_t vb = R + ATT_V_OFF + vbuf * 17408;
#pragma unroll
        for (int ks = 0; ks < 8; ks++) {
            uint32_t ph[4], pl[4];
            pack_split_h(sacc[2 * ks][0],     sacc[2 * ks][1],     ph[0], pl[0]);
            pack_split_h(sacc[2 * ks][2],     sacc[2 * ks][3],     ph[1], pl[1]);
            pack_split_h(sacc[2 * ks + 1][0], sacc[2 * ks + 1][1], ph[2], pl[2]);
            pack_split_h(sacc[2 * ks + 1][2], sacc[2 * ks + 1][3], ph[3], pl[3]);
#pragma unroll
            for (int ntp = 0; ntp < 4; ntp++) {
                uint32_t vh4[4];
                uint32_t off = vb + (((ntp << 4) + ((x4m >> 1) << 3) + x4r) * 136 +
                                     (ks << 4) + ((x4m & 1) << 3)) * 2;
                ldmx4(vh4[0], vh4[1], vh4[2], vh4[3], off);
#pragma unroll
                for (int u = 0; u < 2; u++) {
                    int nt = 2 * ntp + u;
                    mma16816(oacc[nt], ph, vh4 + 2 * u);
                    mma16816(oacc[nt], pl, vh4 + 2 * u);
                }
            }
        }

        if (c + 1 < 8) { CP_WAIT(0); __syncthreads(); }
    }

    float inv[2] = {1.f / lrow[0], 1.f / lrow[1]};
#pragma unroll
    for (int nt = 0; nt < 8; nt++) {
#pragma unroll
        for (int half = 0; half < 2; half++) {
            int t1 = qt * 128 + wid * 16 + er + half * 8;
            int p = t1 >> 4, qq = t1 & 15;
            int col = nt * 8 + ec;
            float v0 = oacc[nt][half * 2 + 0] * inv[half];
            float v1 = oacc[nt][half * 2 + 1] * inv[half];
            uint32_t hp, lp;
            pack_split_h(v0, v1, hp, lp);
            int off = (b * 1024 + h * 64 + p) * 1024 + qq * 64 + col;
            *(uint32_t*)(g_Ahi + off) = hp;
            *(uint32_t*)(g_Alo + off) = lp;
        }
    }
}

// ===========================================================================
extern "C" void kernel_launch(void* const* d_in, const int* in_sizes, int n_in,
                              void* d_out, int out_size) {
    const float* x  = (const float*)d_in[0];
    const float* Wq = (const float*)d_in[1];
    const float* bq = (const float*)d_in[2];
    const float* Wk = (const float*)d_in[3];
    const float* bk = (const float*)d_in[4];
    const float* Wv = (const float*)d_in[5];
    const float* bv = (const float*)d_in[6];
    const float* Wo = (const float*)d_in[7];
    const float* bo = (const float*)d_in[8];
    float* out = (float*)d_out;

    __half *xhi, *xlo, *whi;
    __half *qthi, *kthi, *vhi, *ahi, *alo;
    cudaGetSymbolAddress((void**)&xhi, g_xhi);
    cudaGetSymbolAddress((void**)&xlo, g_xlo);
    cudaGetSymbolAddress((void**)&whi, g_wt_hi);
    cudaGetSymbolAddress((void**)&qthi, g_QThi);
    cudaGetSymbolAddress((void**)&kthi, g_KThi);
    cudaGetSymbolAddress((void**)&vhi, g_Vhi);
    cudaGetSymbolAddress((void**)&ahi, g_Ahi);
    cudaGetSymbolAddress((void**)&alo, g_Alo);

    cudaFuncSetAttribute(qkv_mma_kernel, cudaFuncAttributeMaxDynamicSharedMemorySize,
                         GSMEM_G);
    cudaFuncSetAttribute(wo_mma_kernel, cudaFuncAttributeMaxDynamicSharedMemorySize,
                         GSMEM_G);
    cudaFuncSetAttribute(attn_fa2_kernel, cudaFuncAttributeMaxDynamicSharedMemorySize,
                         ATT_SMEM);

    // 1) fused preprocessing                                      (launch 0)
    prep_kernel<<<dim3(32, 32, 5), dim3(32, 8)>>>(x, Wq, Wk, Wv, Wo, xhi, xlo, whi);

    // 2) fused QKV projections (BK=64, 2-stage)                   (launch 1)
    qkv_mma_kernel<<<dim3(16, 64, 3), 256, GSMEM_G>>>(
        xhi, xlo,
        whi + 0 * DIM * DIM, whi + 1 * DIM * DIM, whi + 2 * DIM * DIM,
        bq, bk, bv, qthi, kthi, vhi);

    // 3) attention (fp16, PV 2-term, 2 CTAs/SM)                   (launch 2)
    attn_fa2_kernel<<<dim3(8, 128), 256, ATT_SMEM>>>();

    // 4) output projection (BK=64, 2-stage)                       (launch 3)
    wo_mma_kernel<<<dim3(16, 64), 256, GSMEM_G>>>(ahi, alo, whi + 3 * DIM * DIM, bo, out);
}